// round 6
// baseline (speedup 1.0000x reference)
#include <cuda_runtime.h>
#include <math.h>

// ---------------- problem constants ----------------
#define BATCH   256
#define SEQ     360
#define PREFIX  340
#define D       256
#define H       4
#define DK      64
#define DFF     2048
#define NPAIR   91
#define PADTOK  799
#define TOKENS  (BATCH*SEQ)          // 92160
#define HEADS   (BATCH*H)            // 1024
#define HSTRIDE (SEQ*DK)             // 23040

// ---------------- scratch (device globals, no cudaMalloc allowed) ----------
__device__ float g_x  [TOKENS*D];     // residual stream
__device__ float g_x2 [TOKENS*D];     // layernorm output
__device__ float g_q  [TOKENS*D];     // (B,H,S,DK)
__device__ float g_k  [TOKENS*D];
__device__ float g_v  [TOKENS*D];
__device__ float g_ctx[TOKENS*D];     // (B,S,D)
__device__ float g_h  [TOKENS*DFF];   // ffn hidden
__device__ float g_pe [PREFIX*D];     // positional encodings

// ---------------- helpers ----------------
__device__ __forceinline__ float warp_sum(float v) {
    #pragma unroll
    for (int o = 16; o; o >>= 1) v += __shfl_xor_sync(0xffffffffu, v, o);
    return v;
}

// ---------------- PE table (double precision, matches numpy) --------------
__global__ void pe_kernel() {
    int s = blockIdx.x, d = threadIdx.x;
    double e   = pow(10000.0, ((double)(2 * d)) / 256.0);
    double arg = (double)s / e;
    g_pe[s * D + d] = (float)((d & 1) ? cos(arg) : sin(arg));
}

// ---------------- embedding + scale + PE ----------------
__global__ void embed_kernel(const int* __restrict__ src,
                             const float* __restrict__ emb) {
    int t = blockIdx.x, d = threadIdx.x;
    int s = t % SEQ;
    int tok = src[t];
    float v = emb[(size_t)tok * D + d];
    if (s < PREFIX) v = fmaf(v, 16.0f, g_pe[s * D + d]);
    g_x[(size_t)t * D + d] = v;
}

// ---------------- layernorm (ddof=1, eps on sd): g_x -> g_x2 --------------
__global__ void ln_kernel(const float* __restrict__ ga,
                          const float* __restrict__ gb) {
    __shared__ float red[8];
    __shared__ float stat;
    int t = blockIdx.x, d = threadIdx.x;
    size_t off = (size_t)t * D + d;
    float v = g_x[off];

    float s = warp_sum(v);
    if ((d & 31) == 0) red[d >> 5] = s;
    __syncthreads();
    if (d == 0) {
        float tt = 0.f;
        #pragma unroll
        for (int q = 0; q < 8; q++) tt += red[q];
        stat = tt * (1.0f / 256.0f);
    }
    __syncthreads();
    float mu = stat;
    float diff = v - mu;

    float ss = warp_sum(diff * diff);
    if ((d & 31) == 0) red[d >> 5] = ss;
    __syncthreads();
    if (d == 0) {
        float tt = 0.f;
        #pragma unroll
        for (int q = 0; q < 8; q++) tt += red[q];
        stat = 1.0f / (sqrtf(tt * (1.0f / 255.0f)) + 1e-6f);
    }
    __syncthreads();
    g_x2[off] = fmaf(ga[d], diff * stat, gb[d]);
}

// ---------------- SGEMM: C(M,N) = A(M,K) @ W(K,N) (+bias, epilogues) ------
// EPI 0: QKV  -> write (B,H,S,DK) layout, +bias
// EPI 1: WO   -> C = res + acc + bias
// EPI 2: FFN1 -> C = relu(acc + bias)
// EPI 3: FFN2 -> C = res + acc + bias
template<int EPI>
__global__ __launch_bounds__(256)
void sgemm_kernel(const float* __restrict__ A, const float* __restrict__ W,
                  const float* __restrict__ bias, const float* res,
                  float* C, int M, int N, int K) {
    __shared__ float As[8][128];
    __shared__ float Bs[8][128];
    const int tid = threadIdx.x;
    const int bm = blockIdx.y * 128;
    const int bn = blockIdx.x * 128;
    const int tx = tid & 15;
    const int ty = tid >> 4;
    const int arow = tid >> 1;
    const int acol = (tid & 1) * 4;
    const int brow = tid >> 5;
    const int bcol = (tid & 31) * 4;

    const float* Aptr = A + (size_t)(bm + arow) * K + acol;
    const float* Wptr = W + (size_t)brow * N + bn + bcol;

    float acc[8][8];
    #pragma unroll
    for (int i = 0; i < 8; i++)
        #pragma unroll
        for (int j = 0; j < 8; j++) acc[i][j] = 0.f;

    for (int k0 = 0; k0 < K; k0 += 8) {
        float4 av = *(const float4*)(Aptr + k0);
        float4 bv = *(const float4*)(Wptr + (size_t)k0 * N);
        As[acol + 0][arow] = av.x;
        As[acol + 1][arow] = av.y;
        As[acol + 2][arow] = av.z;
        As[acol + 3][arow] = av.w;
        *(float4*)(&Bs[brow][bcol]) = bv;
        __syncthreads();
        #pragma unroll
        for (int kk = 0; kk < 8; kk++) {
            float a[8], b[8];
            #pragma unroll
            for (int i = 0; i < 8; i++) a[i] = As[kk][ty * 8 + i];
            #pragma unroll
            for (int j = 0; j < 8; j++) b[j] = Bs[kk][tx * 8 + j];
            #pragma unroll
            for (int i = 0; i < 8; i++)
                #pragma unroll
                for (int j = 0; j < 8; j++)
                    acc[i][j] = fmaf(a[i], b[j], acc[i][j]);
        }
        __syncthreads();
    }

    #pragma unroll
    for (int i = 0; i < 8; i++) {
        int row = bm + ty * 8 + i;
        if (EPI == 0) {
            int bb = row / SEQ;
            int s  = row - bb * SEQ;
            float* cb = C + (size_t)bb * (H * HSTRIDE) + s * DK;
            #pragma unroll
            for (int j = 0; j < 8; j++) {
                int col = bn + tx * 8 + j;
                cb[(col >> 6) * HSTRIDE + (col & 63)] = acc[i][j] + bias[col];
            }
        } else {
            size_t ro = (size_t)row * N;
            #pragma unroll
            for (int j = 0; j < 8; j++) {
                int col = bn + tx * 8 + j;
                float v = acc[i][j] + bias[col];
                if (EPI == 2)      C[ro + col] = fmaxf(v, 0.f);
                else               C[ro + col] = res[ro + col] + v;
            }
        }
    }
}

// ---------------- attention: one block per (b,h), warp per query ----------
#define SKS 66   // padded K row stride (conflict-free float2 reads)
#define ATTN_SMEM ((SEQ*SKS + SEQ*DK + 16*DK + 16*SEQ) * sizeof(float))

__global__ __launch_bounds__(512)
void attn_kernel(const int* __restrict__ src) {
    extern __shared__ float sm[];
    float* sK = sm;                       // SEQ*SKS
    float* sV = sm + SEQ * SKS;           // SEQ*DK
    float* sQ = sV + SEQ * DK;            // 16*DK
    float* sP = sQ + 16 * DK;             // 16*SEQ

    int bh = blockIdx.x;
    int b  = bh >> 2;
    size_t hb = (size_t)bh * HSTRIDE;
    int tid = threadIdx.x;

    for (int i = tid; i < SEQ * DK; i += 512) {
        int j = i >> 6, dk = i & 63;
        sK[j * SKS + dk] = g_k[hb + i];
        sV[i]            = g_v[hb + i];
    }
    __syncthreads();

    int w = tid >> 5, lane = tid & 31;
    float* qrow = sQ + w * DK;
    float* prow = sP + w * SEQ;
    const float2* q2 = (const float2*)qrow;
    const float2* v2 = (const float2*)sV;

    for (int s = w; s < SEQ; s += 16) {
        qrow[lane]      = g_q[hb + s * DK + lane]      * 0.125f;   // 1/sqrt(64)
        qrow[lane + 32] = g_q[hb + s * DK + lane + 32] * 0.125f;
        __syncwarp();
        bool validq = (src[b * SEQ + s] != PADTOK);

        float sc[12];
        #pragma unroll
        for (int t = 0; t < 12; t++) {
            int j = t * 32 + lane;
            if (j < SEQ) {
                const float2* k2 = (const float2*)(sK + j * SKS);
                float a = 0.f;
                #pragma unroll
                for (int d2 = 0; d2 < 32; d2++) {
                    float2 qq = q2[d2], kk = k2[d2];
                    a = fmaf(qq.x, kk.x, a);
                    a = fmaf(qq.y, kk.y, a);
                }
                sc[t] = validq ? a : 0.f;   // pad query -> uniform softmax
            } else sc[t] = -1e30f;
        }

        float m = sc[0];
        #pragma unroll
        for (int t = 1; t < 12; t++) m = fmaxf(m, sc[t]);
        #pragma unroll
        for (int o = 16; o; o >>= 1) m = fmaxf(m, __shfl_xor_sync(0xffffffffu, m, o));

        float ssum = 0.f;
        #pragma unroll
        for (int t = 0; t < 12; t++) { float e = expf(sc[t] - m); sc[t] = e; ssum += e; }
        #pragma unroll
        for (int o = 16; o; o >>= 1) ssum += __shfl_xor_sync(0xffffffffu, ssum, o);
        float inv = 1.f / ssum;

        #pragma unroll
        for (int t = 0; t < 12; t++) {
            int j = t * 32 + lane;
            if (j < SEQ) prow[j] = sc[t] * inv;
        }
        __syncwarp();

        float cx = 0.f, cy = 0.f;
        #pragma unroll 6
        for (int j = 0; j < SEQ; j++) {
            float p = prow[j];
            float2 vv = v2[j * 32 + lane];
            cx = fmaf(p, vv.x, cx);
            cy = fmaf(p, vv.y, cy);
        }
        size_t ob = ((size_t)(b * SEQ + s)) * D + (bh & 3) * DK + lane * 2;
        *(float2*)(g_ctx + ob) = make_float2(cx, cy);
        __syncwarp();
    }
}

// ---------------- classifier + output masks ----------------
__global__ void cls_kernel(const int* __restrict__ src,
                           const float* __restrict__ wl,
                           const float* __restrict__ bl,
                           float* __restrict__ out) {
    int bp = blockIdx.x;
    int b = bp / NPAIR, p = bp - b * NPAIR;

    // pair index -> (i, j, pe)
    int i = 0, rem = p;
    while (rem >= 13 - i) { rem -= 13 - i; i++; }
    int j = i + 1 + rem;
    int base = i * 12 - (i * (i - 1)) / 2;     // sum_{t<i}(12-t)
    int pe = base + (j - i) - 1;
    int eb = 28 + 2 * pe;                      // GIDX edge base
    int gidx[8] = {2*i, 2*i+1, 2*j, 2*j+1, eb, eb+1, eb+2, eb+3};

    int tid = threadIdx.x;                     // 256 threads, one per dim
    const float* xb = g_x + (size_t)(b * SEQ) * D;
    int slots = (j < 13) ? 8 : 4;              // ZMASK zeros slots 4..7 if j==13

    float a0 = 0.f, a1 = 0.f, a2 = 0.f;
    for (int sl = 0; sl < slots; sl++) {
        float xv = xb[gidx[sl] * D + tid];
        const float* wr = wl + ((size_t)(sl * D + tid)) * 3;
        a0 = fmaf(xv, wr[0], a0);
        a1 = fmaf(xv, wr[1], a1);
        a2 = fmaf(xv, wr[2], a2);
    }
    a0 = warp_sum(a0); a1 = warp_sum(a1); a2 = warp_sum(a2);

    __shared__ float red[8][3];
    int lane = tid & 31, w = tid >> 5;
    if (lane == 0) { red[w][0] = a0; red[w][1] = a1; red[w][2] = a2; }
    __syncthreads();

    if (tid == 0) {
        float s0 = bl[0], s1 = bl[1], s2 = bl[2];
        #pragma unroll
        for (int t = 0; t < 8; t++) { s0 += red[t][0]; s1 += red[t][1]; s2 += red[t][2]; }

        const int* sb = src + b * SEQ;
        int ti = sb[2*i], ai = sb[2*i+1], tj = sb[2*j], aj = sb[2*j+1];
        bool c1 = (ai == 2) || (aj == 2);
        bool c2 = (tj == 1) || (ai == 1) || (aj == 1);
        bool c3 = (ti == PADTOK) || (tj == PADTOK) || (ai == 0) || (aj == 0);
        bool c4 = false;
        if (j < 13) {
            int es = 28 + 4 * pe;              // note: 4*pe here (EIDX), not 2*pe
            c4 = (sb[es] == 1) || (sb[es+1] == 1) || (sb[es+2] == 1) || (sb[es+3] == 1);
        }
        bool m111 = c3 || c4;
        bool mk1 = m111 || c2;
        bool mk2 = mk1 || c1;
        float* o = out + (size_t)bp * 3;
        o[0] = m111 ? -1e9f : s0;
        o[1] = mk1  ? -1e9f : s1;
        o[2] = mk2  ? -1e9f : s2;
    }
}

// ---------------- launch ----------------
extern "C" void kernel_launch(void* const* d_in, const int* in_sizes, int n_in,
                              void* d_out, int out_size) {
    (void)in_sizes; (void)n_in; (void)out_size;
    const int*   src = (const int*)  d_in[0];
    const float* emb = (const float*)d_in[1];
    const float* wq  = (const float*)d_in[2];
    const float* bq  = (const float*)d_in[3];
    const float* wk  = (const float*)d_in[4];
    const float* bk  = (const float*)d_in[5];
    const float* wv  = (const float*)d_in[6];
    const float* bv  = (const float*)d_in[7];
    const float* wo  = (const float*)d_in[8];
    const float* bo  = (const float*)d_in[9];
    const float* n1a = (const float*)d_in[10];
    const float* n1b = (const float*)d_in[11];
    const float* n2a = (const float*)d_in[12];
    const float* n2b = (const float*)d_in[13];
    const float* w1  = (const float*)d_in[14];
    const float* b1  = (const float*)d_in[15];
    const float* w2  = (const float*)d_in[16];
    const float* b2  = (const float*)d_in[17];
    const float* wl  = (const float*)d_in[18];
    const float* bl  = (const float*)d_in[19];
    float* out = (float*)d_out;

    float *px, *px2, *pq, *pk, *pv, *pctx, *ph;
    cudaGetSymbolAddress((void**)&px,   g_x);
    cudaGetSymbolAddress((void**)&px2,  g_x2);
    cudaGetSymbolAddress((void**)&pq,   g_q);
    cudaGetSymbolAddress((void**)&pk,   g_k);
    cudaGetSymbolAddress((void**)&pv,   g_v);
    cudaGetSymbolAddress((void**)&pctx, g_ctx);
    cudaGetSymbolAddress((void**)&ph,   g_h);

    cudaFuncSetAttribute(attn_kernel, cudaFuncAttributeMaxDynamicSharedMemorySize,
                         (int)ATTN_SMEM);

    // 1. PE table + embedding
    pe_kernel<<<PREFIX, D>>>();
    embed_kernel<<<TOKENS, D>>>(src, emb);

    // 2. layernorm 1 (g_x -> g_x2)
    ln_kernel<<<TOKENS, D>>>(n1a, n1b);

    // 3. QKV projections (EPI 0 writes (B,H,S,DK) layout)
    dim3 g256(D / 128, TOKENS / 128);
    sgemm_kernel<0><<<g256, 256>>>(px2, wq, bq, nullptr, pq, TOKENS, D, D);
    sgemm_kernel<0><<<g256, 256>>>(px2, wk, bk, nullptr, pk, TOKENS, D, D);
    sgemm_kernel<0><<<g256, 256>>>(px2, wv, bv, nullptr, pv, TOKENS, D, D);

    // 4. attention
    attn_kernel<<<HEADS, 512, ATTN_SMEM>>>(src);

    // 5. output projection + residual (x += ctx@wo + bo)
    sgemm_kernel<1><<<g256, 256>>>(pctx, wo, bo, px, px, TOKENS, D, D);

    // 6. layernorm 2 (g_x -> g_x2)
    ln_kernel<<<TOKENS, D>>>(n2a, n2b);

    // 7. FFN
    dim3 gff1(DFF / 128, TOKENS / 128);
    sgemm_kernel<2><<<gff1, 256>>>(px2, w1, b1, nullptr, ph, TOKENS, DFF, D);
    sgemm_kernel<3><<<g256, 256>>>(ph, w2, b2, px, px, TOKENS, D, DFF);

    // 8. classifier + masks
    cls_kernel<<<BATCH * NPAIR, D>>>(src, wl, bl, out);
}

// round 7
// speedup vs baseline: 1.8856x; 1.8856x over previous
#include <cuda_runtime.h>
#include <math.h>

// ---------------- problem constants ----------------
#define BATCH   256
#define SEQ     360
#define PREFIX  340
#define D       256
#define H       4
#define DK      64
#define DFF     2048
#define NPAIR   91
#define PADTOK  799
#define TOKENS  (BATCH*SEQ)          // 92160
#define HEADS   (BATCH*H)            // 1024
#define HSTRIDE (SEQ*DK)             // 23040

// ---------------- scratch (device globals, no cudaMalloc allowed) ----------
__device__ float g_x  [TOKENS*D];     // residual stream
__device__ float g_x2 [TOKENS*D];     // layernorm output
__device__ float g_q  [TOKENS*D];     // (B,H,S,DK)
__device__ float g_k  [TOKENS*D];
__device__ float g_v  [TOKENS*D];
__device__ float g_ctx[TOKENS*D];     // (B,S,D)
__device__ float g_h  [TOKENS*DFF];   // ffn hidden
__device__ float g_pe [PREFIX*D];     // positional encodings

// ---------------- helpers ----------------
__device__ __forceinline__ float warp_sum(float v) {
    #pragma unroll
    for (int o = 16; o; o >>= 1) v += __shfl_xor_sync(0xffffffffu, v, o);
    return v;
}
__device__ __forceinline__ unsigned f2tf32(float f) {
    unsigned u;
    asm("cvt.rna.tf32.f32 %0, %1;" : "=r"(u) : "f"(f));
    return u;
}

// ---------------- PE table (double precision, matches numpy) --------------
__global__ void pe_kernel() {
    int s = blockIdx.x, d = threadIdx.x;
    double e   = pow(10000.0, ((double)(2 * d)) / 256.0);
    double arg = (double)s / e;
    g_pe[s * D + d] = (float)((d & 1) ? cos(arg) : sin(arg));
}

// ---------------- embedding + scale + PE ----------------
__global__ void embed_kernel(const int* __restrict__ src,
                             const float* __restrict__ emb) {
    int t = blockIdx.x, d = threadIdx.x;
    int s = t % SEQ;
    int tok = src[t];
    float v = emb[(size_t)tok * D + d];
    if (s < PREFIX) v = fmaf(v, 16.0f, g_pe[s * D + d]);
    g_x[(size_t)t * D + d] = v;
}

// ---------------- layernorm (ddof=1, eps on sd): g_x -> g_x2 --------------
__global__ void ln_kernel(const float* __restrict__ ga,
                          const float* __restrict__ gb) {
    __shared__ float red[8];
    __shared__ float stat;
    int t = blockIdx.x, d = threadIdx.x;
    size_t off = (size_t)t * D + d;
    float v = g_x[off];

    float s = warp_sum(v);
    if ((d & 31) == 0) red[d >> 5] = s;
    __syncthreads();
    if (d == 0) {
        float tt = 0.f;
        #pragma unroll
        for (int q = 0; q < 8; q++) tt += red[q];
        stat = tt * (1.0f / 256.0f);
    }
    __syncthreads();
    float mu = stat;
    float diff = v - mu;

    float ss = warp_sum(diff * diff);
    if ((d & 31) == 0) red[d >> 5] = ss;
    __syncthreads();
    if (d == 0) {
        float tt = 0.f;
        #pragma unroll
        for (int q = 0; q < 8; q++) tt += red[q];
        stat = 1.0f / (sqrtf(tt * (1.0f / 255.0f)) + 1e-6f);
    }
    __syncthreads();
    g_x2[off] = fmaf(ga[d], diff * stat, gb[d]);
}

// ---------------- TF32 tensor-core GEMM ----------------
// C(M,N) = A(M,K) @ W(K,N) (+bias, epilogues)
// EPI 0: QKV  -> write (B,H,S,DK) layout, +bias
// EPI 1: WO   -> C = res + acc + bias
// EPI 2: FFN1 -> C = relu(acc + bias)
// EPI 3: FFN2 -> C = res + acc + bias
// Block tile 128x128x16, 256 threads, 8 warps (2x4), warp tile 64x32.
#define ASTR 20    // A smem stride (floats): conflict-free for frag reads
#define BSTR 136   // B smem stride (floats): conflict-free for frag reads

template<int EPI>
__global__ __launch_bounds__(256)
void tgemm_kernel(const float* __restrict__ A, const float* __restrict__ W,
                  const float* __restrict__ bias, const float* __restrict__ res,
                  float* __restrict__ C, int M, int N, int K) {
    __shared__ unsigned As[128 * ASTR];
    __shared__ unsigned Bs[16 * BSTR];

    const int tid = threadIdx.x;
    const int lane = tid & 31;
    const int wid  = tid >> 5;
    const int warp_m = wid >> 2;        // 0..1  (64 rows each)
    const int warp_n = wid & 3;         // 0..3  (32 cols each)
    const int g = lane >> 2;            // group id 0..7
    const int t = lane & 3;             // thread-in-group 0..3

    const int bm = blockIdx.y * 128;
    const int bn = blockIdx.x * 128;

    // gmem load mapping
    const int ar = tid >> 1;                 // A row 0..127
    const int ac = (tid & 1) * 8;            // A col {0,8}
    const int br0 = tid >> 5;                // B rows 0..7 (and +8)
    const int bc  = (tid & 31) * 4;          // B col4*4

    const float* Ap = A + (size_t)(bm + ar) * K + ac;
    const float* Wp0 = W + (size_t)br0 * N + bn + bc;
    const float* Wp1 = W + (size_t)(br0 + 8) * N + bn + bc;

    float acc[4][4][4];
    #pragma unroll
    for (int mi = 0; mi < 4; mi++)
        #pragma unroll
        for (int ni = 0; ni < 4; ni++)
            #pragma unroll
            for (int r = 0; r < 4; r++) acc[mi][ni][r] = 0.f;

    // prefetch first tile
    float4 av0 = *(const float4*)(Ap);
    float4 av1 = *(const float4*)(Ap + 4);
    float4 bv0 = *(const float4*)(Wp0);
    float4 bv1 = *(const float4*)(Wp1);

    for (int k0 = 0; k0 < K; k0 += 16) {
        // store staged tile to smem (with tf32 rounding)
        {
            unsigned4_t: ;
            uint4 ua0 = make_uint4(f2tf32(av0.x), f2tf32(av0.y), f2tf32(av0.z), f2tf32(av0.w));
            uint4 ua1 = make_uint4(f2tf32(av1.x), f2tf32(av1.y), f2tf32(av1.z), f2tf32(av1.w));
            *(uint4*)(&As[ar * ASTR + ac])     = ua0;
            *(uint4*)(&As[ar * ASTR + ac + 4]) = ua1;
            uint4 ub0 = make_uint4(f2tf32(bv0.x), f2tf32(bv0.y), f2tf32(bv0.z), f2tf32(bv0.w));
            uint4 ub1 = make_uint4(f2tf32(bv1.x), f2tf32(bv1.y), f2tf32(bv1.z), f2tf32(bv1.w));
            *(uint4*)(&Bs[br0 * BSTR + bc])       = ub0;
            *(uint4*)(&Bs[(br0 + 8) * BSTR + bc]) = ub1;
        }
        __syncthreads();

        // prefetch next tile (overlaps with compute below)
        if (k0 + 16 < K) {
            av0 = *(const float4*)(Ap + k0 + 16);
            av1 = *(const float4*)(Ap + k0 + 20);
            bv0 = *(const float4*)(Wp0 + (size_t)(k0 + 16) * N);
            bv1 = *(const float4*)(Wp1 + (size_t)(k0 + 16) * N);
        }

        #pragma unroll
        for (int kk = 0; kk < 16; kk += 8) {
            unsigned af[4][4], bf[4][2];
            #pragma unroll
            for (int mi = 0; mi < 4; mi++) {
                int r = warp_m * 64 + mi * 16 + g;
                int c = kk + t;
                af[mi][0] = As[r * ASTR + c];
                af[mi][1] = As[(r + 8) * ASTR + c];
                af[mi][2] = As[r * ASTR + c + 4];
                af[mi][3] = As[(r + 8) * ASTR + c + 4];
            }
            #pragma unroll
            for (int ni = 0; ni < 4; ni++) {
                int col = warp_n * 32 + ni * 8 + g;
                int rb = kk + t;
                bf[ni][0] = Bs[rb * BSTR + col];
                bf[ni][1] = Bs[(rb + 4) * BSTR + col];
            }
            #pragma unroll
            for (int mi = 0; mi < 4; mi++)
                #pragma unroll
                for (int ni = 0; ni < 4; ni++) {
                    asm volatile(
                        "mma.sync.aligned.m16n8k8.row.col.f32.tf32.tf32.f32 "
                        "{%0,%1,%2,%3}, {%4,%5,%6,%7}, {%8,%9}, {%0,%1,%2,%3};"
                        : "+f"(acc[mi][ni][0]), "+f"(acc[mi][ni][1]),
                          "+f"(acc[mi][ni][2]), "+f"(acc[mi][ni][3])
                        : "r"(af[mi][0]), "r"(af[mi][1]), "r"(af[mi][2]), "r"(af[mi][3]),
                          "r"(bf[ni][0]), "r"(bf[ni][1]));
                }
        }
        __syncthreads();
    }

    // ------------- epilogue -------------
    #pragma unroll
    for (int mi = 0; mi < 4; mi++) {
        int row0 = bm + warp_m * 64 + mi * 16 + g;   // rows row0 and row0+8
        #pragma unroll
        for (int ni = 0; ni < 4; ni++) {
            int col = bn + warp_n * 32 + ni * 8 + t * 2;
            float2 bb = *(const float2*)(bias + col);
            #pragma unroll
            for (int half = 0; half < 2; half++) {
                int row = row0 + half * 8;
                float v0 = acc[mi][ni][half * 2 + 0] + bb.x;
                float v1 = acc[mi][ni][half * 2 + 1] + bb.y;
                if (EPI == 0) {
                    int bbt = row / SEQ;
                    int s   = row - bbt * SEQ;
                    int head = col >> 6, dk = col & 63;
                    float* cb = C + (size_t)bbt * (H * HSTRIDE) + head * HSTRIDE
                                  + s * DK + dk;
                    *(float2*)cb = make_float2(v0, v1);
                } else {
                    size_t ro = (size_t)row * N + col;
                    if (EPI == 2) {
                        *(float2*)(C + ro) = make_float2(fmaxf(v0, 0.f), fmaxf(v1, 0.f));
                    } else {
                        float2 rv = *(const float2*)(res + ro);
                        *(float2*)(C + ro) = make_float2(rv.x + v0, rv.y + v1);
                    }
                }
            }
        }
    }
}

// ---------------- attention: one block per (b,h), warp per query ----------
#define SKS 68   // padded K row stride (conflict-free float4 reads)
#define ATTN_SMEM ((SEQ*SKS + SEQ*DK + 16*DK + 16*SEQ) * sizeof(float))

__global__ __launch_bounds__(512)
void attn_kernel(const int* __restrict__ src) {
    extern __shared__ float sm[];
    float* sK = sm;                       // SEQ*SKS
    float* sV = sm + SEQ * SKS;           // SEQ*DK
    float* sQ = sV + SEQ * DK;            // 16*DK
    float* sP = sQ + 16 * DK;             // 16*SEQ

    int bh = blockIdx.x;
    int b  = bh >> 2;
    size_t hb = (size_t)bh * HSTRIDE;
    int tid = threadIdx.x;

    for (int i = tid; i < SEQ * DK; i += 512) {
        int j = i >> 6, dk = i & 63;
        sK[j * SKS + dk] = g_k[hb + i];
        sV[i]            = g_v[hb + i];
    }
    __syncthreads();

    int w = tid >> 5, lane = tid & 31;
    int l16 = lane & 15, jj = lane >> 4;
    float* qrow = sQ + w * DK;
    float* prow = sP + w * SEQ;
    const float4* q4 = (const float4*)qrow;
    const float4* v4 = (const float4*)sV;

    for (int s = w; s < SEQ; s += 16) {
        qrow[lane]      = g_q[hb + s * DK + lane]      * 0.125f;   // 1/sqrt(64)
        qrow[lane + 32] = g_q[hb + s * DK + lane + 32] * 0.125f;
        __syncwarp();
        bool validq = (src[b * SEQ + s] != PADTOK);

        float sc[12];
        #pragma unroll
        for (int tt = 0; tt < 12; tt++) {
            int j = tt * 32 + lane;
            if (j < SEQ) {
                const float4* k4 = (const float4*)(sK + (size_t)j * SKS);
                float a = 0.f;
                #pragma unroll
                for (int d4 = 0; d4 < 16; d4++) {
                    float4 qq = q4[d4], kk = k4[d4];
                    a = fmaf(qq.x, kk.x, a);
                    a = fmaf(qq.y, kk.y, a);
                    a = fmaf(qq.z, kk.z, a);
                    a = fmaf(qq.w, kk.w, a);
                }
                sc[tt] = validq ? a : 0.f;   // pad query -> uniform softmax
            } else sc[tt] = -1e30f;
        }

        float m = sc[0];
        #pragma unroll
        for (int tt = 1; tt < 12; tt++) m = fmaxf(m, sc[tt]);
        #pragma unroll
        for (int o = 16; o; o >>= 1) m = fmaxf(m, __shfl_xor_sync(0xffffffffu, m, o));

        float ssum = 0.f;
        #pragma unroll
        for (int tt = 0; tt < 12; tt++) { float e = expf(sc[tt] - m); sc[tt] = e; ssum += e; }
        #pragma unroll
        for (int o = 16; o; o >>= 1) ssum += __shfl_xor_sync(0xffffffffu, ssum, o);
        float inv = 1.f / ssum;

        #pragma unroll
        for (int tt = 0; tt < 12; tt++) {
            int j = tt * 32 + lane;
            if (j < SEQ) prow[j] = sc[tt] * inv;
        }
        __syncwarp();

        // PV: half-warps each take one of 2 keys per iter, lane owns 4 dims
        float cx = 0.f, cy = 0.f, cz = 0.f, cw = 0.f;
        const float2* p2v = (const float2*)prow;
        #pragma unroll 4
        for (int j0 = 0; j0 < SEQ; j0 += 2) {
            float2 pp = p2v[j0 >> 1];
            float p = jj ? pp.y : pp.x;
            float4 vv = v4[(j0 + jj) * 16 + l16];
            cx = fmaf(p, vv.x, cx);
            cy = fmaf(p, vv.y, cy);
            cz = fmaf(p, vv.z, cz);
            cw = fmaf(p, vv.w, cw);
        }
        cx += __shfl_xor_sync(0xffffffffu, cx, 16);
        cy += __shfl_xor_sync(0xffffffffu, cy, 16);
        cz += __shfl_xor_sync(0xffffffffu, cz, 16);
        cw += __shfl_xor_sync(0xffffffffu, cw, 16);
        if (jj == 0) {
            size_t ob = ((size_t)(b * SEQ + s)) * D + (bh & 3) * DK + l16 * 4;
            *(float4*)(g_ctx + ob) = make_float4(cx, cy, cz, cw);
        }
        __syncwarp();
    }
}

// ---------------- classifier + output masks ----------------
__global__ void cls_kernel(const int* __restrict__ src,
                           const float* __restrict__ wl,
                           const float* __restrict__ bl,
                           float* __restrict__ out) {
    int bp = blockIdx.x;
    int b = bp / NPAIR, p = bp - b * NPAIR;

    // pair index -> (i, j, pe)
    int i = 0, rem = p;
    while (rem >= 13 - i) { rem -= 13 - i; i++; }
    int j = i + 1 + rem;
    int base = i * 12 - (i * (i - 1)) / 2;     // sum_{t<i}(12-t)
    int pe = base + (j - i) - 1;
    int eb = 28 + 2 * pe;                      // GIDX edge base
    int gidx[8] = {2*i, 2*i+1, 2*j, 2*j+1, eb, eb+1, eb+2, eb+3};

    int tid = threadIdx.x;                     // 256 threads, one per dim
    const float* xb = g_x + (size_t)(b * SEQ) * D;
    int slots = (j < 13) ? 8 : 4;              // ZMASK zeros slots 4..7 if j==13

    float a0 = 0.f, a1 = 0.f, a2 = 0.f;
    for (int sl = 0; sl < slots; sl++) {
        float xv = xb[gidx[sl] * D + tid];
        const float* wr = wl + ((size_t)(sl * D + tid)) * 3;
        a0 = fmaf(xv, wr[0], a0);
        a1 = fmaf(xv, wr[1], a1);
        a2 = fmaf(xv, wr[2], a2);
    }
    a0 = warp_sum(a0); a1 = warp_sum(a1); a2 = warp_sum(a2);

    __shared__ float red[8][3];
    int lane = tid & 31, w = tid >> 5;
    if (lane == 0) { red[w][0] = a0; red[w][1] = a1; red[w][2] = a2; }
    __syncthreads();

    if (tid == 0) {
        float s0 = bl[0], s1 = bl[1], s2 = bl[2];
        #pragma unroll
        for (int t = 0; t < 8; t++) { s0 += red[t][0]; s1 += red[t][1]; s2 += red[t][2]; }

        const int* sb = src + b * SEQ;
        int ti = sb[2*i], ai = sb[2*i+1], tj = sb[2*j], aj = sb[2*j+1];
        bool c1 = (ai == 2) || (aj == 2);
        bool c2 = (tj == 1) || (ai == 1) || (aj == 1);
        bool c3 = (ti == PADTOK) || (tj == PADTOK) || (ai == 0) || (aj == 0);
        bool c4 = false;
        if (j < 13) {
            int es = 28 + 4 * pe;              // EIDX base: 4*pe (not 2*pe)
            c4 = (sb[es] == 1) || (sb[es+1] == 1) || (sb[es+2] == 1) || (sb[es+3] == 1);
        }
        bool m111 = c3 || c4;
        bool mk1 = m111 || c2;
        bool mk2 = mk1 || c1;
        float* o = out + (size_t)bp * 3;
        o[0] = m111 ? -1e9f : s0;
        o[1] = mk1  ? -1e9f : s1;
        o[2] = mk2  ? -1e9f : s2;
    }
}

// ---------------- launch ----------------
extern "C" void kernel_launch(void* const* d_in, const int* in_sizes, int n_in,
                              void* d_out, int out_size) {
    (void)in_sizes; (void)n_in; (void)out_size;
    const int*   src = (const int*)  d_in[0];
    const float* emb = (const float*)d_in[1];
    const float* wq  = (const float*)d_in[2];
    const float* bq  = (const float*)d_in[3];
    const float* wk  = (const float*)d_in[4];
    const float* bk  = (const float*)d_in[5];
    const float* wv  = (const float*)d_in[6];
    const float* bv  = (const float*)d_in[7];
    const float* wo  = (const float*)d_in[8];
    const float* bo  = (const float*)d_in[9];
    const float* n1a = (const float*)d_in[10];
    const float* n1b = (const float*)d_in[11];
    const float* n2a = (const float*)d_in[12];
    const float* n2b = (const float*)d_in[13];
    const float* w1  = (const float*)d_in[14];
    const float* b1  = (const float*)d_in[15];
    const float* w2  = (const float*)d_in[16];
    const float* b2  = (const float*)d_in[17];
    const float* wl  = (const float*)d_in[18];
    const float* bl  = (const float*)d_in[19];
    float* out = (float*)d_out;

    float *px, *px2, *pq, *pk, *pv, *pctx, *ph;
    cudaGetSymbolAddress((void**)&px,   g_x);
    cudaGetSymbolAddress((void**)&px2,  g_x2);
    cudaGetSymbolAddress((void**)&pq,   g_q);
    cudaGetSymbolAddress((void**)&pk,   g_k);
    cudaGetSymbolAddress((void**)&pv,   g_v);
    cudaGetSymbolAddress((void**)&pctx, g_ctx);
    cudaGetSymbolAddress((void**)&ph,   g_h);

    cudaFuncSetAttribute(attn_kernel, cudaFuncAttributeMaxDynamicSharedMemorySize,
                         (int)ATTN_SMEM);

    // 1. PE table + embedding
    pe_kernel<<<PREFIX, D>>>();
    embed_kernel<<<TOKENS, D>>>(src, emb);

    // 2. layernorm 1 (g_x -> g_x2)
    ln_kernel<<<TOKENS, D>>>(n1a, n1b);

    // 3. QKV projections (EPI 0 writes (B,H,S,DK) layout)
    dim3 g256(D / 128, TOKENS / 128);
    tgemm_kernel<0><<<g256, 256>>>(px2, wq, bq, nullptr, pq, TOKENS, D, D);
    tgemm_kernel<0><<<g256, 256>>>(px2, wk, bk, nullptr, pk, TOKENS, D, D);
    tgemm_kernel<0><<<g256, 256>>>(px2, wv, bv, nullptr, pv, TOKENS, D, D);

    // 4. attention
    attn_kernel<<<HEADS, 512, ATTN_SMEM>>>(src);

    // 5. output projection + residual (x += ctx@wo + bo)
    tgemm_kernel<1><<<g256, 256>>>(pctx, wo, bo, px, px, TOKENS, D, D);

    // 6. layernorm 2 (g_x -> g_x2)
    ln_kernel<<<TOKENS, D>>>(n2a, n2b);

    // 7. FFN
    dim3 gff1(DFF / 128, TOKENS / 128);
    tgemm_kernel<2><<<gff1, 256>>>(px2, w1, b1, nullptr, ph, TOKENS, DFF, D);
    tgemm_kernel<3><<<g256, 256>>>(ph, w2, b2, px, px, TOKENS, D, DFF);

    // 8. classifier + masks
    cls_kernel<<<BATCH * NPAIR, D>>>(src, wl, bl, out);
}

// round 8
// speedup vs baseline: 2.3162x; 1.2283x over previous
#include <cuda_runtime.h>
#include <cuda_bf16.h>
#include <math.h>

// ---------------- problem constants ----------------
#define BATCH   256
#define SEQ     360
#define PREFIX  340
#define D       256
#define H       4
#define DK      64
#define DFF     2048
#define NPAIR   91
#define PADTOK  799
#define TOKENS  (BATCH*SEQ)          // 92160
#define HEADS   (BATCH*H)            // 1024
#define HSTRIDE (SEQ*DK)             // 23040

typedef __nv_bfloat16 bf16;
typedef __nv_bfloat162 bf162;

// ---------------- scratch (device globals) ----------------
__device__ float g_x  [TOKENS*D];       // residual stream (fp32)
__device__ bf16  g_xb [TOKENS*D];       // layernorm output (bf16)
__device__ float g_q  [TOKENS*D];       // (B,H,S,DK) fp32
__device__ float g_k  [TOKENS*D];
__device__ float g_v  [TOKENS*D];
__device__ bf16  g_ctxb[TOKENS*D];      // attention output (bf16)
__device__ bf16  g_hb [TOKENS*DFF];     // ffn hidden (bf16)
__device__ float g_pe [PREFIX*D];       // positional encodings
// transposed bf16 weights [N][K]
__device__ bf16  g_wqT[D*D];
__device__ bf16  g_wkT[D*D];
__device__ bf16  g_wvT[D*D];
__device__ bf16  g_woT[D*D];
__device__ bf16  g_w1T[D*DFF];
__device__ bf16  g_w2T[D*DFF];
__device__ float g_bqs[D];              // bq * 0.125

// ---------------- helpers ----------------
__device__ __forceinline__ float warp_sum(float v) {
    #pragma unroll
    for (int o = 16; o; o >>= 1) v += __shfl_xor_sync(0xffffffffu, v, o);
    return v;
}

// ---------------- PE table (double precision, matches numpy) --------------
__global__ void pe_kernel() {
    int s = blockIdx.x, d = threadIdx.x;
    double e   = pow(10000.0, ((double)(2 * d)) / 256.0);
    double arg = (double)s / e;
    g_pe[s * D + d] = (float)((d & 1) ? cos(arg) : sin(arg));
}

// ---------------- weight transpose + bf16 convert --------------------------
// w is [K][N] row-major fp32; wT is [N][K] bf16.
__global__ void convT_kernel(const float* __restrict__ w, bf16* __restrict__ wT,
                             int K, int N, float scale) {
    int idx = blockIdx.x * 256 + threadIdx.x;
    int k = idx / N, n = idx - k * N;
    wT[(size_t)n * K + k] = __float2bfloat16(w[idx] * scale);
}
__global__ void scaleb_kernel(const float* __restrict__ b) {
    g_bqs[threadIdx.x] = b[threadIdx.x] * 0.125f;
}

// ---------------- fused embedding + scale + PE + layernorm1 ---------------
__global__ void embed_ln_kernel(const int* __restrict__ src,
                                const float* __restrict__ emb,
                                const float* __restrict__ ga,
                                const float* __restrict__ gb) {
    __shared__ float red[8];
    __shared__ float stat;
    int t = blockIdx.x, d = threadIdx.x;
    int s = t % SEQ;
    int tok = src[t];
    float v = emb[(size_t)tok * D + d];
    if (s < PREFIX) v = fmaf(v, 16.0f, g_pe[s * D + d]);
    size_t off = (size_t)t * D + d;
    g_x[off] = v;

    float sum = warp_sum(v);
    if ((d & 31) == 0) red[d >> 5] = sum;
    __syncthreads();
    if (d == 0) {
        float tt = 0.f;
        #pragma unroll
        for (int q = 0; q < 8; q++) tt += red[q];
        stat = tt * (1.0f / 256.0f);
    }
    __syncthreads();
    float diff = v - stat;

    float ss = warp_sum(diff * diff);
    if ((d & 31) == 0) red[d >> 5] = ss;
    __syncthreads();
    if (d == 0) {
        float tt = 0.f;
        #pragma unroll
        for (int q = 0; q < 8; q++) tt += red[q];
        stat = 1.0f / (sqrtf(tt * (1.0f / 255.0f)) + 1e-6f);
    }
    __syncthreads();
    g_xb[off] = __float2bfloat16(fmaf(ga[d], diff * stat, gb[d]));
}

// ---------------- layernorm 2 (g_x -> g_xb, ddof=1, eps on sd) ------------
__global__ void ln_kernel(const float* __restrict__ ga,
                          const float* __restrict__ gb) {
    __shared__ float red[8];
    __shared__ float stat;
    int t = blockIdx.x, d = threadIdx.x;
    size_t off = (size_t)t * D + d;
    float v = g_x[off];

    float s = warp_sum(v);
    if ((d & 31) == 0) red[d >> 5] = s;
    __syncthreads();
    if (d == 0) {
        float tt = 0.f;
        #pragma unroll
        for (int q = 0; q < 8; q++) tt += red[q];
        stat = tt * (1.0f / 256.0f);
    }
    __syncthreads();
    float diff = v - stat;

    float ss = warp_sum(diff * diff);
    if ((d & 31) == 0) red[d >> 5] = ss;
    __syncthreads();
    if (d == 0) {
        float tt = 0.f;
        #pragma unroll
        for (int q = 0; q < 8; q++) tt += red[q];
        stat = 1.0f / (sqrtf(tt * (1.0f / 255.0f)) + 1e-6f);
    }
    __syncthreads();
    g_xb[off] = __float2bfloat16(fmaf(ga[d], diff * stat, gb[d]));
}

// ---------------- bf16 tensor-core GEMM ----------------
// C(M,N) = A(M,K) @ Wt(N,K)^T (+bias, epilogues)
// A: bf16 [M][K] row-major.  Wt: bf16 [N][K] row-major (pre-transposed).
// EPI 0: QKV  -> fp32 C in (B,H,S,DK) layout, +bias
// EPI 1: WO   -> fp32 C = res + acc + bias
// EPI 2: FFN1 -> bf16 C = relu(acc + bias)
// EPI 3: FFN2 -> fp32 C = res + acc + bias
// Block 128x128x32, 256 threads, 8 warps (2x4), warp tile 64x32, double-buffered.
#define STR32 20   // uint32 (bf16x2) stride per row; g*20+t distinct mod 32

template<int EPI>
__global__ __launch_bounds__(256)
void bgemm_kernel(const bf16* __restrict__ A, const bf16* __restrict__ Wt,
                  const float* __restrict__ bias, const float* __restrict__ res,
                  void* __restrict__ Cv, int M, int N, int K) {
    __shared__ unsigned As[2][128 * STR32];
    __shared__ unsigned Bs[2][128 * STR32];

    const int tid  = threadIdx.x;
    const int lane = tid & 31;
    const int wid  = tid >> 5;
    const int wm = wid >> 2;            // 0..1  (64 rows)
    const int wn = wid & 3;             // 0..3  (32 cols)
    const int g = lane >> 2;            // 0..7
    const int t = lane & 3;             // 0..3

    const int bm = blockIdx.y * 128;
    const int bn = blockIdx.x * 128;

    const int lrow = tid >> 1;          // 0..127
    const int lch  = tid & 1;           // 16-bf16 chunk
    const bf16* Ap = A  + (size_t)(bm + lrow) * K + lch * 16;
    const bf16* Bp = Wt + (size_t)(bn + lrow) * K + lch * 16;

    float acc[4][4][4];
    #pragma unroll
    for (int mi = 0; mi < 4; mi++)
        #pragma unroll
        for (int ni = 0; ni < 4; ni++)
            #pragma unroll
            for (int r = 0; r < 4; r++) acc[mi][ni][r] = 0.f;

    uint4 ap0 = *(const uint4*)(Ap);
    uint4 ap1 = *(const uint4*)(Ap + 8);
    uint4 bp0 = *(const uint4*)(Bp);
    uint4 bp1 = *(const uint4*)(Bp + 8);
    {
        unsigned* as = &As[0][lrow * STR32 + lch * 8];
        *(uint4*)as = ap0; *(uint4*)(as + 4) = ap1;
        unsigned* bs = &Bs[0][lrow * STR32 + lch * 8];
        *(uint4*)bs = bp0; *(uint4*)(bs + 4) = bp1;
    }
    __syncthreads();

    const int ntiles = K >> 5;
    for (int tl = 0; tl < ntiles; tl++) {
        const int cur = tl & 1, nxt = cur ^ 1;
        if (tl + 1 < ntiles) {
            const bf16* ap = Ap + (tl + 1) * 32;
            const bf16* bp = Bp + (tl + 1) * 32;
            ap0 = *(const uint4*)(ap);
            ap1 = *(const uint4*)(ap + 8);
            bp0 = *(const uint4*)(bp);
            bp1 = *(const uint4*)(bp + 8);
        }
        #pragma unroll
        for (int kk = 0; kk < 2; kk++) {          // two k16 halves
            unsigned af[4][4], bf[4][2];
            #pragma unroll
            for (int mi = 0; mi < 4; mi++) {
                const unsigned* base = &As[cur][(wm * 64 + mi * 16 + g) * STR32 + kk * 8 + t];
                af[mi][0] = base[0];
                af[mi][1] = base[8 * STR32];
                af[mi][2] = base[4];
                af[mi][3] = base[8 * STR32 + 4];
            }
            #pragma unroll
            for (int ni = 0; ni < 4; ni++) {
                const unsigned* base = &Bs[cur][(wn * 32 + ni * 8 + g) * STR32 + kk * 8 + t];
                bf[ni][0] = base[0];
                bf[ni][1] = base[4];
            }
            #pragma unroll
            for (int mi = 0; mi < 4; mi++)
                #pragma unroll
                for (int ni = 0; ni < 4; ni++) {
                    asm volatile(
                        "mma.sync.aligned.m16n8k16.row.col.f32.bf16.bf16.f32 "
                        "{%0,%1,%2,%3}, {%4,%5,%6,%7}, {%8,%9}, {%0,%1,%2,%3};"
                        : "+f"(acc[mi][ni][0]), "+f"(acc[mi][ni][1]),
                          "+f"(acc[mi][ni][2]), "+f"(acc[mi][ni][3])
                        : "r"(af[mi][0]), "r"(af[mi][1]), "r"(af[mi][2]), "r"(af[mi][3]),
                          "r"(bf[ni][0]), "r"(bf[ni][1]));
                }
        }
        if (tl + 1 < ntiles) {
            unsigned* as = &As[nxt][lrow * STR32 + lch * 8];
            *(uint4*)as = ap0; *(uint4*)(as + 4) = ap1;
            unsigned* bs = &Bs[nxt][lrow * STR32 + lch * 8];
            *(uint4*)bs = bp0; *(uint4*)(bs + 4) = bp1;
        }
        __syncthreads();
    }

    // ------------- epilogue -------------
    float* C  = (float*)Cv;
    bf16*  Cb = (bf16*)Cv;
    #pragma unroll
    for (int mi = 0; mi < 4; mi++) {
        int row0 = bm + wm * 64 + mi * 16 + g;
        #pragma unroll
        for (int ni = 0; ni < 4; ni++) {
            int col = bn + wn * 32 + ni * 8 + t * 2;
            float2 bb = *(const float2*)(bias + col);
            #pragma unroll
            for (int half = 0; half < 2; half++) {
                int row = row0 + half * 8;
                float v0 = acc[mi][ni][half * 2 + 0] + bb.x;
                float v1 = acc[mi][ni][half * 2 + 1] + bb.y;
                if (EPI == 0) {
                    int bbt = row / SEQ;
                    int s   = row - bbt * SEQ;
                    float* cb = C + (size_t)bbt * (H * HSTRIDE) + (col >> 6) * HSTRIDE
                                  + s * DK + (col & 63);
                    *(float2*)cb = make_float2(v0, v1);
                } else if (EPI == 2) {
                    *(bf162*)(Cb + (size_t)row * N + col) =
                        __floats2bfloat162_rn(fmaxf(v0, 0.f), fmaxf(v1, 0.f));
                } else {
                    size_t ro = (size_t)row * N + col;
                    float2 rv = *(const float2*)(res + ro);
                    *(float2*)(C + ro) = make_float2(rv.x + v0, rv.y + v1);
                }
            }
        }
    }
}

// ---------------- attention: one block per (b,h), warp per query ----------
#define SKS 68   // padded K row stride (conflict-free float4 reads)
#define ATTN_SMEM ((SEQ*SKS + SEQ*DK + 16*DK + 16*SEQ) * sizeof(float))

__global__ __launch_bounds__(512)
void attn_kernel(const int* __restrict__ src) {
    extern __shared__ float sm[];
    float* sK = sm;                       // SEQ*SKS
    float* sV = sm + SEQ * SKS;           // SEQ*DK
    float* sQ = sV + SEQ * DK;            // 16*DK
    float* sP = sQ + 16 * DK;             // 16*SEQ

    int bh = blockIdx.x;
    int b  = bh >> 2;
    size_t hb = (size_t)bh * HSTRIDE;
    int tid = threadIdx.x;

    for (int i = tid; i < SEQ * DK; i += 512) {
        int j = i >> 6, dk = i & 63;
        sK[j * SKS + dk] = g_k[hb + i];
        sV[i]            = g_v[hb + i];
    }
    __syncthreads();

    int w = tid >> 5, lane = tid & 31;
    int l16 = lane & 15, jj = lane >> 4;
    float* qrow = sQ + w * DK;
    float* prow = sP + w * SEQ;
    const float4* q4 = (const float4*)qrow;
    const float4* v4 = (const float4*)sV;

    for (int s = w; s < SEQ; s += 16) {
        qrow[lane]      = g_q[hb + s * DK + lane];       // scale folded into wq/bq
        qrow[lane + 32] = g_q[hb + s * DK + lane + 32];
        __syncwarp();
        bool validq = (src[b * SEQ + s] != PADTOK);

        float sc[12];
        #pragma unroll
        for (int tt = 0; tt < 12; tt++) {
            int j = tt * 32 + lane;
            if (j < SEQ) {
                const float4* k4 = (const float4*)(sK + (size_t)j * SKS);
                float a = 0.f;
                #pragma unroll
                for (int d4 = 0; d4 < 16; d4++) {
                    float4 qq = q4[d4], kk = k4[d4];
                    a = fmaf(qq.x, kk.x, a);
                    a = fmaf(qq.y, kk.y, a);
                    a = fmaf(qq.z, kk.z, a);
                    a = fmaf(qq.w, kk.w, a);
                }
                sc[tt] = validq ? a : 0.f;   // pad query -> uniform softmax
            } else sc[tt] = -1e30f;
        }

        float m = sc[0];
        #pragma unroll
        for (int tt = 1; tt < 12; tt++) m = fmaxf(m, sc[tt]);
        #pragma unroll
        for (int o = 16; o; o >>= 1) m = fmaxf(m, __shfl_xor_sync(0xffffffffu, m, o));

        float ssum = 0.f;
        #pragma unroll
        for (int tt = 0; tt < 12; tt++) { float e = expf(sc[tt] - m); sc[tt] = e; ssum += e; }
        #pragma unroll
        for (int o = 16; o; o >>= 1) ssum += __shfl_xor_sync(0xffffffffu, ssum, o);
        float inv = 1.f / ssum;

        #pragma unroll
        for (int tt = 0; tt < 12; tt++) {
            int j = tt * 32 + lane;
            if (j < SEQ) prow[j] = sc[tt] * inv;
        }
        __syncwarp();

        // PV: half-warps each take one of 2 keys per iter, lane owns 4 dims
        float cx = 0.f, cy = 0.f, cz = 0.f, cw = 0.f;
        const float2* p2v = (const float2*)prow;
        #pragma unroll 4
        for (int j0 = 0; j0 < SEQ; j0 += 2) {
            float2 pp = p2v[j0 >> 1];
            float p = jj ? pp.y : pp.x;
            float4 vv = v4[(j0 + jj) * 16 + l16];
            cx = fmaf(p, vv.x, cx);
            cy = fmaf(p, vv.y, cy);
            cz = fmaf(p, vv.z, cz);
            cw = fmaf(p, vv.w, cw);
        }
        cx += __shfl_xor_sync(0xffffffffu, cx, 16);
        cy += __shfl_xor_sync(0xffffffffu, cy, 16);
        cz += __shfl_xor_sync(0xffffffffu, cz, 16);
        cw += __shfl_xor_sync(0xffffffffu, cw, 16);
        if (jj == 0) {
            size_t ob = ((size_t)(b * SEQ + s)) * D + (bh & 3) * DK + l16 * 4;
            bf162 p0 = __floats2bfloat162_rn(cx, cy);
            bf162 p1 = __floats2bfloat162_rn(cz, cw);
            *(bf162*)(g_ctxb + ob)     = p0;
            *(bf162*)(g_ctxb + ob + 2) = p1;
        }
        __syncwarp();
    }
}

// ---------------- classifier + output masks ----------------
__global__ void cls_kernel(const int* __restrict__ src,
                           const float* __restrict__ wl,
                           const float* __restrict__ bl,
                           float* __restrict__ out) {
    int bp = blockIdx.x;
    int b = bp / NPAIR, p = bp - b * NPAIR;

    int i = 0, rem = p;
    while (rem >= 13 - i) { rem -= 13 - i; i++; }
    int j = i + 1 + rem;
    int base = i * 12 - (i * (i - 1)) / 2;
    int pe = base + (j - i) - 1;
    int eb = 28 + 2 * pe;
    int gidx[8] = {2*i, 2*i+1, 2*j, 2*j+1, eb, eb+1, eb+2, eb+3};

    int tid = threadIdx.x;
    const float* xb = g_x + (size_t)(b * SEQ) * D;
    int slots = (j < 13) ? 8 : 4;

    float a0 = 0.f, a1 = 0.f, a2 = 0.f;
    for (int sl = 0; sl < slots; sl++) {
        float xv = xb[gidx[sl] * D + tid];
        const float* wr = wl + ((size_t)(sl * D + tid)) * 3;
        a0 = fmaf(xv, wr[0], a0);
        a1 = fmaf(xv, wr[1], a1);
        a2 = fmaf(xv, wr[2], a2);
    }
    a0 = warp_sum(a0); a1 = warp_sum(a1); a2 = warp_sum(a2);

    __shared__ float red[8][3];
    int lane = tid & 31, w = tid >> 5;
    if (lane == 0) { red[w][0] = a0; red[w][1] = a1; red[w][2] = a2; }
    __syncthreads();

    if (tid == 0) {
        float s0 = bl[0], s1 = bl[1], s2 = bl[2];
        #pragma unroll
        for (int t = 0; t < 8; t++) { s0 += red[t][0]; s1 += red[t][1]; s2 += red[t][2]; }

        const int* sb = src + b * SEQ;
        int ti = sb[2*i], ai = sb[2*i+1], tj = sb[2*j], aj = sb[2*j+1];
        bool c1 = (ai == 2) || (aj == 2);
        bool c2 = (tj == 1) || (ai == 1) || (aj == 1);
        bool c3 = (ti == PADTOK) || (tj == PADTOK) || (ai == 0) || (aj == 0);
        bool c4 = false;
        if (j < 13) {
            int es = 28 + 4 * pe;              // EIDX base: 4*pe (not 2*pe)
            c4 = (sb[es] == 1) || (sb[es+1] == 1) || (sb[es+2] == 1) || (sb[es+3] == 1);
        }
        bool m111 = c3 || c4;
        bool mk1 = m111 || c2;
        bool mk2 = mk1 || c1;
        float* o = out + (size_t)bp * 3;
        o[0] = m111 ? -1e9f : s0;
        o[1] = mk1  ? -1e9f : s1;
        o[2] = mk2  ? -1e9f : s2;
    }
}

// ---------------- launch ----------------
extern "C" void kernel_launch(void* const* d_in, const int* in_sizes, int n_in,
                              void* d_out, int out_size) {
    (void)in_sizes; (void)n_in; (void)out_size;
    const int*   src = (const int*)  d_in[0];
    const float* emb = (const float*)d_in[1];
    const float* wq  = (const float*)d_in[2];
    const float* bq  = (const float*)d_in[3];
    const float* wk  = (const float*)d_in[4];
    const float* bk  = (const float*)d_in[5];
    const float* wv  = (const float*)d_in[6];
    const float* bv  = (const float*)d_in[7];
    const float* wo  = (const float*)d_in[8];
    const float* bo  = (const float*)d_in[9];
    const float* n1a = (const float*)d_in[10];
    const float* n1b = (const float*)d_in[11];
    const float* n2a = (const float*)d_in[12];
    const float* n2b = (const float*)d_in[13];
    const float* w1  = (const float*)d_in[14];
    const float* b1  = (const float*)d_in[15];
    const float* w2  = (const float*)d_in[16];
    const float* b2  = (const float*)d_in[17];
    const float* wl  = (const float*)d_in[18];
    const float* bl  = (const float*)d_in[19];
    float* out = (float*)d_out;

    float *px, *pq, *pk, *pv, *pbqs;
    bf16 *pxb, *pctxb, *phb, *pwqT, *pwkT, *pwvT, *pwoT, *pw1T, *pw2T;
    cudaGetSymbolAddress((void**)&px,    g_x);
    cudaGetSymbolAddress((void**)&pxb,   g_xb);
    cudaGetSymbolAddress((void**)&pq,    g_q);
    cudaGetSymbolAddress((void**)&pk,    g_k);
    cudaGetSymbolAddress((void**)&pv,    g_v);
    cudaGetSymbolAddress((void**)&pctxb, g_ctxb);
    cudaGetSymbolAddress((void**)&phb,   g_hb);
    cudaGetSymbolAddress((void**)&pwqT,  g_wqT);
    cudaGetSymbolAddress((void**)&pwkT,  g_wkT);
    cudaGetSymbolAddress((void**)&pwvT,  g_wvT);
    cudaGetSymbolAddress((void**)&pwoT,  g_woT);
    cudaGetSymbolAddress((void**)&pw1T,  g_w1T);
    cudaGetSymbolAddress((void**)&pw2T,  g_w2T);
    cudaGetSymbolAddress((void**)&pbqs,  g_bqs);

    cudaFuncSetAttribute(attn_kernel, cudaFuncAttributeMaxDynamicSharedMemorySize,
                         (int)ATTN_SMEM);

    // 0. weight conversion (transpose + bf16; fold 0.125 into wq/bq)
    convT_kernel<<<(D*D)/256, 256>>>(wq, pwqT, D, D, 0.125f);
    convT_kernel<<<(D*D)/256, 256>>>(wk, pwkT, D, D, 1.0f);
    convT_kernel<<<(D*D)/256, 256>>>(wv, pwvT, D, D, 1.0f);
    convT_kernel<<<(D*D)/256, 256>>>(wo, pwoT, D, D, 1.0f);
    convT_kernel<<<(D*DFF)/256, 256>>>(w1, pw1T, D, DFF, 1.0f);   // w1[256][2048] -> [2048][256]
    convT_kernel<<<(D*DFF)/256, 256>>>(w2, pw2T, DFF, D, 1.0f);   // w2[2048][256] -> [256][2048]
    scaleb_kernel<<<1, D>>>(bq);

    // 1. PE + fused embedding+LN1 (writes g_x fp32 and g_xb bf16)
    pe_kernel<<<PREFIX, D>>>();
    embed_ln_kernel<<<TOKENS, D>>>(src, emb, n1a, n1b);

    // 2. QKV projections
    dim3 g256(D / 128, TOKENS / 128);
    bgemm_kernel<0><<<g256, 256>>>(pxb, pwqT, pbqs, nullptr, pq, TOKENS, D, D);
    bgemm_kernel<0><<<g256, 256>>>(pxb, pwkT, bk,   nullptr, pk, TOKENS, D, D);
    bgemm_kernel<0><<<g256, 256>>>(pxb, pwvT, bv,   nullptr, pv, TOKENS, D, D);

    // 3. attention -> g_ctxb (bf16)
    attn_kernel<<<HEADS, 512, ATTN_SMEM>>>(src);

    // 4. output projection + residual (x += ctx@wo + bo)
    bgemm_kernel<1><<<g256, 256>>>(pctxb, pwoT, bo, px, px, TOKENS, D, D);

    // 5. layernorm 2 (g_x -> g_xb)
    ln_kernel<<<TOKENS, D>>>(n2a, n2b);

    // 6. FFN (hidden in bf16)
    dim3 gff1(DFF / 128, TOKENS / 128);
    bgemm_kernel<2><<<gff1, 256>>>(pxb, pw1T, b1, nullptr, phb, TOKENS, DFF, D);
    bgemm_kernel<3><<<g256, 256>>>(phb, pw2T, b2, px, px, TOKENS, D, DFF);

    // 7. classifier + masks
    cls_kernel<<<BATCH * NPAIR, D>>>(src, wl, bl, out);
}

// round 9
// speedup vs baseline: 2.3164x; 1.0001x over previous
#include <cuda_runtime.h>
#include <cuda_bf16.h>
#include <math.h>

// ---------------- problem constants ----------------
#define BATCH   256
#define SEQ     360
#define PREFIX  340
#define D       256
#define H       4
#define DK      64
#define DFF     2048
#define NPAIR   91
#define PADTOK  799
#define TOKENS  (BATCH*SEQ)          // 92160
#define HEADS   (BATCH*H)            // 1024
#define HSTRIDE (SEQ*DK)             // 23040

typedef __nv_bfloat16 bf16;
typedef __nv_bfloat162 bf162;

// ---------------- scratch (device globals) ----------------
__device__ float g_x  [TOKENS*D];       // residual stream (fp32)
__device__ bf16  g_xb [TOKENS*D];       // layernorm output (bf16)
__device__ float g_q  [TOKENS*D];       // (B,H,S,DK) fp32
__device__ float g_k  [TOKENS*D];
__device__ float g_v  [TOKENS*D];
__device__ bf16  g_ctxb[TOKENS*D];      // attention output (bf16)
__device__ bf16  g_hb [TOKENS*DFF];     // ffn hidden (bf16)
__device__ float g_pe [PREFIX*D];       // positional encodings
// transposed bf16 weights [N][K]
__device__ bf16  g_wqT[D*D];
__device__ bf16  g_wkT[D*D];
__device__ bf16  g_wvT[D*D];
__device__ bf16  g_woT[D*D];
__device__ bf16  g_w1T[D*DFF];
__device__ bf16  g_w2T[D*DFF];
__device__ float g_bqs[D];              // bq * 0.125

// ---------------- helpers ----------------
__device__ __forceinline__ float warp_sum(float v) {
    #pragma unroll
    for (int o = 16; o; o >>= 1) v += __shfl_xor_sync(0xffffffffu, v, o);
    return v;
}

// ---------------- PE table (double precision, matches numpy) --------------
__global__ void pe_kernel() {
    int s = blockIdx.x, d = threadIdx.x;
    double e   = pow(10000.0, ((double)(2 * d)) / 256.0);
    double arg = (double)s / e;
    g_pe[s * D + d] = (float)((d & 1) ? cos(arg) : sin(arg));
}

// ---------------- weight transpose + bf16 convert --------------------------
// w is [K][N] row-major fp32; wT is [N][K] bf16.
__global__ void convT_kernel(const float* __restrict__ w, bf16* __restrict__ wT,
                             int K, int N, float scale) {
    int idx = blockIdx.x * 256 + threadIdx.x;
    int k = idx / N, n = idx - k * N;
    wT[(size_t)n * K + k] = __float2bfloat16(w[idx] * scale);
}
__global__ void scaleb_kernel(const float* __restrict__ b) {
    g_bqs[threadIdx.x] = b[threadIdx.x] * 0.125f;
}

// ---------------- fused embedding + scale + PE + layernorm1 ---------------
__global__ void embed_ln_kernel(const int* __restrict__ src,
                                const float* __restrict__ emb,
                                const float* __restrict__ ga,
                                const float* __restrict__ gb) {
    __shared__ float red[8];
    __shared__ float stat;
    int t = blockIdx.x, d = threadIdx.x;
    int s = t % SEQ;
    int tok = src[t];
    float v = emb[(size_t)tok * D + d];
    if (s < PREFIX) v = fmaf(v, 16.0f, g_pe[s * D + d]);
    size_t off = (size_t)t * D + d;
    g_x[off] = v;

    float sum = warp_sum(v);
    if ((d & 31) == 0) red[d >> 5] = sum;
    __syncthreads();
    if (d == 0) {
        float tt = 0.f;
        #pragma unroll
        for (int q = 0; q < 8; q++) tt += red[q];
        stat = tt * (1.0f / 256.0f);
    }
    __syncthreads();
    float diff = v - stat;

    float ss = warp_sum(diff * diff);
    if ((d & 31) == 0) red[d >> 5] = ss;
    __syncthreads();
    if (d == 0) {
        float tt = 0.f;
        #pragma unroll
        for (int q = 0; q < 8; q++) tt += red[q];
        stat = 1.0f / (sqrtf(tt * (1.0f / 255.0f)) + 1e-6f);
    }
    __syncthreads();
    g_xb[off] = __float2bfloat16(fmaf(ga[d], diff * stat, gb[d]));
}

// ---------------- layernorm 2 (g_x -> g_xb, ddof=1, eps on sd) ------------
__global__ void ln_kernel(const float* __restrict__ ga,
                          const float* __restrict__ gb) {
    __shared__ float red[8];
    __shared__ float stat;
    int t = blockIdx.x, d = threadIdx.x;
    size_t off = (size_t)t * D + d;
    float v = g_x[off];

    float s = warp_sum(v);
    if ((d & 31) == 0) red[d >> 5] = s;
    __syncthreads();
    if (d == 0) {
        float tt = 0.f;
        #pragma unroll
        for (int q = 0; q < 8; q++) tt += red[q];
        stat = tt * (1.0f / 256.0f);
    }
    __syncthreads();
    float diff = v - stat;

    float ss = warp_sum(diff * diff);
    if ((d & 31) == 0) red[d >> 5] = ss;
    __syncthreads();
    if (d == 0) {
        float tt = 0.f;
        #pragma unroll
        for (int q = 0; q < 8; q++) tt += red[q];
        stat = 1.0f / (sqrtf(tt * (1.0f / 255.0f)) + 1e-6f);
    }
    __syncthreads();
    g_xb[off] = __float2bfloat16(fmaf(ga[d], diff * stat, gb[d]));
}

// ---------------- bf16 tensor-core GEMM ----------------
// C(M,N) = A(M,K) @ Wt(N,K)^T (+bias, epilogues)
// A: bf16 [M][K] row-major.  Wt: bf16 [N][K] row-major (pre-transposed).
// EPI 0: QKV  -> fp32 C in (B,H,S,DK) layout, +bias
// EPI 1: WO   -> fp32 C = res + acc + bias
// EPI 2: FFN1 -> bf16 C = relu(acc + bias)
// EPI 3: FFN2 -> fp32 C = res + acc + bias
// Block 128x128x32, 256 threads, 8 warps (2x4), warp tile 64x32, double-buffered.
#define STR32 20   // uint32 (bf16x2) stride per row; g*20+t distinct mod 32

template<int EPI>
__global__ __launch_bounds__(256)
void bgemm_kernel(const bf16* __restrict__ A, const bf16* __restrict__ Wt,
                  const float* __restrict__ bias, const float* __restrict__ res,
                  void* __restrict__ Cv, int M, int N, int K) {
    __shared__ unsigned As[2][128 * STR32];
    __shared__ unsigned Bs[2][128 * STR32];

    const int tid  = threadIdx.x;
    const int lane = tid & 31;
    const int wid  = tid >> 5;
    const int wm = wid >> 2;            // 0..1  (64 rows)
    const int wn = wid & 3;             // 0..3  (32 cols)
    const int g = lane >> 2;            // 0..7
    const int t = lane & 3;             // 0..3

    const int bm = blockIdx.y * 128;
    const int bn = blockIdx.x * 128;

    const int lrow = tid >> 1;          // 0..127
    const int lch  = tid & 1;           // 16-bf16 chunk
    const bf16* Ap = A  + (size_t)(bm + lrow) * K + lch * 16;
    const bf16* Bp = Wt + (size_t)(bn + lrow) * K + lch * 16;

    float acc[4][4][4];
    #pragma unroll
    for (int mi = 0; mi < 4; mi++)
        #pragma unroll
        for (int ni = 0; ni < 4; ni++)
            #pragma unroll
            for (int r = 0; r < 4; r++) acc[mi][ni][r] = 0.f;

    uint4 ap0 = *(const uint4*)(Ap);
    uint4 ap1 = *(const uint4*)(Ap + 8);
    uint4 bp0 = *(const uint4*)(Bp);
    uint4 bp1 = *(const uint4*)(Bp + 8);
    {
        unsigned* as = &As[0][lrow * STR32 + lch * 8];
        *(uint4*)as = ap0; *(uint4*)(as + 4) = ap1;
        unsigned* bs = &Bs[0][lrow * STR32 + lch * 8];
        *(uint4*)bs = bp0; *(uint4*)(bs + 4) = bp1;
    }
    __syncthreads();

    const int ntiles = K >> 5;
    for (int tl = 0; tl < ntiles; tl++) {
        const int cur = tl & 1, nxt = cur ^ 1;
        if (tl + 1 < ntiles) {
            const bf16* ap = Ap + (tl + 1) * 32;
            const bf16* bp = Bp + (tl + 1) * 32;
            ap0 = *(const uint4*)(ap);
            ap1 = *(const uint4*)(ap + 8);
            bp0 = *(const uint4*)(bp);
            bp1 = *(const uint4*)(bp + 8);
        }
        #pragma unroll
        for (int kk = 0; kk < 2; kk++) {          // two k16 halves
            unsigned af[4][4], bf[4][2];
            #pragma unroll
            for (int mi = 0; mi < 4; mi++) {
                const unsigned* base = &As[cur][(wm * 64 + mi * 16 + g) * STR32 + kk * 8 + t];
                af[mi][0] = base[0];
                af[mi][1] = base[8 * STR32];
                af[mi][2] = base[4];
                af[mi][3] = base[8 * STR32 + 4];
            }
            #pragma unroll
            for (int ni = 0; ni < 4; ni++) {
                const unsigned* base = &Bs[cur][(wn * 32 + ni * 8 + g) * STR32 + kk * 8 + t];
                bf[ni][0] = base[0];
                bf[ni][1] = base[4];
            }
            #pragma unroll
            for (int mi = 0; mi < 4; mi++)
                #pragma unroll
                for (int ni = 0; ni < 4; ni++) {
                    asm volatile(
                        "mma.sync.aligned.m16n8k16.row.col.f32.bf16.bf16.f32 "
                        "{%0,%1,%2,%3}, {%4,%5,%6,%7}, {%8,%9}, {%0,%1,%2,%3};"
                        : "+f"(acc[mi][ni][0]), "+f"(acc[mi][ni][1]),
                          "+f"(acc[mi][ni][2]), "+f"(acc[mi][ni][3])
                        : "r"(af[mi][0]), "r"(af[mi][1]), "r"(af[mi][2]), "r"(af[mi][3]),
                          "r"(bf[ni][0]), "r"(bf[ni][1]));
                }
        }
        if (tl + 1 < ntiles) {
            unsigned* as = &As[nxt][lrow * STR32 + lch * 8];
            *(uint4*)as = ap0; *(uint4*)(as + 4) = ap1;
            unsigned* bs = &Bs[nxt][lrow * STR32 + lch * 8];
            *(uint4*)bs = bp0; *(uint4*)(bs + 4) = bp1;
        }
        __syncthreads();
    }

    // ------------- epilogue -------------
    float* C  = (float*)Cv;
    bf16*  Cb = (bf16*)Cv;
    #pragma unroll
    for (int mi = 0; mi < 4; mi++) {
        int row0 = bm + wm * 64 + mi * 16 + g;
        #pragma unroll
        for (int ni = 0; ni < 4; ni++) {
            int col = bn + wn * 32 + ni * 8 + t * 2;
            float2 bb = *(const float2*)(bias + col);
            #pragma unroll
            for (int half = 0; half < 2; half++) {
                int row = row0 + half * 8;
                float v0 = acc[mi][ni][half * 2 + 0] + bb.x;
                float v1 = acc[mi][ni][half * 2 + 1] + bb.y;
                if (EPI == 0) {
                    int bbt = row / SEQ;
                    int s   = row - bbt * SEQ;
                    float* cb = C + (size_t)bbt * (H * HSTRIDE) + (col >> 6) * HSTRIDE
                                  + s * DK + (col & 63);
                    *(float2*)cb = make_float2(v0, v1);
                } else if (EPI == 2) {
                    *(bf162*)(Cb + (size_t)row * N + col) =
                        __floats2bfloat162_rn(fmaxf(v0, 0.f), fmaxf(v1, 0.f));
                } else {
                    size_t ro = (size_t)row * N + col;
                    float2 rv = *(const float2*)(res + ro);
                    *(float2*)(C + ro) = make_float2(rv.x + v0, rv.y + v1);
                }
            }
        }
    }
}

// ---------------- attention: one block per (b,h), warp per query ----------
#define SKS 68   // padded K row stride (conflict-free float4 reads)
#define ATTN_SMEM ((SEQ*SKS + SEQ*DK + 16*DK + 16*SEQ) * sizeof(float))

__global__ __launch_bounds__(512)
void attn_kernel(const int* __restrict__ src) {
    extern __shared__ float sm[];
    float* sK = sm;                       // SEQ*SKS
    float* sV = sm + SEQ * SKS;           // SEQ*DK
    float* sQ = sV + SEQ * DK;            // 16*DK
    float* sP = sQ + 16 * DK;             // 16*SEQ

    int bh = blockIdx.x;
    int b  = bh >> 2;
    size_t hb = (size_t)bh * HSTRIDE;
    int tid = threadIdx.x;

    for (int i = tid; i < SEQ * DK; i += 512) {
        int j = i >> 6, dk = i & 63;
        sK[j * SKS + dk] = g_k[hb + i];
        sV[i]            = g_v[hb + i];
    }
    __syncthreads();

    int w = tid >> 5, lane = tid & 31;
    int l16 = lane & 15, jj = lane >> 4;
    float* qrow = sQ + w * DK;
    float* prow = sP + w * SEQ;
    const float4* q4 = (const float4*)qrow;
    const float4* v4 = (const float4*)sV;

    for (int s = w; s < SEQ; s += 16) {
        qrow[lane]      = g_q[hb + s * DK + lane];       // scale folded into wq/bq
        qrow[lane + 32] = g_q[hb + s * DK + lane + 32];
        __syncwarp();
        bool validq = (src[b * SEQ + s] != PADTOK);

        float sc[12];
        #pragma unroll
        for (int tt = 0; tt < 12; tt++) {
            int j = tt * 32 + lane;
            if (j < SEQ) {
                const float4* k4 = (const float4*)(sK + (size_t)j * SKS);
                float a = 0.f;
                #pragma unroll
                for (int d4 = 0; d4 < 16; d4++) {
                    float4 qq = q4[d4], kk = k4[d4];
                    a = fmaf(qq.x, kk.x, a);
                    a = fmaf(qq.y, kk.y, a);
                    a = fmaf(qq.z, kk.z, a);
                    a = fmaf(qq.w, kk.w, a);
                }
                sc[tt] = validq ? a : 0.f;   // pad query -> uniform softmax
            } else sc[tt] = -1e30f;
        }

        float m = sc[0];
        #pragma unroll
        for (int tt = 1; tt < 12; tt++) m = fmaxf(m, sc[tt]);
        #pragma unroll
        for (int o = 16; o; o >>= 1) m = fmaxf(m, __shfl_xor_sync(0xffffffffu, m, o));

        float ssum = 0.f;
        #pragma unroll
        for (int tt = 0; tt < 12; tt++) { float e = expf(sc[tt] - m); sc[tt] = e; ssum += e; }
        #pragma unroll
        for (int o = 16; o; o >>= 1) ssum += __shfl_xor_sync(0xffffffffu, ssum, o);
        float inv = 1.f / ssum;

        #pragma unroll
        for (int tt = 0; tt < 12; tt++) {
            int j = tt * 32 + lane;
            if (j < SEQ) prow[j] = sc[tt] * inv;
        }
        __syncwarp();

        // PV: half-warps each take one of 2 keys per iter, lane owns 4 dims
        float cx = 0.f, cy = 0.f, cz = 0.f, cw = 0.f;
        const float2* p2v = (const float2*)prow;
        #pragma unroll 4
        for (int j0 = 0; j0 < SEQ; j0 += 2) {
            float2 pp = p2v[j0 >> 1];
            float p = jj ? pp.y : pp.x;
            float4 vv = v4[(j0 + jj) * 16 + l16];
            cx = fmaf(p, vv.x, cx);
            cy = fmaf(p, vv.y, cy);
            cz = fmaf(p, vv.z, cz);
            cw = fmaf(p, vv.w, cw);
        }
        cx += __shfl_xor_sync(0xffffffffu, cx, 16);
        cy += __shfl_xor_sync(0xffffffffu, cy, 16);
        cz += __shfl_xor_sync(0xffffffffu, cz, 16);
        cw += __shfl_xor_sync(0xffffffffu, cw, 16);
        if (jj == 0) {
            size_t ob = ((size_t)(b * SEQ + s)) * D + (bh & 3) * DK + l16 * 4;
            bf162 p0 = __floats2bfloat162_rn(cx, cy);
            bf162 p1 = __floats2bfloat162_rn(cz, cw);
            *(bf162*)(g_ctxb + ob)     = p0;
            *(bf162*)(g_ctxb + ob + 2) = p1;
        }
        __syncwarp();
    }
}

// ---------------- classifier + output masks ----------------
__global__ void cls_kernel(const int* __restrict__ src,
                           const float* __restrict__ wl,
                           const float* __restrict__ bl,
                           float* __restrict__ out) {
    int bp = blockIdx.x;
    int b = bp / NPAIR, p = bp - b * NPAIR;

    int i = 0, rem = p;
    while (rem >= 13 - i) { rem -= 13 - i; i++; }
    int j = i + 1 + rem;
    int base = i * 12 - (i * (i - 1)) / 2;
    int pe = base + (j - i) - 1;
    int eb = 28 + 2 * pe;
    int gidx[8] = {2*i, 2*i+1, 2*j, 2*j+1, eb, eb+1, eb+2, eb+3};

    int tid = threadIdx.x;
    const float* xb = g_x + (size_t)(b * SEQ) * D;
    int slots = (j < 13) ? 8 : 4;

    float a0 = 0.f, a1 = 0.f, a2 = 0.f;
    for (int sl = 0; sl < slots; sl++) {
        float xv = xb[gidx[sl] * D + tid];
        const float* wr = wl + ((size_t)(sl * D + tid)) * 3;
        a0 = fmaf(xv, wr[0], a0);
        a1 = fmaf(xv, wr[1], a1);
        a2 = fmaf(xv, wr[2], a2);
    }
    a0 = warp_sum(a0); a1 = warp_sum(a1); a2 = warp_sum(a2);

    __shared__ float red[8][3];
    int lane = tid & 31, w = tid >> 5;
    if (lane == 0) { red[w][0] = a0; red[w][1] = a1; red[w][2] = a2; }
    __syncthreads();

    if (tid == 0) {
        float s0 = bl[0], s1 = bl[1], s2 = bl[2];
        #pragma unroll
        for (int t = 0; t < 8; t++) { s0 += red[t][0]; s1 += red[t][1]; s2 += red[t][2]; }

        const int* sb = src + b * SEQ;
        int ti = sb[2*i], ai = sb[2*i+1], tj = sb[2*j], aj = sb[2*j+1];
        bool c1 = (ai == 2) || (aj == 2);
        bool c2 = (tj == 1) || (ai == 1) || (aj == 1);
        bool c3 = (ti == PADTOK) || (tj == PADTOK) || (ai == 0) || (aj == 0);
        bool c4 = false;
        if (j < 13) {
            int es = 28 + 4 * pe;              // EIDX base: 4*pe (not 2*pe)
            c4 = (sb[es] == 1) || (sb[es+1] == 1) || (sb[es+2] == 1) || (sb[es+3] == 1);
        }
        bool m111 = c3 || c4;
        bool mk1 = m111 || c2;
        bool mk2 = mk1 || c1;
        float* o = out + (size_t)bp * 3;
        o[0] = m111 ? -1e9f : s0;
        o[1] = mk1  ? -1e9f : s1;
        o[2] = mk2  ? -1e9f : s2;
    }
}

// ---------------- launch ----------------
extern "C" void kernel_launch(void* const* d_in, const int* in_sizes, int n_in,
                              void* d_out, int out_size) {
    (void)in_sizes; (void)n_in; (void)out_size;
    const int*   src = (const int*)  d_in[0];
    const float* emb = (const float*)d_in[1];
    const float* wq  = (const float*)d_in[2];
    const float* bq  = (const float*)d_in[3];
    const float* wk  = (const float*)d_in[4];
    const float* bk  = (const float*)d_in[5];
    const float* wv  = (const float*)d_in[6];
    const float* bv  = (const float*)d_in[7];
    const float* wo  = (const float*)d_in[8];
    const float* bo  = (const float*)d_in[9];
    const float* n1a = (const float*)d_in[10];
    const float* n1b = (const float*)d_in[11];
    const float* n2a = (const float*)d_in[12];
    const float* n2b = (const float*)d_in[13];
    const float* w1  = (const float*)d_in[14];
    const float* b1  = (const float*)d_in[15];
    const float* w2  = (const float*)d_in[16];
    const float* b2  = (const float*)d_in[17];
    const float* wl  = (const float*)d_in[18];
    const float* bl  = (const float*)d_in[19];
    float* out = (float*)d_out;

    float *px, *pq, *pk, *pv, *pbqs;
    bf16 *pxb, *pctxb, *phb, *pwqT, *pwkT, *pwvT, *pwoT, *pw1T, *pw2T;
    cudaGetSymbolAddress((void**)&px,    g_x);
    cudaGetSymbolAddress((void**)&pxb,   g_xb);
    cudaGetSymbolAddress((void**)&pq,    g_q);
    cudaGetSymbolAddress((void**)&pk,    g_k);
    cudaGetSymbolAddress((void**)&pv,    g_v);
    cudaGetSymbolAddress((void**)&pctxb, g_ctxb);
    cudaGetSymbolAddress((void**)&phb,   g_hb);
    cudaGetSymbolAddress((void**)&pwqT,  g_wqT);
    cudaGetSymbolAddress((void**)&pwkT,  g_wkT);
    cudaGetSymbolAddress((void**)&pwvT,  g_wvT);
    cudaGetSymbolAddress((void**)&pwoT,  g_woT);
    cudaGetSymbolAddress((void**)&pw1T,  g_w1T);
    cudaGetSymbolAddress((void**)&pw2T,  g_w2T);
    cudaGetSymbolAddress((void**)&pbqs,  g_bqs);

    cudaFuncSetAttribute(attn_kernel, cudaFuncAttributeMaxDynamicSharedMemorySize,
                         (int)ATTN_SMEM);

    // 0. weight conversion (transpose + bf16; fold 0.125 into wq/bq)
    convT_kernel<<<(D*D)/256, 256>>>(wq, pwqT, D, D, 0.125f);
    convT_kernel<<<(D*D)/256, 256>>>(wk, pwkT, D, D, 1.0f);
    convT_kernel<<<(D*D)/256, 256>>>(wv, pwvT, D, D, 1.0f);
    convT_kernel<<<(D*D)/256, 256>>>(wo, pwoT, D, D, 1.0f);
    convT_kernel<<<(D*DFF)/256, 256>>>(w1, pw1T, D, DFF, 1.0f);   // w1[256][2048] -> [2048][256]
    convT_kernel<<<(D*DFF)/256, 256>>>(w2, pw2T, DFF, D, 1.0f);   // w2[2048][256] -> [256][2048]
    scaleb_kernel<<<1, D>>>(bq);

    // 1. PE + fused embedding+LN1 (writes g_x fp32 and g_xb bf16)
    pe_kernel<<<PREFIX, D>>>();
    embed_ln_kernel<<<TOKENS, D>>>(src, emb, n1a, n1b);

    // 2. QKV projections
    dim3 g256(D / 128, TOKENS / 128);
    bgemm_kernel<0><<<g256, 256>>>(pxb, pwqT, pbqs, nullptr, pq, TOKENS, D, D);
    bgemm_kernel<0><<<g256, 256>>>(pxb, pwkT, bk,   nullptr, pk, TOKENS, D, D);
    bgemm_kernel<0><<<g256, 256>>>(pxb, pwvT, bv,   nullptr, pv, TOKENS, D, D);

    // 3. attention -> g_ctxb (bf16)
    attn_kernel<<<HEADS, 512, ATTN_SMEM>>>(src);

    // 4. output projection + residual (x += ctx@wo + bo)
    bgemm_kernel<1><<<g256, 256>>>(pctxb, pwoT, bo, px, px, TOKENS, D, D);

    // 5. layernorm 2 (g_x -> g_xb)
    ln_kernel<<<TOKENS, D>>>(n2a, n2b);

    // 6. FFN (hidden in bf16)
    dim3 gff1(DFF / 128, TOKENS / 128);
    bgemm_kernel<2><<<gff1, 256>>>(pxb, pw1T, b1, nullptr, phb, TOKENS, DFF, D);
    bgemm_kernel<3><<<g256, 256>>>(phb, pw2T, b2, px, px, TOKENS, D, DFF);

    // 7. classifier + masks
    cls_kernel<<<BATCH * NPAIR, D>>>(src, wl, bl, out);
}

// round 10
// speedup vs baseline: 3.7076x; 1.6006x over previous
#include <cuda_runtime.h>
#include <cuda_bf16.h>
#include <math.h>

// ---------------- problem constants ----------------
#define BATCH   256
#define SEQ     360
#define PREFIX  340
#define D       256
#define H       4
#define DK      64
#define DFF     2048
#define NPAIR   91
#define PADTOK  799
#define TOKENS  (BATCH*SEQ)          // 92160
#define HEADS   (BATCH*H)            // 1024
#define HSTRIDE (SEQ*DK)             // 23040

typedef __nv_bfloat16 bf16;
typedef __nv_bfloat162 bf162;

// ---------------- scratch (device globals) ----------------
__device__ float g_x  [TOKENS*D];       // residual stream (fp32)
__device__ bf16  g_xb [TOKENS*D];       // layernorm output (bf16)
__device__ bf16  g_qb [TOKENS*D];       // (B,H,S,DK) bf16
__device__ bf16  g_kb [TOKENS*D];
__device__ bf16  g_vb [TOKENS*D];
__device__ bf16  g_ctxb[TOKENS*D];      // attention output (bf16)
__device__ bf16  g_hb [TOKENS*DFF];     // ffn hidden (bf16)
__device__ float g_pe [PREFIX*D];       // positional encodings
// transposed bf16 weights [N][K]
__device__ bf16  g_wqT[D*D];
__device__ bf16  g_wkT[D*D];
__device__ bf16  g_wvT[D*D];
__device__ bf16  g_woT[D*D];
__device__ bf16  g_w1T[D*DFF];
__device__ bf16  g_w2T[D*DFF];
__device__ float g_bqs[D];              // bq * 0.125

// ---------------- helpers ----------------
__device__ __forceinline__ float warp_sum(float v) {
    #pragma unroll
    for (int o = 16; o; o >>= 1) v += __shfl_xor_sync(0xffffffffu, v, o);
    return v;
}

#define BMMA(c, a0, a1, a2, a3, b0, b1)                                        \
    asm volatile(                                                              \
        "mma.sync.aligned.m16n8k16.row.col.f32.bf16.bf16.f32 "                 \
        "{%0,%1,%2,%3}, {%4,%5,%6,%7}, {%8,%9}, {%0,%1,%2,%3};"                \
        : "+f"(c[0]), "+f"(c[1]), "+f"(c[2]), "+f"(c[3])                       \
        : "r"(a0), "r"(a1), "r"(a2), "r"(a3), "r"(b0), "r"(b1))

// ---------------- PE table (double precision, matches numpy) --------------
__global__ void pe_kernel() {
    int s = blockIdx.x, d = threadIdx.x;
    double e   = pow(10000.0, ((double)(2 * d)) / 256.0);
    double arg = (double)s / e;
    g_pe[s * D + d] = (float)((d & 1) ? cos(arg) : sin(arg));
}

// ---------------- weight transpose + bf16 convert --------------------------
__global__ void convT_kernel(const float* __restrict__ w, bf16* __restrict__ wT,
                             int K, int N, float scale) {
    int idx = blockIdx.x * 256 + threadIdx.x;
    int k = idx / N, n = idx - k * N;
    wT[(size_t)n * K + k] = __float2bfloat16(w[idx] * scale);
}
__global__ void scaleb_kernel(const float* __restrict__ b) {
    g_bqs[threadIdx.x] = b[threadIdx.x] * 0.125f;
}

// ---------------- fused embedding + scale + PE + layernorm1 ---------------
__global__ void embed_ln_kernel(const int* __restrict__ src,
                                const float* __restrict__ emb,
                                const float* __restrict__ ga,
                                const float* __restrict__ gb) {
    __shared__ float red[8];
    __shared__ float stat;
    int t = blockIdx.x, d = threadIdx.x;
    int s = t % SEQ;
    int tok = src[t];
    float v = emb[(size_t)tok * D + d];
    if (s < PREFIX) v = fmaf(v, 16.0f, g_pe[s * D + d]);
    size_t off = (size_t)t * D + d;
    g_x[off] = v;

    float sum = warp_sum(v);
    if ((d & 31) == 0) red[d >> 5] = sum;
    __syncthreads();
    if (d == 0) {
        float tt = 0.f;
        #pragma unroll
        for (int q = 0; q < 8; q++) tt += red[q];
        stat = tt * (1.0f / 256.0f);
    }
    __syncthreads();
    float diff = v - stat;

    float ss = warp_sum(diff * diff);
    if ((d & 31) == 0) red[d >> 5] = ss;
    __syncthreads();
    if (d == 0) {
        float tt = 0.f;
        #pragma unroll
        for (int q = 0; q < 8; q++) tt += red[q];
        stat = 1.0f / (sqrtf(tt * (1.0f / 255.0f)) + 1e-6f);
    }
    __syncthreads();
    g_xb[off] = __float2bfloat16(fmaf(ga[d], diff * stat, gb[d]));
}

// ---------------- layernorm 2 (g_x -> g_xb, ddof=1, eps on sd) ------------
__global__ void ln_kernel(const float* __restrict__ ga,
                          const float* __restrict__ gb) {
    __shared__ float red[8];
    __shared__ float stat;
    int t = blockIdx.x, d = threadIdx.x;
    size_t off = (size_t)t * D + d;
    float v = g_x[off];

    float s = warp_sum(v);
    if ((d & 31) == 0) red[d >> 5] = s;
    __syncthreads();
    if (d == 0) {
        float tt = 0.f;
        #pragma unroll
        for (int q = 0; q < 8; q++) tt += red[q];
        stat = tt * (1.0f / 256.0f);
    }
    __syncthreads();
    float diff = v - stat;

    float ss = warp_sum(diff * diff);
    if ((d & 31) == 0) red[d >> 5] = ss;
    __syncthreads();
    if (d == 0) {
        float tt = 0.f;
        #pragma unroll
        for (int q = 0; q < 8; q++) tt += red[q];
        stat = 1.0f / (sqrtf(tt * (1.0f / 255.0f)) + 1e-6f);
    }
    __syncthreads();
    g_xb[off] = __float2bfloat16(fmaf(ga[d], diff * stat, gb[d]));
}

// ---------------- bf16 tensor-core GEMM ----------------
// EPI 0: QKV  -> bf16 C in (B,H,S,DK) layout, +bias
// EPI 1: WO   -> fp32 C = res + acc + bias
// EPI 2: FFN1 -> bf16 C = relu(acc + bias)
// EPI 3: FFN2 -> fp32 C = res + acc + bias
#define STR32 20

template<int EPI>
__global__ __launch_bounds__(256)
void bgemm_kernel(const bf16* __restrict__ A, const bf16* __restrict__ Wt,
                  const float* __restrict__ bias, const float* __restrict__ res,
                  void* __restrict__ Cv, int M, int N, int K) {
    __shared__ unsigned As[2][128 * STR32];
    __shared__ unsigned Bs[2][128 * STR32];

    const int tid  = threadIdx.x;
    const int lane = tid & 31;
    const int wid  = tid >> 5;
    const int wm = wid >> 2;
    const int wn = wid & 3;
    const int g = lane >> 2;
    const int t = lane & 3;

    const int bm = blockIdx.y * 128;
    const int bn = blockIdx.x * 128;

    const int lrow = tid >> 1;
    const int lch  = tid & 1;
    const bf16* Ap = A  + (size_t)(bm + lrow) * K + lch * 16;
    const bf16* Bp = Wt + (size_t)(bn + lrow) * K + lch * 16;

    float acc[4][4][4];
    #pragma unroll
    for (int mi = 0; mi < 4; mi++)
        #pragma unroll
        for (int ni = 0; ni < 4; ni++)
            #pragma unroll
            for (int r = 0; r < 4; r++) acc[mi][ni][r] = 0.f;

    uint4 ap0 = *(const uint4*)(Ap);
    uint4 ap1 = *(const uint4*)(Ap + 8);
    uint4 bp0 = *(const uint4*)(Bp);
    uint4 bp1 = *(const uint4*)(Bp + 8);
    {
        unsigned* as = &As[0][lrow * STR32 + lch * 8];
        *(uint4*)as = ap0; *(uint4*)(as + 4) = ap1;
        unsigned* bs = &Bs[0][lrow * STR32 + lch * 8];
        *(uint4*)bs = bp0; *(uint4*)(bs + 4) = bp1;
    }
    __syncthreads();

    const int ntiles = K >> 5;
    for (int tl = 0; tl < ntiles; tl++) {
        const int cur = tl & 1, nxt = cur ^ 1;
        if (tl + 1 < ntiles) {
            const bf16* ap = Ap + (tl + 1) * 32;
            const bf16* bp = Bp + (tl + 1) * 32;
            ap0 = *(const uint4*)(ap);
            ap1 = *(const uint4*)(ap + 8);
            bp0 = *(const uint4*)(bp);
            bp1 = *(const uint4*)(bp + 8);
        }
        #pragma unroll
        for (int kk = 0; kk < 2; kk++) {
            unsigned af[4][4], bf[4][2];
            #pragma unroll
            for (int mi = 0; mi < 4; mi++) {
                const unsigned* base = &As[cur][(wm * 64 + mi * 16 + g) * STR32 + kk * 8 + t];
                af[mi][0] = base[0];
                af[mi][1] = base[8 * STR32];
                af[mi][2] = base[4];
                af[mi][3] = base[8 * STR32 + 4];
            }
            #pragma unroll
            for (int ni = 0; ni < 4; ni++) {
                const unsigned* base = &Bs[cur][(wn * 32 + ni * 8 + g) * STR32 + kk * 8 + t];
                bf[ni][0] = base[0];
                bf[ni][1] = base[4];
            }
            #pragma unroll
            for (int mi = 0; mi < 4; mi++)
                #pragma unroll
                for (int ni = 0; ni < 4; ni++)
                    BMMA(acc[mi][ni], af[mi][0], af[mi][1], af[mi][2], af[mi][3],
                         bf[ni][0], bf[ni][1]);
        }
        if (tl + 1 < ntiles) {
            unsigned* as = &As[nxt][lrow * STR32 + lch * 8];
            *(uint4*)as = ap0; *(uint4*)(as + 4) = ap1;
            unsigned* bs = &Bs[nxt][lrow * STR32 + lch * 8];
            *(uint4*)bs = bp0; *(uint4*)(bs + 4) = bp1;
        }
        __syncthreads();
    }

    float* C  = (float*)Cv;
    bf16*  Cb = (bf16*)Cv;
    #pragma unroll
    for (int mi = 0; mi < 4; mi++) {
        int row0 = bm + wm * 64 + mi * 16 + g;
        #pragma unroll
        for (int ni = 0; ni < 4; ni++) {
            int col = bn + wn * 32 + ni * 8 + t * 2;
            float2 bb = *(const float2*)(bias + col);
            #pragma unroll
            for (int half = 0; half < 2; half++) {
                int row = row0 + half * 8;
                float v0 = acc[mi][ni][half * 2 + 0] + bb.x;
                float v1 = acc[mi][ni][half * 2 + 1] + bb.y;
                if (EPI == 0) {
                    int bbt = row / SEQ;
                    int s   = row - bbt * SEQ;
                    bf16* cb = Cb + (size_t)bbt * (H * HSTRIDE) + (col >> 6) * HSTRIDE
                                  + s * DK + (col & 63);
                    *(bf162*)cb = __floats2bfloat162_rn(v0, v1);
                } else if (EPI == 2) {
                    *(bf162*)(Cb + (size_t)row * N + col) =
                        __floats2bfloat162_rn(fmaxf(v0, 0.f), fmaxf(v1, 0.f));
                } else {
                    size_t ro = (size_t)row * N + col;
                    float2 rv = *(const float2*)(res + ro);
                    *(float2*)(C + ro) = make_float2(rv.x + v0, rv.y + v1);
                }
            }
        }
    }
}

// ---------------- tensor-core attention ----------------
// Block = (qtile, head). 64-query tile, all 360 keys (padded to 368).
// 8 warps: S-phase 4 q-subs x 2 key-halves; PV-phase 4 q-subs x 2 dk-halves.
#define QSTR 36     // Q/K smem row stride (uint32)
#define PSTR 188    // P/VT smem row stride (uint32); 376 bf16
#define ATT_SMEM ((64*QSTR + 368*QSTR + 64*PSTR + 64*PSTR) * 4 + 256 * 4)

__global__ __launch_bounds__(256, 1)
void fattn_kernel(const int* __restrict__ src) {
    extern __shared__ unsigned sm32[];
    unsigned* q32  = sm32;                 // 64 x 36
    unsigned* k32  = q32  + 64 * QSTR;     // 368 x 36
    unsigned* vt32 = k32  + 368 * QSTR;    // 64 x 188 (VT: [dk][key])
    unsigned* p32  = vt32 + 64 * PSTR;     // 64 x 188 (P bf16)
    float* redm = (float*)(p32 + 64 * PSTR);   // 2 x 64
    float* reds = redm + 128;                  // 2 x 64

    const int qt = blockIdx.x;
    const int bh = blockIdx.y;
    const int b  = bh >> 2;
    const int qbase = qt * 64;
    const size_t hb = (size_t)bh * HSTRIDE;
    const int tid = threadIdx.x;

    // ---- load Q tile (zero OOB rows) ----
    const uint4* gq = (const uint4*)(g_qb + hb + (size_t)qbase * DK);
    #pragma unroll
    for (int u = tid; u < 512; u += 256) {
        int row = u >> 3, c8 = u & 7;
        uint4 val = make_uint4(0u, 0u, 0u, 0u);
        if (qbase + row < SEQ) val = gq[row * 8 + c8];
        *(uint4*)&q32[row * QSTR + c8 * 4] = val;
    }
    // ---- load K (360 rows) ----
    const uint4* gk = (const uint4*)(g_kb + hb);
    for (int u = tid; u < 2880; u += 256) {
        int row = u >> 3, c8 = u & 7;
        *(uint4*)&k32[row * QSTR + c8 * 4] = gk[u];
    }
    // ---- load V transposed: VT[dk][key] ----
    const bf16* gv = g_vb + hb;
    bf16* vt = (bf16*)vt32;
    for (int i = tid; i < SEQ * DK; i += 256) {
        int key = i >> 6, dk = i & 63;
        vt[dk * 376 + key] = gv[i];
    }
    for (int i = tid; i < 64 * 16; i += 256) {       // zero key pad 360..375
        int dk = i >> 4, key = 360 + (i & 15);
        vt[dk * 376 + key] = __float2bfloat16(0.f);
    }
    __syncthreads();

    const int lane = tid & 31, wid = tid >> 5;
    const int wq = wid >> 1;              // q-subtile 0..3
    const int wk = wid & 1;               // key-half / dk-half 0..1
    const int g = lane >> 2, t = lane & 3;
    const int kb = wk * 184;
    const int r_lo = wq * 16 + g, r_hi = r_lo + 8;

    // ---- S = Q K^T (per warp: 16 q x 184 keys) ----
    float acc[23][4];
    #pragma unroll
    for (int ni = 0; ni < 23; ni++)
        #pragma unroll
        for (int r = 0; r < 4; r++) acc[ni][r] = 0.f;

    #pragma unroll
    for (int kt = 0; kt < 4; kt++) {
        const unsigned* ab = &q32[r_lo * QSTR + kt * 8 + t];
        unsigned a0 = ab[0], a1 = ab[8 * QSTR], a2 = ab[4], a3 = ab[8 * QSTR + 4];
        #pragma unroll
        for (int ni = 0; ni < 23; ni++) {
            const unsigned* bb = &k32[(kb + ni * 8 + g) * QSTR + kt * 8 + t];
            unsigned b0 = bb[0], b1 = bb[4];
            BMMA(acc[ni], a0, a1, a2, a3, b0, b1);
        }
    }

    // ---- softmax (query-pad masking; key pad -> -inf) ----
    bool v_lo = true, v_hi = true;
    if (qbase + r_lo < SEQ) v_lo = (src[b * SEQ + qbase + r_lo] != PADTOK);
    if (qbase + r_hi < SEQ) v_hi = (src[b * SEQ + qbase + r_hi] != PADTOK);

    float m_lo = -1e30f, m_hi = -1e30f;
    #pragma unroll
    for (int ni = 0; ni < 23; ni++) {
        int col0 = kb + ni * 8 + t * 2;
        bool in0 = col0 < SEQ, in1 = col0 + 1 < SEQ;
        acc[ni][0] = in0 ? (v_lo ? acc[ni][0] : 0.f) : -1e30f;
        acc[ni][1] = in1 ? (v_lo ? acc[ni][1] : 0.f) : -1e30f;
        acc[ni][2] = in0 ? (v_hi ? acc[ni][2] : 0.f) : -1e30f;
        acc[ni][3] = in1 ? (v_hi ? acc[ni][3] : 0.f) : -1e30f;
        m_lo = fmaxf(m_lo, fmaxf(acc[ni][0], acc[ni][1]));
        m_hi = fmaxf(m_hi, fmaxf(acc[ni][2], acc[ni][3]));
    }
    m_lo = fmaxf(m_lo, __shfl_xor_sync(0xffffffffu, m_lo, 1));
    m_lo = fmaxf(m_lo, __shfl_xor_sync(0xffffffffu, m_lo, 2));
    m_hi = fmaxf(m_hi, __shfl_xor_sync(0xffffffffu, m_hi, 1));
    m_hi = fmaxf(m_hi, __shfl_xor_sync(0xffffffffu, m_hi, 2));
    if (t == 0) { redm[wk * 64 + r_lo] = m_lo; redm[wk * 64 + r_hi] = m_hi; }
    __syncthreads();
    m_lo = fmaxf(redm[r_lo], redm[64 + r_lo]);
    m_hi = fmaxf(redm[r_hi], redm[64 + r_hi]);

    float s_lo = 0.f, s_hi = 0.f;
    #pragma unroll
    for (int ni = 0; ni < 23; ni++) {
        acc[ni][0] = __expf(acc[ni][0] - m_lo);
        acc[ni][1] = __expf(acc[ni][1] - m_lo);
        acc[ni][2] = __expf(acc[ni][2] - m_hi);
        acc[ni][3] = __expf(acc[ni][3] - m_hi);
        s_lo += acc[ni][0] + acc[ni][1];
        s_hi += acc[ni][2] + acc[ni][3];
    }
    s_lo += __shfl_xor_sync(0xffffffffu, s_lo, 1);
    s_lo += __shfl_xor_sync(0xffffffffu, s_lo, 2);
    s_hi += __shfl_xor_sync(0xffffffffu, s_hi, 1);
    s_hi += __shfl_xor_sync(0xffffffffu, s_hi, 2);
    if (t == 0) { reds[wk * 64 + r_lo] = s_lo; reds[wk * 64 + r_hi] = s_hi; }
    __syncthreads();
    float inv_lo = 1.f / (reds[r_lo] + reds[64 + r_lo]);
    float inv_hi = 1.f / (reds[r_hi] + reds[64 + r_hi]);

    // ---- write P (bf16) ----
    #pragma unroll
    for (int ni = 0; ni < 23; ni++) {
        int cu = (kb >> 1) + ni * 4 + t;          // uint32 column index
        bf162 p0 = __floats2bfloat162_rn(acc[ni][0] * inv_lo, acc[ni][1] * inv_lo);
        bf162 p1 = __floats2bfloat162_rn(acc[ni][2] * inv_hi, acc[ni][3] * inv_hi);
        p32[r_lo * PSTR + cu] = *(unsigned*)&p0;
        p32[r_hi * PSTR + cu] = *(unsigned*)&p1;
    }
    __syncthreads();

    // ---- O = P @ V (per warp: 16 q x 32 dk, k = 368) ----
    float o[4][4];
    #pragma unroll
    for (int ni = 0; ni < 4; ni++)
        #pragma unroll
        for (int r = 0; r < 4; r++) o[ni][r] = 0.f;

    #pragma unroll
    for (int kt = 0; kt < 23; kt++) {
        const unsigned* ab = &p32[r_lo * PSTR + kt * 8 + t];
        unsigned a0 = ab[0], a1 = ab[8 * PSTR], a2 = ab[4], a3 = ab[8 * PSTR + 4];
        #pragma unroll
        for (int ni = 0; ni < 4; ni++) {
            const unsigned* bb = &vt32[(wk * 32 + ni * 8 + g) * PSTR + kt * 8 + t];
            unsigned b0 = bb[0], b1 = bb[4];
            BMMA(o[ni], a0, a1, a2, a3, b0, b1);
        }
    }

    // ---- write O (bf16) to g_ctxb (B,S,D) ----
    const int head = bh & 3;
    #pragma unroll
    for (int ni = 0; ni < 4; ni++) {
        int col = wk * 32 + ni * 8 + t * 2;
        if (qbase + r_lo < SEQ) {
            size_t ob = ((size_t)(b * SEQ + qbase + r_lo)) * D + head * DK + col;
            *(bf162*)(g_ctxb + ob) = __floats2bfloat162_rn(o[ni][0], o[ni][1]);
        }
        if (qbase + r_hi < SEQ) {
            size_t ob = ((size_t)(b * SEQ + qbase + r_hi)) * D + head * DK + col;
            *(bf162*)(g_ctxb + ob) = __floats2bfloat162_rn(o[ni][2], o[ni][3]);
        }
    }
}

// ---------------- classifier + output masks ----------------
__global__ void cls_kernel(const int* __restrict__ src,
                           const float* __restrict__ wl,
                           const float* __restrict__ bl,
                           float* __restrict__ out) {
    int bp = blockIdx.x;
    int b = bp / NPAIR, p = bp - b * NPAIR;

    int i = 0, rem = p;
    while (rem >= 13 - i) { rem -= 13 - i; i++; }
    int j = i + 1 + rem;
    int base = i * 12 - (i * (i - 1)) / 2;
    int pe = base + (j - i) - 1;
    int eb = 28 + 2 * pe;
    int gidx[8] = {2*i, 2*i+1, 2*j, 2*j+1, eb, eb+1, eb+2, eb+3};

    int tid = threadIdx.x;
    const float* xb = g_x + (size_t)(b * SEQ) * D;
    int slots = (j < 13) ? 8 : 4;

    float a0 = 0.f, a1 = 0.f, a2 = 0.f;
    for (int sl = 0; sl < slots; sl++) {
        float xv = xb[gidx[sl] * D + tid];
        const float* wr = wl + ((size_t)(sl * D + tid)) * 3;
        a0 = fmaf(xv, wr[0], a0);
        a1 = fmaf(xv, wr[1], a1);
        a2 = fmaf(xv, wr[2], a2);
    }
    a0 = warp_sum(a0); a1 = warp_sum(a1); a2 = warp_sum(a2);

    __shared__ float red[8][3];
    int lane = tid & 31, w = tid >> 5;
    if (lane == 0) { red[w][0] = a0; red[w][1] = a1; red[w][2] = a2; }
    __syncthreads();

    if (tid == 0) {
        float s0 = bl[0], s1 = bl[1], s2 = bl[2];
        #pragma unroll
        for (int t = 0; t < 8; t++) { s0 += red[t][0]; s1 += red[t][1]; s2 += red[t][2]; }

        const int* sb = src + b * SEQ;
        int ti = sb[2*i], ai = sb[2*i+1], tj = sb[2*j], aj = sb[2*j+1];
        bool c1 = (ai == 2) || (aj == 2);
        bool c2 = (tj == 1) || (ai == 1) || (aj == 1);
        bool c3 = (ti == PADTOK) || (tj == PADTOK) || (ai == 0) || (aj == 0);
        bool c4 = false;
        if (j < 13) {
            int es = 28 + 4 * pe;              // EIDX base: 4*pe (not 2*pe)
            c4 = (sb[es] == 1) || (sb[es+1] == 1) || (sb[es+2] == 1) || (sb[es+3] == 1);
        }
        bool m111 = c3 || c4;
        bool mk1 = m111 || c2;
        bool mk2 = mk1 || c1;
        float* o = out + (size_t)bp * 3;
        o[0] = m111 ? -1e9f : s0;
        o[1] = mk1  ? -1e9f : s1;
        o[2] = mk2  ? -1e9f : s2;
    }
}

// ---------------- launch ----------------
extern "C" void kernel_launch(void* const* d_in, const int* in_sizes, int n_in,
                              void* d_out, int out_size) {
    (void)in_sizes; (void)n_in; (void)out_size;
    const int*   src = (const int*)  d_in[0];
    const float* emb = (const float*)d_in[1];
    const float* wq  = (const float*)d_in[2];
    const float* bq  = (const float*)d_in[3];
    const float* wk  = (const float*)d_in[4];
    const float* bk  = (const float*)d_in[5];
    const float* wv  = (const float*)d_in[6];
    const float* bv  = (const float*)d_in[7];
    const float* wo  = (const float*)d_in[8];
    const float* bo  = (const float*)d_in[9];
    const float* n1a = (const float*)d_in[10];
    const float* n1b = (const float*)d_in[11];
    const float* n2a = (const float*)d_in[12];
    const float* n2b = (const float*)d_in[13];
    const float* w1  = (const float*)d_in[14];
    const float* b1  = (const float*)d_in[15];
    const float* w2  = (const float*)d_in[16];
    const float* b2  = (const float*)d_in[17];
    const float* wl  = (const float*)d_in[18];
    const float* bl  = (const float*)d_in[19];
    float* out = (float*)d_out;

    float *px, *pbqs;
    bf16 *pxb, *pqb, *pkb, *pvb, *pctxb, *phb, *pwqT, *pwkT, *pwvT, *pwoT, *pw1T, *pw2T;
    cudaGetSymbolAddress((void**)&px,    g_x);
    cudaGetSymbolAddress((void**)&pxb,   g_xb);
    cudaGetSymbolAddress((void**)&pqb,   g_qb);
    cudaGetSymbolAddress((void**)&pkb,   g_kb);
    cudaGetSymbolAddress((void**)&pvb,   g_vb);
    cudaGetSymbolAddress((void**)&pctxb, g_ctxb);
    cudaGetSymbolAddress((void**)&phb,   g_hb);
    cudaGetSymbolAddress((void**)&pwqT,  g_wqT);
    cudaGetSymbolAddress((void**)&pwkT,  g_wkT);
    cudaGetSymbolAddress((void**)&pwvT,  g_wvT);
    cudaGetSymbolAddress((void**)&pwoT,  g_woT);
    cudaGetSymbolAddress((void**)&pw1T,  g_w1T);
    cudaGetSymbolAddress((void**)&pw2T,  g_w2T);
    cudaGetSymbolAddress((void**)&pbqs,  g_bqs);

    cudaFuncSetAttribute(fattn_kernel, cudaFuncAttributeMaxDynamicSharedMemorySize,
                         (int)ATT_SMEM);

    // 0. weight conversion (transpose + bf16; fold 0.125 into wq/bq)
    convT_kernel<<<(D*D)/256, 256>>>(wq, pwqT, D, D, 0.125f);
    convT_kernel<<<(D*D)/256, 256>>>(wk, pwkT, D, D, 1.0f);
    convT_kernel<<<(D*D)/256, 256>>>(wv, pwvT, D, D, 1.0f);
    convT_kernel<<<(D*D)/256, 256>>>(wo, pwoT, D, D, 1.0f);
    convT_kernel<<<(D*DFF)/256, 256>>>(w1, pw1T, D, DFF, 1.0f);
    convT_kernel<<<(D*DFF)/256, 256>>>(w2, pw2T, DFF, D, 1.0f);
    scaleb_kernel<<<1, D>>>(bq);

    // 1. PE + fused embedding+LN1
    pe_kernel<<<PREFIX, D>>>();
    embed_ln_kernel<<<TOKENS, D>>>(src, emb, n1a, n1b);

    // 2. QKV projections (bf16 out, (B,H,S,DK))
    dim3 g256(D / 128, TOKENS / 128);
    bgemm_kernel<0><<<g256, 256>>>(pxb, pwqT, pbqs, nullptr, pqb, TOKENS, D, D);
    bgemm_kernel<0><<<g256, 256>>>(pxb, pwkT, bk,   nullptr, pkb, TOKENS, D, D);
    bgemm_kernel<0><<<g256, 256>>>(pxb, pwvT, bv,   nullptr, pvb, TOKENS, D, D);

    // 3. tensor-core attention -> g_ctxb (bf16)
    dim3 ga(6, HEADS);
    fattn_kernel<<<ga, 256, ATT_SMEM>>>(src);

    // 4. output projection + residual (x += ctx@wo + bo)
    bgemm_kernel<1><<<g256, 256>>>(pctxb, pwoT, bo, px, px, TOKENS, D, D);

    // 5. layernorm 2 (g_x -> g_xb)
    ln_kernel<<<TOKENS, D>>>(n2a, n2b);

    // 6. FFN (hidden in bf16)
    dim3 gff1(DFF / 128, TOKENS / 128);
    bgemm_kernel<2><<<gff1, 256>>>(pxb, pw1T, b1, nullptr, phb, TOKENS, DFF, D);
    bgemm_kernel<3><<<g256, 256>>>(phb, pw2T, b2, px, px, TOKENS, D, DFF);

    // 7. classifier + masks
    cls_kernel<<<BATCH * NPAIR, D>>>(src, wl, bl, out);
}

// round 11
// speedup vs baseline: 4.1232x; 1.1121x over previous
#include <cuda_runtime.h>
#include <cuda_bf16.h>
#include <math.h>

// ---------------- problem constants ----------------
#define BATCH   256
#define SEQ     360
#define PREFIX  340
#define D       256
#define H       4
#define DK      64
#define DFF     2048
#define NPAIR   91
#define PADTOK  799
#define TOKENS  (BATCH*SEQ)          // 92160
#define HEADS   (BATCH*H)            // 1024
#define HSTRIDE (SEQ*DK)             // 23040

typedef __nv_bfloat16 bf16;
typedef __nv_bfloat162 bf162;

// ---------------- scratch (device globals) ----------------
__device__ float g_x  [TOKENS*D];       // residual stream (fp32)
__device__ bf16  g_xb [TOKENS*D];       // layernorm output (bf16)
__device__ bf16  g_qb [TOKENS*D];       // (B,H,S,DK) bf16
__device__ bf16  g_kb [TOKENS*D];
__device__ bf16  g_vb [TOKENS*D];
__device__ bf16  g_ctxb[TOKENS*D];      // attention output (bf16)
__device__ bf16  g_hb [TOKENS*DFF];     // ffn hidden (bf16)
__device__ float g_pe [PREFIX*D];       // positional encodings
// transposed bf16 weights [N][K]
__device__ bf16  g_wqkvT[3*D*D];        // q (x0.125) | k | v
__device__ bf16  g_woT[D*D];
__device__ bf16  g_w1T[D*DFF];
__device__ bf16  g_w2T[D*DFF];
__device__ float g_bqkv[3*D];           // bq*0.125 | bk | bv

// ---------------- helpers ----------------
__device__ __forceinline__ float warp_sum(float v) {
    #pragma unroll
    for (int o = 16; o; o >>= 1) v += __shfl_xor_sync(0xffffffffu, v, o);
    return v;
}

#define BMMA(c, a0, a1, a2, a3, b0, b1)                                        \
    asm volatile(                                                              \
        "mma.sync.aligned.m16n8k16.row.col.f32.bf16.bf16.f32 "                 \
        "{%0,%1,%2,%3}, {%4,%5,%6,%7}, {%8,%9}, {%0,%1,%2,%3};"                \
        : "+f"(c[0]), "+f"(c[1]), "+f"(c[2]), "+f"(c[3])                       \
        : "r"(a0), "r"(a1), "r"(a2), "r"(a3), "r"(b0), "r"(b1))

__device__ __forceinline__ void ldsm4(unsigned &r0, unsigned &r1,
                                      unsigned &r2, unsigned &r3, unsigned addr) {
    asm volatile("ldmatrix.sync.aligned.m8n8.x4.shared.b16 {%0,%1,%2,%3}, [%4];"
        : "=r"(r0), "=r"(r1), "=r"(r2), "=r"(r3) : "r"(addr));
}
__device__ __forceinline__ void cpasync16(void* sdst, const void* gsrc) {
    unsigned s = (unsigned)__cvta_generic_to_shared(sdst);
    asm volatile("cp.async.cg.shared.global [%0], [%1], 16;" :: "r"(s), "l"(gsrc));
}

// ---------------- PE table (double precision, matches numpy) --------------
__global__ void pe_kernel() {
    int s = blockIdx.x, d = threadIdx.x;
    double e   = pow(10000.0, ((double)(2 * d)) / 256.0);
    double arg = (double)s / e;
    g_pe[s * D + d] = (float)((d & 1) ? cos(arg) : sin(arg));
}

// ---------------- all weight transposes + bf16 convert (one kernel) -------
__global__ void convall_kernel(const float* __restrict__ wq, const float* __restrict__ wk,
                               const float* __restrict__ wv, const float* __restrict__ wo,
                               const float* __restrict__ w1, const float* __restrict__ w2) {
    int bid = blockIdx.x, tid = threadIdx.x;
    if (bid < 1024) {                       // 4 DxD matrices, 256 blocks each
        int m = bid >> 8;
        int idx = ((bid & 255) << 8) + tid;
        int k = idx >> 8, n = idx & 255;
        if (m == 0)      g_wqkvT[n * 256 + k]           = __float2bfloat16(wq[idx] * 0.125f);
        else if (m == 1) g_wqkvT[65536 + n * 256 + k]   = __float2bfloat16(wk[idx]);
        else if (m == 2) g_wqkvT[131072 + n * 256 + k]  = __float2bfloat16(wv[idx]);
        else             g_woT[n * 256 + k]             = __float2bfloat16(wo[idx]);
    } else if (bid < 3072) {                // w1 [256][2048] -> [2048][256]
        int idx = (bid - 1024) * 256 + tid;
        int k = idx >> 11, n = idx & 2047;
        g_w1T[n * 256 + k] = __float2bfloat16(w1[idx]);
    } else {                                // w2 [2048][256] -> [256][2048]
        int idx = (bid - 3072) * 256 + tid;
        int k = idx >> 8, n = idx & 255;
        g_w2T[(size_t)n * 2048 + k] = __float2bfloat16(w2[idx]);
    }
}
__global__ void pack_bias_kernel(const float* __restrict__ bq,
                                 const float* __restrict__ bk,
                                 const float* __restrict__ bv) {
    int i = threadIdx.x;
    if (i < 256)      g_bqkv[i] = bq[i] * 0.125f;
    else if (i < 512) g_bqkv[i] = bk[i - 256];
    else              g_bqkv[i] = bv[i - 512];
}

// ---------------- fused embedding + scale + PE + LN1 (warp per token) -----
__global__ void embed_ln_kernel(const int* __restrict__ src,
                                const float* __restrict__ emb,
                                const float* __restrict__ ga,
                                const float* __restrict__ gb) {
    int w = threadIdx.x >> 5, lane = threadIdx.x & 31;
    int t = blockIdx.x * 8 + w;
    int tok = src[t];
    int s = t % SEQ;
    const float4* er = (const float4*)(emb + (size_t)tok * D);
    float4 a = er[lane * 2], b = er[lane * 2 + 1];
    if (s < PREFIX) {
        const float4* pr = (const float4*)(g_pe + s * D);
        float4 p = pr[lane * 2], q = pr[lane * 2 + 1];
        a.x = fmaf(a.x, 16.f, p.x); a.y = fmaf(a.y, 16.f, p.y);
        a.z = fmaf(a.z, 16.f, p.z); a.w = fmaf(a.w, 16.f, p.w);
        b.x = fmaf(b.x, 16.f, q.x); b.y = fmaf(b.y, 16.f, q.y);
        b.z = fmaf(b.z, 16.f, q.z); b.w = fmaf(b.w, 16.f, q.w);
    }
    size_t off = (size_t)t * D + lane * 8;
    *(float4*)(g_x + off)     = a;
    *(float4*)(g_x + off + 4) = b;

    float sum = a.x + a.y + a.z + a.w + b.x + b.y + b.z + b.w;
    float mu = warp_sum(sum) * (1.0f / 256.0f);
    float dx[8] = {a.x - mu, a.y - mu, a.z - mu, a.w - mu,
                   b.x - mu, b.y - mu, b.z - mu, b.w - mu};
    float ss = 0.f;
    #pragma unroll
    for (int i = 0; i < 8; i++) ss = fmaf(dx[i], dx[i], ss);
    float inv = 1.0f / (sqrtf(warp_sum(ss) * (1.0f / 255.0f)) + 1e-6f);

    const float4* gav = (const float4*)(ga + lane * 8);
    const float4* gbv = (const float4*)(gb + lane * 8);
    float4 g0 = gav[0], g1 = gav[1], h0 = gbv[0], h1 = gbv[1];
    bf162 o[4];
    o[0] = __floats2bfloat162_rn(fmaf(g0.x, dx[0]*inv, h0.x), fmaf(g0.y, dx[1]*inv, h0.y));
    o[1] = __floats2bfloat162_rn(fmaf(g0.z, dx[2]*inv, h0.z), fmaf(g0.w, dx[3]*inv, h0.w));
    o[2] = __floats2bfloat162_rn(fmaf(g1.x, dx[4]*inv, h1.x), fmaf(g1.y, dx[5]*inv, h1.y));
    o[3] = __floats2bfloat162_rn(fmaf(g1.z, dx[6]*inv, h1.z), fmaf(g1.w, dx[7]*inv, h1.w));
    *(uint4*)(g_xb + off) = *(uint4*)o;
}

// ---------------- layernorm 2 (warp per token) ----------------------------
__global__ void ln_kernel(const float* __restrict__ ga,
                          const float* __restrict__ gb) {
    int w = threadIdx.x >> 5, lane = threadIdx.x & 31;
    int t = blockIdx.x * 8 + w;
    size_t off = (size_t)t * D + lane * 8;
    float4 a = *(const float4*)(g_x + off);
    float4 b = *(const float4*)(g_x + off + 4);

    float sum = a.x + a.y + a.z + a.w + b.x + b.y + b.z + b.w;
    float mu = warp_sum(sum) * (1.0f / 256.0f);
    float dx[8] = {a.x - mu, a.y - mu, a.z - mu, a.w - mu,
                   b.x - mu, b.y - mu, b.z - mu, b.w - mu};
    float ss = 0.f;
    #pragma unroll
    for (int i = 0; i < 8; i++) ss = fmaf(dx[i], dx[i], ss);
    float inv = 1.0f / (sqrtf(warp_sum(ss) * (1.0f / 255.0f)) + 1e-6f);

    const float4* gav = (const float4*)(ga + lane * 8);
    const float4* gbv = (const float4*)(gb + lane * 8);
    float4 g0 = gav[0], g1 = gav[1], h0 = gbv[0], h1 = gbv[1];
    bf162 o[4];
    o[0] = __floats2bfloat162_rn(fmaf(g0.x, dx[0]*inv, h0.x), fmaf(g0.y, dx[1]*inv, h0.y));
    o[1] = __floats2bfloat162_rn(fmaf(g0.z, dx[2]*inv, h0.z), fmaf(g0.w, dx[3]*inv, h0.w));
    o[2] = __floats2bfloat162_rn(fmaf(g1.x, dx[4]*inv, h1.x), fmaf(g1.y, dx[5]*inv, h1.y));
    o[3] = __floats2bfloat162_rn(fmaf(g1.z, dx[6]*inv, h1.z), fmaf(g1.w, dx[7]*inv, h1.w));
    *(uint4*)(g_xb + off) = *(uint4*)o;
}

// ---------------- bf16 tensor-core GEMM (cp.async + ldmatrix, K-tile 64) --
// EPI 0: QKV  -> bf16 into C0/C1/C2 (q/k/v) in (B,H,S,DK) layout, +bias
// EPI 1: WO   -> fp32 C0 = res + acc + bias
// EPI 2: FFN1 -> bf16 C0 = relu(acc + bias)
// EPI 3: FFN2 -> fp32 C0 = res + acc + bias
#define KT 64
#define BSTRH 72                              // smem row stride (bf16)
#define ABYTES (128*BSTRH*2)                  // 18432 bytes per stage per matrix
#define GEMM_SMEM (4*ABYTES)                  // 73728

template<int EPI>
__global__ __launch_bounds__(256)
void bgemm_kernel(const bf16* __restrict__ A, const bf16* __restrict__ Wt,
                  const float* __restrict__ bias, const float* __restrict__ res,
                  void* __restrict__ Cv0, void* __restrict__ Cv1, void* __restrict__ Cv2,
                  int M, int N, int K) {
    extern __shared__ bf16 smem[];
    const unsigned SMU = (unsigned)__cvta_generic_to_shared(smem);

    const int tid  = threadIdx.x;
    const int lane = tid & 31;
    const int wid  = tid >> 5;
    const int wm = wid >> 2;                  // 0..1  (64 rows)
    const int wn = wid & 3;                   // 0..3  (32 cols)
    const int g = lane >> 2;
    const int t = lane & 3;

    const int bm = blockIdx.y * 128;
    const int bn = blockIdx.x * 128;

    // cp.async load mapping: thread -> (row, 32-bf16 half)
    const int lrow  = tid >> 1;
    const int lhalf = (tid & 1) * 32;
    const bf16* Ap = A  + (size_t)(bm + lrow) * K + lhalf;
    const bf16* Bp = Wt + (size_t)(bn + lrow) * K + lhalf;
    bf16* sA = smem;
    bf16* sB = smem + 2 * 128 * BSTRH;

    // ldmatrix lane constants
    const int a_r = lane & 15;
    const int a_c = ((lane >> 4) & 1) * 8;
    const int b_n = (lane & 7) + ((lane >> 4) & 1) * 8;
    const int b_c = ((lane >> 3) & 1) * 8;

    float acc[4][4][4];
    #pragma unroll
    for (int mi = 0; mi < 4; mi++)
        #pragma unroll
        for (int ni = 0; ni < 4; ni++)
            #pragma unroll
            for (int r = 0; r < 4; r++) acc[mi][ni][r] = 0.f;

    const int nt = K >> 6;

    // prefetch tile 0 into stage 0
    {
        bf16* ad = sA + lrow * BSTRH + lhalf;
        bf16* bd = sB + lrow * BSTRH + lhalf;
        const bf16* ap = Ap;
        const bf16* bp = Bp;
        #pragma unroll
        for (int c = 0; c < 4; c++) cpasync16(ad + c * 8, ap + c * 8);
        #pragma unroll
        for (int c = 0; c < 4; c++) cpasync16(bd + c * 8, bp + c * 8);
    }
    asm volatile("cp.async.commit_group;");

    for (int tl = 0; tl < nt; tl++) {
        const int cur = tl & 1;
        if (tl + 1 < nt) {
            const int nxt = cur ^ 1;
            bf16* ad = sA + nxt * 128 * BSTRH + lrow * BSTRH + lhalf;
            bf16* bd = sB + nxt * 128 * BSTRH + lrow * BSTRH + lhalf;
            const bf16* ap = Ap + (tl + 1) * KT;
            const bf16* bp = Bp + (tl + 1) * KT;
            #pragma unroll
            for (int c = 0; c < 4; c++) cpasync16(ad + c * 8, ap + c * 8);
            #pragma unroll
            for (int c = 0; c < 4; c++) cpasync16(bd + c * 8, bp + c * 8);
            asm volatile("cp.async.commit_group;");
            asm volatile("cp.async.wait_group 1;" ::: "memory");
        } else {
            asm volatile("cp.async.wait_group 0;" ::: "memory");
        }
        __syncthreads();

        const unsigned abase = SMU + cur * ABYTES;
        const unsigned bbase = SMU + 2 * ABYTES + cur * ABYTES;
        #pragma unroll
        for (int kk = 0; kk < 4; kk++) {
            unsigned af[4][4], bfr[2][4];
            #pragma unroll
            for (int mi = 0; mi < 4; mi++) {
                unsigned addr = abase +
                    ((unsigned)((wm * 64 + mi * 16 + a_r) * BSTRH + kk * 16 + a_c) << 1);
                ldsm4(af[mi][0], af[mi][1], af[mi][2], af[mi][3], addr);
            }
            #pragma unroll
            for (int p = 0; p < 2; p++) {
                unsigned addr = bbase +
                    ((unsigned)((wn * 32 + p * 16 + b_n) * BSTRH + kk * 16 + b_c) << 1);
                ldsm4(bfr[p][0], bfr[p][1], bfr[p][2], bfr[p][3], addr);
            }
            #pragma unroll
            for (int mi = 0; mi < 4; mi++)
                #pragma unroll
                for (int ni = 0; ni < 4; ni++)
                    BMMA(acc[mi][ni], af[mi][0], af[mi][1], af[mi][2], af[mi][3],
                         bfr[ni >> 1][(ni & 1) * 2], bfr[ni >> 1][(ni & 1) * 2 + 1]);
        }
        __syncthreads();
    }

    // ------------- epilogue -------------
    float* C  = (float*)Cv0;
    bf16*  Cb = (bf16*)Cv0;
    if (EPI == 0) {
        int tgt = bn >> 8;                      // block-uniform target q/k/v
        Cb = (bf16*)(tgt == 0 ? Cv0 : tgt == 1 ? Cv1 : Cv2);
    }
    #pragma unroll
    for (int mi = 0; mi < 4; mi++) {
        int row0 = bm + wm * 64 + mi * 16 + g;
        #pragma unroll
        for (int ni = 0; ni < 4; ni++) {
            int col = bn + wn * 32 + ni * 8 + t * 2;
            float2 bb = *(const float2*)(bias + col);
            #pragma unroll
            for (int half = 0; half < 2; half++) {
                int row = row0 + half * 8;
                float v0 = acc[mi][ni][half * 2 + 0] + bb.x;
                float v1 = acc[mi][ni][half * 2 + 1] + bb.y;
                if (EPI == 0) {
                    int ic = col & 255;
                    int bbt = row / SEQ;
                    int s   = row - bbt * SEQ;
                    bf16* cb = Cb + (size_t)bbt * (H * HSTRIDE) + (ic >> 6) * HSTRIDE
                                  + s * DK + (ic & 63);
                    *(bf162*)cb = __floats2bfloat162_rn(v0, v1);
                } else if (EPI == 2) {
                    *(bf162*)(Cb + (size_t)row * N + col) =
                        __floats2bfloat162_rn(fmaxf(v0, 0.f), fmaxf(v1, 0.f));
                } else {
                    size_t ro = (size_t)row * N + col;
                    float2 rv = *(const float2*)(res + ro);
                    *(float2*)(C + ro) = make_float2(rv.x + v0, rv.y + v1);
                }
            }
        }
    }
}

// ---------------- tensor-core attention ----------------
#define QSTR 36     // Q/K smem row stride (uint32)
#define PSTR 188    // P/VT smem row stride (uint32); 376 bf16
#define ATT_SMEM ((64*QSTR + 368*QSTR + 64*PSTR + 64*PSTR) * 4 + 256 * 4)

__global__ __launch_bounds__(256, 1)
void fattn_kernel(const int* __restrict__ src) {
    extern __shared__ unsigned sm32[];
    unsigned* q32  = sm32;                 // 64 x 36
    unsigned* k32  = q32  + 64 * QSTR;     // 368 x 36
    unsigned* vt32 = k32  + 368 * QSTR;    // 64 x 188 (VT: [dk][key])
    unsigned* p32  = vt32 + 64 * PSTR;     // 64 x 188 (P bf16)
    float* redm = (float*)(p32 + 64 * PSTR);
    float* reds = redm + 128;

    const int qt = blockIdx.x;
    const int bh = blockIdx.y;
    const int b  = bh >> 2;
    const int qbase = qt * 64;
    const size_t hb = (size_t)bh * HSTRIDE;
    const int tid = threadIdx.x;

    const uint4* gq = (const uint4*)(g_qb + hb + (size_t)qbase * DK);
    #pragma unroll
    for (int u = tid; u < 512; u += 256) {
        int row = u >> 3, c8 = u & 7;
        uint4 val = make_uint4(0u, 0u, 0u, 0u);
        if (qbase + row < SEQ) val = gq[row * 8 + c8];
        *(uint4*)&q32[row * QSTR + c8 * 4] = val;
    }
    const uint4* gk = (const uint4*)(g_kb + hb);
    for (int u = tid; u < 2880; u += 256) {
        int row = u >> 3, c8 = u & 7;
        *(uint4*)&k32[row * QSTR + c8 * 4] = gk[u];
    }
    const bf16* gv = g_vb + hb;
    bf16* vt = (bf16*)vt32;
    for (int i = tid; i < SEQ * DK; i += 256) {
        int key = i >> 6, dk = i & 63;
        vt[dk * 376 + key] = gv[i];
    }
    for (int i = tid; i < 64 * 16; i += 256) {
        int dk = i >> 4, key = 360 + (i & 15);
        vt[dk * 376 + key] = __float2bfloat16(0.f);
    }
    __syncthreads();

    const int lane = tid & 31, wid = tid >> 5;
    const int wq = wid >> 1;
    const int wk = wid & 1;
    const int g = lane >> 2, t = lane & 3;
    const int kb = wk * 184;
    const int r_lo = wq * 16 + g, r_hi = r_lo + 8;

    float acc[23][4];
    #pragma unroll
    for (int ni = 0; ni < 23; ni++)
        #pragma unroll
        for (int r = 0; r < 4; r++) acc[ni][r] = 0.f;

    #pragma unroll
    for (int kt = 0; kt < 4; kt++) {
        const unsigned* ab = &q32[r_lo * QSTR + kt * 8 + t];
        unsigned a0 = ab[0], a1 = ab[8 * QSTR], a2 = ab[4], a3 = ab[8 * QSTR + 4];
        #pragma unroll
        for (int ni = 0; ni < 23; ni++) {
            const unsigned* bb = &k32[(kb + ni * 8 + g) * QSTR + kt * 8 + t];
            unsigned b0 = bb[0], b1 = bb[4];
            BMMA(acc[ni], a0, a1, a2, a3, b0, b1);
        }
    }

    bool v_lo = true, v_hi = true;
    if (qbase + r_lo < SEQ) v_lo = (src[b * SEQ + qbase + r_lo] != PADTOK);
    if (qbase + r_hi < SEQ) v_hi = (src[b * SEQ + qbase + r_hi] != PADTOK);

    float m_lo = -1e30f, m_hi = -1e30f;
    #pragma unroll
    for (int ni = 0; ni < 23; ni++) {
        int col0 = kb + ni * 8 + t * 2;
        bool in0 = col0 < SEQ, in1 = col0 + 1 < SEQ;
        acc[ni][0] = in0 ? (v_lo ? acc[ni][0] : 0.f) : -1e30f;
        acc[ni][1] = in1 ? (v_lo ? acc[ni][1] : 0.f) : -1e30f;
        acc[ni][2] = in0 ? (v_hi ? acc[ni][2] : 0.f) : -1e30f;
        acc[ni][3] = in1 ? (v_hi ? acc[ni][3] : 0.f) : -1e30f;
        m_lo = fmaxf(m_lo, fmaxf(acc[ni][0], acc[ni][1]));
        m_hi = fmaxf(m_hi, fmaxf(acc[ni][2], acc[ni][3]));
    }
    m_lo = fmaxf(m_lo, __shfl_xor_sync(0xffffffffu, m_lo, 1));
    m_lo = fmaxf(m_lo, __shfl_xor_sync(0xffffffffu, m_lo, 2));
    m_hi = fmaxf(m_hi, __shfl_xor_sync(0xffffffffu, m_hi, 1));
    m_hi = fmaxf(m_hi, __shfl_xor_sync(0xffffffffu, m_hi, 2));
    if (t == 0) { redm[wk * 64 + r_lo] = m_lo; redm[wk * 64 + r_hi] = m_hi; }
    __syncthreads();
    m_lo = fmaxf(redm[r_lo], redm[64 + r_lo]);
    m_hi = fmaxf(redm[r_hi], redm[64 + r_hi]);

    float s_lo = 0.f, s_hi = 0.f;
    #pragma unroll
    for (int ni = 0; ni < 23; ni++) {
        acc[ni][0] = __expf(acc[ni][0] - m_lo);
        acc[ni][1] = __expf(acc[ni][1] - m_lo);
        acc[ni][2] = __expf(acc[ni][2] - m_hi);
        acc[ni][3] = __expf(acc[ni][3] - m_hi);
        s_lo += acc[ni][0] + acc[ni][1];
        s_hi += acc[ni][2] + acc[ni][3];
    }
    s_lo += __shfl_xor_sync(0xffffffffu, s_lo, 1);
    s_lo += __shfl_xor_sync(0xffffffffu, s_lo, 2);
    s_hi += __shfl_xor_sync(0xffffffffu, s_hi, 1);
    s_hi += __shfl_xor_sync(0xffffffffu, s_hi, 2);
    if (t == 0) { reds[wk * 64 + r_lo] = s_lo; reds[wk * 64 + r_hi] = s_hi; }
    __syncthreads();
    float inv_lo = 1.f / (reds[r_lo] + reds[64 + r_lo]);
    float inv_hi = 1.f / (reds[r_hi] + reds[64 + r_hi]);

    #pragma unroll
    for (int ni = 0; ni < 23; ni++) {
        int cu = (kb >> 1) + ni * 4 + t;
        bf162 p0 = __floats2bfloat162_rn(acc[ni][0] * inv_lo, acc[ni][1] * inv_lo);
        bf162 p1 = __floats2bfloat162_rn(acc[ni][2] * inv_hi, acc[ni][3] * inv_hi);
        p32[r_lo * PSTR + cu] = *(unsigned*)&p0;
        p32[r_hi * PSTR + cu] = *(unsigned*)&p1;
    }
    __syncthreads();

    float o[4][4];
    #pragma unroll
    for (int ni = 0; ni < 4; ni++)
        #pragma unroll
        for (int r = 0; r < 4; r++) o[ni][r] = 0.f;

    #pragma unroll
    for (int kt = 0; kt < 23; kt++) {
        const unsigned* ab = &p32[r_lo * PSTR + kt * 8 + t];
        unsigned a0 = ab[0], a1 = ab[8 * PSTR], a2 = ab[4], a3 = ab[8 * PSTR + 4];
        #pragma unroll
        for (int ni = 0; ni < 4; ni++) {
            const unsigned* bb = &vt32[(wk * 32 + ni * 8 + g) * PSTR + kt * 8 + t];
            unsigned b0 = bb[0], b1 = bb[4];
            BMMA(o[ni], a0, a1, a2, a3, b0, b1);
        }
    }

    const int head = bh & 3;
    #pragma unroll
    for (int ni = 0; ni < 4; ni++) {
        int col = wk * 32 + ni * 8 + t * 2;
        if (qbase + r_lo < SEQ) {
            size_t ob = ((size_t)(b * SEQ + qbase + r_lo)) * D + head * DK + col;
            *(bf162*)(g_ctxb + ob) = __floats2bfloat162_rn(o[ni][0], o[ni][1]);
        }
        if (qbase + r_hi < SEQ) {
            size_t ob = ((size_t)(b * SEQ + qbase + r_hi)) * D + head * DK + col;
            *(bf162*)(g_ctxb + ob) = __floats2bfloat162_rn(o[ni][2], o[ni][3]);
        }
    }
}

// ---------------- classifier + output masks ----------------
__global__ void cls_kernel(const int* __restrict__ src,
                           const float* __restrict__ wl,
                           const float* __restrict__ bl,
                           float* __restrict__ out) {
    int bp = blockIdx.x;
    int b = bp / NPAIR, p = bp - b * NPAIR;

    int i = 0, rem = p;
    while (rem >= 13 - i) { rem -= 13 - i; i++; }
    int j = i + 1 + rem;
    int base = i * 12 - (i * (i - 1)) / 2;
    int pe = base + (j - i) - 1;
    int eb = 28 + 2 * pe;
    int gidx[8] = {2*i, 2*i+1, 2*j, 2*j+1, eb, eb+1, eb+2, eb+3};

    int tid = threadIdx.x;
    const float* xb = g_x + (size_t)(b * SEQ) * D;
    int slots = (j < 13) ? 8 : 4;

    float a0 = 0.f, a1 = 0.f, a2 = 0.f;
    for (int sl = 0; sl < slots; sl++) {
        float xv = xb[gidx[sl] * D + tid];
        const float* wr = wl + ((size_t)(sl * D + tid)) * 3;
        a0 = fmaf(xv, wr[0], a0);
        a1 = fmaf(xv, wr[1], a1);
        a2 = fmaf(xv, wr[2], a2);
    }
    a0 = warp_sum(a0); a1 = warp_sum(a1); a2 = warp_sum(a2);

    __shared__ float red[8][3];
    int lane = tid & 31, w = tid >> 5;
    if (lane == 0) { red[w][0] = a0; red[w][1] = a1; red[w][2] = a2; }
    __syncthreads();

    if (tid == 0) {
        float s0 = bl[0], s1 = bl[1], s2 = bl[2];
        #pragma unroll
        for (int t = 0; t < 8; t++) { s0 += red[t][0]; s1 += red[t][1]; s2 += red[t][2]; }

        const int* sb = src + b * SEQ;
        int ti = sb[2*i], ai = sb[2*i+1], tj = sb[2*j], aj = sb[2*j+1];
        bool c1 = (ai == 2) || (aj == 2);
        bool c2 = (tj == 1) || (ai == 1) || (aj == 1);
        bool c3 = (ti == PADTOK) || (tj == PADTOK) || (ai == 0) || (aj == 0);
        bool c4 = false;
        if (j < 13) {
            int es = 28 + 4 * pe;              // EIDX base: 4*pe (not 2*pe)
            c4 = (sb[es] == 1) || (sb[es+1] == 1) || (sb[es+2] == 1) || (sb[es+3] == 1);
        }
        bool m111 = c3 || c4;
        bool mk1 = m111 || c2;
        bool mk2 = mk1 || c1;
        float* o = out + (size_t)bp * 3;
        o[0] = m111 ? -1e9f : s0;
        o[1] = mk1  ? -1e9f : s1;
        o[2] = mk2  ? -1e9f : s2;
    }
}

// ---------------- launch ----------------
extern "C" void kernel_launch(void* const* d_in, const int* in_sizes, int n_in,
                              void* d_out, int out_size) {
    (void)in_sizes; (void)n_in; (void)out_size;
    const int*   src = (const int*)  d_in[0];
    const float* emb = (const float*)d_in[1];
    const float* wq  = (const float*)d_in[2];
    const float* bq  = (const float*)d_in[3];
    const float* wk  = (const float*)d_in[4];
    const float* bk  = (const float*)d_in[5];
    const float* wv  = (const float*)d_in[6];
    const float* bv  = (const float*)d_in[7];
    const float* wo  = (const float*)d_in[8];
    const float* bo  = (const float*)d_in[9];
    const float* n1a = (const float*)d_in[10];
    const float* n1b = (const float*)d_in[11];
    const float* n2a = (const float*)d_in[12];
    const float* n2b = (const float*)d_in[13];
    const float* w1  = (const float*)d_in[14];
    const float* b1  = (const float*)d_in[15];
    const float* w2  = (const float*)d_in[16];
    const float* b2  = (const float*)d_in[17];
    const float* wl  = (const float*)d_in[18];
    const float* bl  = (const float*)d_in[19];
    float* out = (float*)d_out;

    float *px, *pbqkv;
    bf16 *pxb, *pqb, *pkb, *pvb, *pctxb, *phb, *pwqkvT, *pwoT, *pw1T, *pw2T;
    cudaGetSymbolAddress((void**)&px,     g_x);
    cudaGetSymbolAddress((void**)&pxb,    g_xb);
    cudaGetSymbolAddress((void**)&pqb,    g_qb);
    cudaGetSymbolAddress((void**)&pkb,    g_kb);
    cudaGetSymbolAddress((void**)&pvb,    g_vb);
    cudaGetSymbolAddress((void**)&pctxb,  g_ctxb);
    cudaGetSymbolAddress((void**)&phb,    g_hb);
    cudaGetSymbolAddress((void**)&pwqkvT, g_wqkvT);
    cudaGetSymbolAddress((void**)&pwoT,   g_woT);
    cudaGetSymbolAddress((void**)&pw1T,   g_w1T);
    cudaGetSymbolAddress((void**)&pw2T,   g_w2T);
    cudaGetSymbolAddress((void**)&pbqkv,  g_bqkv);

    cudaFuncSetAttribute(fattn_kernel, cudaFuncAttributeMaxDynamicSharedMemorySize,
                         (int)ATT_SMEM);
    cudaFuncSetAttribute(bgemm_kernel<0>, cudaFuncAttributeMaxDynamicSharedMemorySize, GEMM_SMEM);
    cudaFuncSetAttribute(bgemm_kernel<1>, cudaFuncAttributeMaxDynamicSharedMemorySize, GEMM_SMEM);
    cudaFuncSetAttribute(bgemm_kernel<2>, cudaFuncAttributeMaxDynamicSharedMemorySize, GEMM_SMEM);
    cudaFuncSetAttribute(bgemm_kernel<3>, cudaFuncAttributeMaxDynamicSharedMemorySize, GEMM_SMEM);

    // launch index:                                             (ncu -s 5 -> #5)
    convall_kernel<<<5120, 256>>>(wq, wk, wv, wo, w1, w2);            // 0
    pack_bias_kernel<<<1, 768>>>(bq, bk, bv);                         // 1
    pe_kernel<<<PREFIX, D>>>();                                       // 2
    embed_ln_kernel<<<TOKENS/8, 256>>>(src, emb, n1a, n1b);           // 3

    dim3 gqkv(6, TOKENS / 128);
    bgemm_kernel<0><<<gqkv, 256, GEMM_SMEM>>>(pxb, pwqkvT, pbqkv, nullptr,
                                              pqb, pkb, pvb, TOKENS, 768, D);   // 4

    dim3 ga(6, HEADS);
    fattn_kernel<<<ga, 256, ATT_SMEM>>>(src);                         // 5 <- profiled

    dim3 g256(2, TOKENS / 128);
    bgemm_kernel<1><<<g256, 256, GEMM_SMEM>>>(pctxb, pwoT, bo, px,
                                              px, nullptr, nullptr, TOKENS, D, D);   // 6

    ln_kernel<<<TOKENS/8, 256>>>(n2a, n2b);                           // 7

    dim3 gff1(16, TOKENS / 128);
    bgemm_kernel<2><<<gff1, 256, GEMM_SMEM>>>(pxb, pw1T, b1, nullptr,
                                              phb, nullptr, nullptr, TOKENS, DFF, D); // 8
    bgemm_kernel<3><<<g256, 256, GEMM_SMEM>>>(phb, pw2T, b2, px,
                                              px, nullptr, nullptr, TOKENS, D, DFF);  // 9

    cls_kernel<<<BATCH * NPAIR, D>>>(src, wl, bl, out);               // 10
}

// round 12
// speedup vs baseline: 5.3350x; 1.2939x over previous
#include <cuda_runtime.h>
#include <cuda_bf16.h>
#include <math.h>

// ---------------- problem constants ----------------
#define BATCH   256
#define SEQ     360
#define PREFIX  340
#define D       256
#define H       4
#define DK      64
#define DFF     2048
#define NPAIR   91
#define PADTOK  799
#define TOKENS  (BATCH*SEQ)          // 92160
#define HEADS   (BATCH*H)            // 1024
#define HSTRIDE (SEQ*DK)             // 23040

typedef __nv_bfloat16 bf16;
typedef __nv_bfloat162 bf162;

// ---------------- scratch (device globals) ----------------
__device__ float g_x  [TOKENS*D];       // residual stream (fp32)
__device__ bf16  g_xb [TOKENS*D];       // layernorm output (bf16)
__device__ bf16  g_qb [TOKENS*D];       // (B,H,S,DK) bf16
__device__ bf16  g_kb [TOKENS*D];
__device__ bf16  g_vb [TOKENS*D];
__device__ bf16  g_ctxb[TOKENS*D];      // attention output (bf16)
__device__ bf16  g_hb [TOKENS*DFF];     // ffn hidden (bf16)
__device__ float g_pe [PREFIX*D];       // positional encodings
// transposed bf16 weights [N][K]
__device__ bf16  g_wqkvT[3*D*D];        // q (x0.125) | k | v
__device__ bf16  g_woT[D*D];
__device__ bf16  g_w1T[D*DFF];
__device__ bf16  g_w2T[D*DFF];
__device__ float g_bqkv[3*D];           // bq*0.125 | bk | bv

// ---------------- helpers ----------------
__device__ __forceinline__ float warp_sum(float v) {
    #pragma unroll
    for (int o = 16; o; o >>= 1) v += __shfl_xor_sync(0xffffffffu, v, o);
    return v;
}

#define BMMA(c, a0, a1, a2, a3, b0, b1)                                        \
    asm volatile(                                                              \
        "mma.sync.aligned.m16n8k16.row.col.f32.bf16.bf16.f32 "                 \
        "{%0,%1,%2,%3}, {%4,%5,%6,%7}, {%8,%9}, {%0,%1,%2,%3};"                \
        : "+f"(c[0]), "+f"(c[1]), "+f"(c[2]), "+f"(c[3])                       \
        : "r"(a0), "r"(a1), "r"(a2), "r"(a3), "r"(b0), "r"(b1))

__device__ __forceinline__ void ldsm4(unsigned &r0, unsigned &r1,
                                      unsigned &r2, unsigned &r3, unsigned addr) {
    asm volatile("ldmatrix.sync.aligned.m8n8.x4.shared.b16 {%0,%1,%2,%3}, [%4];"
        : "=r"(r0), "=r"(r1), "=r"(r2), "=r"(r3) : "r"(addr));
}
__device__ __forceinline__ void cpasync16(void* sdst, const void* gsrc) {
    unsigned s = (unsigned)__cvta_generic_to_shared(sdst);
    asm volatile("cp.async.cg.shared.global [%0], [%1], 16;" :: "r"(s), "l"(gsrc));
}

// ---------------- PE table (fp32; abs err ~3e-5, tolerance 1e-3) ----------
__global__ void pe_kernel() {
    int s = blockIdx.x, d = threadIdx.x;
    // pos / 10000^(2d/256) = pos * exp2(-(d/128)*log2(10000))
    float ex  = exp2f(-13.287712379549449f * ((float)d) * (1.0f / 128.0f));
    float arg = (float)s * ex;
    g_pe[s * D + d] = (d & 1) ? cosf(arg) : sinf(arg);
}

// ---------------- all weight transposes + bf16 convert (one kernel) -------
__global__ void convall_kernel(const float* __restrict__ wq, const float* __restrict__ wk,
                               const float* __restrict__ wv, const float* __restrict__ wo,
                               const float* __restrict__ w1, const float* __restrict__ w2) {
    int bid = blockIdx.x, tid = threadIdx.x;
    if (bid < 1024) {                       // 4 DxD matrices, 256 blocks each
        int m = bid >> 8;
        int idx = ((bid & 255) << 8) + tid;
        int k = idx >> 8, n = idx & 255;
        if (m == 0)      g_wqkvT[n * 256 + k]           = __float2bfloat16(wq[idx] * 0.125f);
        else if (m == 1) g_wqkvT[65536 + n * 256 + k]   = __float2bfloat16(wk[idx]);
        else if (m == 2) g_wqkvT[131072 + n * 256 + k]  = __float2bfloat16(wv[idx]);
        else             g_woT[n * 256 + k]             = __float2bfloat16(wo[idx]);
    } else if (bid < 3072) {                // w1 [256][2048] -> [2048][256]
        int idx = (bid - 1024) * 256 + tid;
        int k = idx >> 11, n = idx & 2047;
        g_w1T[n * 256 + k] = __float2bfloat16(w1[idx]);
    } else {                                // w2 [2048][256] -> [256][2048]
        int idx = (bid - 3072) * 256 + tid;
        int k = idx >> 8, n = idx & 255;
        g_w2T[(size_t)n * 2048 + k] = __float2bfloat16(w2[idx]);
    }
}
__global__ void pack_bias_kernel(const float* __restrict__ bq,
                                 const float* __restrict__ bk,
                                 const float* __restrict__ bv) {
    int i = threadIdx.x;
    if (i < 256)      g_bqkv[i] = bq[i] * 0.125f;
    else if (i < 512) g_bqkv[i] = bk[i - 256];
    else              g_bqkv[i] = bv[i - 512];
}

// ---------------- fused embedding + scale + PE + LN1 (warp per token) -----
__global__ void embed_ln_kernel(const int* __restrict__ src,
                                const float* __restrict__ emb,
                                const float* __restrict__ ga,
                                const float* __restrict__ gb) {
    int w = threadIdx.x >> 5, lane = threadIdx.x & 31;
    int t = blockIdx.x * 8 + w;
    int tok = src[t];
    int s = t % SEQ;
    const float4* er = (const float4*)(emb + (size_t)tok * D);
    float4 a = er[lane * 2], b = er[lane * 2 + 1];
    if (s < PREFIX) {
        const float4* pr = (const float4*)(g_pe + s * D);
        float4 p = pr[lane * 2], q = pr[lane * 2 + 1];
        a.x = fmaf(a.x, 16.f, p.x); a.y = fmaf(a.y, 16.f, p.y);
        a.z = fmaf(a.z, 16.f, p.z); a.w = fmaf(a.w, 16.f, p.w);
        b.x = fmaf(b.x, 16.f, q.x); b.y = fmaf(b.y, 16.f, q.y);
        b.z = fmaf(b.z, 16.f, q.z); b.w = fmaf(b.w, 16.f, q.w);
    }
    size_t off = (size_t)t * D + lane * 8;
    *(float4*)(g_x + off)     = a;
    *(float4*)(g_x + off + 4) = b;

    float sum = a.x + a.y + a.z + a.w + b.x + b.y + b.z + b.w;
    float mu = warp_sum(sum) * (1.0f / 256.0f);
    float dx[8] = {a.x - mu, a.y - mu, a.z - mu, a.w - mu,
                   b.x - mu, b.y - mu, b.z - mu, b.w - mu};
    float ss = 0.f;
    #pragma unroll
    for (int i = 0; i < 8; i++) ss = fmaf(dx[i], dx[i], ss);
    float inv = 1.0f / (sqrtf(warp_sum(ss) * (1.0f / 255.0f)) + 1e-6f);

    const float4* gav = (const float4*)(ga + lane * 8);
    const float4* gbv = (const float4*)(gb + lane * 8);
    float4 g0 = gav[0], g1 = gav[1], h0 = gbv[0], h1 = gbv[1];
    bf162 o[4];
    o[0] = __floats2bfloat162_rn(fmaf(g0.x, dx[0]*inv, h0.x), fmaf(g0.y, dx[1]*inv, h0.y));
    o[1] = __floats2bfloat162_rn(fmaf(g0.z, dx[2]*inv, h0.z), fmaf(g0.w, dx[3]*inv, h0.w));
    o[2] = __floats2bfloat162_rn(fmaf(g1.x, dx[4]*inv, h1.x), fmaf(g1.y, dx[5]*inv, h1.y));
    o[3] = __floats2bfloat162_rn(fmaf(g1.z, dx[6]*inv, h1.z), fmaf(g1.w, dx[7]*inv, h1.w));
    *(uint4*)(g_xb + off) = *(uint4*)o;
}

// ---------------- layernorm 2 (warp per token) ----------------------------
__global__ void ln_kernel(const float* __restrict__ ga,
                          const float* __restrict__ gb) {
    int w = threadIdx.x >> 5, lane = threadIdx.x & 31;
    int t = blockIdx.x * 8 + w;
    size_t off = (size_t)t * D + lane * 8;
    float4 a = *(const float4*)(g_x + off);
    float4 b = *(const float4*)(g_x + off + 4);

    float sum = a.x + a.y + a.z + a.w + b.x + b.y + b.z + b.w;
    float mu = warp_sum(sum) * (1.0f / 256.0f);
    float dx[8] = {a.x - mu, a.y - mu, a.z - mu, a.w - mu,
                   b.x - mu, b.y - mu, b.z - mu, b.w - mu};
    float ss = 0.f;
    #pragma unroll
    for (int i = 0; i < 8; i++) ss = fmaf(dx[i], dx[i], ss);
    float inv = 1.0f / (sqrtf(warp_sum(ss) * (1.0f / 255.0f)) + 1e-6f);

    const float4* gav = (const float4*)(ga + lane * 8);
    const float4* gbv = (const float4*)(gb + lane * 8);
    float4 g0 = gav[0], g1 = gav[1], h0 = gbv[0], h1 = gbv[1];
    bf162 o[4];
    o[0] = __floats2bfloat162_rn(fmaf(g0.x, dx[0]*inv, h0.x), fmaf(g0.y, dx[1]*inv, h0.y));
    o[1] = __floats2bfloat162_rn(fmaf(g0.z, dx[2]*inv, h0.z), fmaf(g0.w, dx[3]*inv, h0.w));
    o[2] = __floats2bfloat162_rn(fmaf(g1.x, dx[4]*inv, h1.x), fmaf(g1.y, dx[5]*inv, h1.y));
    o[3] = __floats2bfloat162_rn(fmaf(g1.z, dx[6]*inv, h1.z), fmaf(g1.w, dx[7]*inv, h1.w));
    *(uint4*)(g_xb + off) = *(uint4*)o;
}

// ---------------- bf16 tensor-core GEMM (128x256 CTA, warp 64x64) --------
// EPI 0: QKV  -> bf16 into C0/C1/C2 (q/k/v) in (B,H,S,DK) layout, +bias
// EPI 1: WO   -> fp32 C0 = res + acc + bias
// EPI 2: FFN1 -> bf16 C0 = relu(acc + bias)
// EPI 3: FFN2 -> fp32 C0 = res + acc + bias
#define KT 64
#define BSTRH 72                              // smem row stride (bf16)
#define A_STG (128*BSTRH)                     // bf16 elems per A stage
#define B_STG (256*BSTRH)                     // bf16 elems per B stage
#define GEMM_SMEM ((2*A_STG + 2*B_STG) * 2)   // 110592 bytes

template<int EPI>
__global__ __launch_bounds__(256)
void bgemm_kernel(const bf16* __restrict__ A, const bf16* __restrict__ Wt,
                  const float* __restrict__ bias, const float* __restrict__ res,
                  void* __restrict__ Cv0, void* __restrict__ Cv1, void* __restrict__ Cv2,
                  int M, int N, int K) {
    extern __shared__ bf16 smem[];
    const unsigned SMU = (unsigned)__cvta_generic_to_shared(smem);

    const int tid  = threadIdx.x;
    const int lane = tid & 31;
    const int wid  = tid >> 5;
    const int wm = wid >> 2;                  // 0..1  (64 rows)
    const int wn = wid & 3;                   // 0..3  (64 cols)
    const int g = lane >> 2;
    const int t = lane & 3;

    const int bm = blockIdx.y * 128;
    const int bn = blockIdx.x * 256;

    // cp.async mapping: A row=tid/2 half=(tid&1)*32 ; B row=tid full 64
    const int arow  = tid >> 1;
    const int ahalf = (tid & 1) * 32;
    const bf16* Ap = A  + (size_t)(bm + arow) * K + ahalf;
    const bf16* Bp = Wt + (size_t)(bn + tid) * K;
    bf16* sA = smem;
    bf16* sB = smem + 2 * A_STG;

    // ldmatrix lane constants
    const int a_r = lane & 15;
    const int a_c = ((lane >> 4) & 1) * 8;
    const int b_n = (lane & 7) + ((lane >> 4) & 1) * 8;
    const int b_c = ((lane >> 3) & 1) * 8;

    float acc[4][8][4];
    #pragma unroll
    for (int mi = 0; mi < 4; mi++)
        #pragma unroll
        for (int ni = 0; ni < 8; ni++)
            #pragma unroll
            for (int r = 0; r < 4; r++) acc[mi][ni][r] = 0.f;

    const int nt = K >> 6;

    // prefetch tile 0 into stage 0
    {
        bf16* ad = sA + arow * BSTRH + ahalf;
        #pragma unroll
        for (int c = 0; c < 4; c++) cpasync16(ad + c * 8, Ap + c * 8);
        bf16* bd = sB + tid * BSTRH;
        #pragma unroll
        for (int c = 0; c < 8; c++) cpasync16(bd + c * 8, Bp + c * 8);
    }
    asm volatile("cp.async.commit_group;");

    for (int tl = 0; tl < nt; tl++) {
        const int cur = tl & 1;
        if (tl + 1 < nt) {
            const int nxt = cur ^ 1;
            bf16* ad = sA + nxt * A_STG + arow * BSTRH + ahalf;
            const bf16* ap = Ap + (tl + 1) * KT;
            #pragma unroll
            for (int c = 0; c < 4; c++) cpasync16(ad + c * 8, ap + c * 8);
            bf16* bd = sB + nxt * B_STG + tid * BSTRH;
            const bf16* bp = Bp + (tl + 1) * KT;
            #pragma unroll
            for (int c = 0; c < 8; c++) cpasync16(bd + c * 8, bp + c * 8);
            asm volatile("cp.async.commit_group;");
            asm volatile("cp.async.wait_group 1;" ::: "memory");
        } else {
            asm volatile("cp.async.wait_group 0;" ::: "memory");
        }
        __syncthreads();

        const unsigned abase = SMU + cur * (A_STG * 2);
        const unsigned bbase = SMU + 2 * (A_STG * 2) + cur * (B_STG * 2);
        #pragma unroll
        for (int kk = 0; kk < 4; kk++) {
            unsigned af[4][4], bfr[4][4];
            #pragma unroll
            for (int mi = 0; mi < 4; mi++) {
                unsigned addr = abase +
                    ((unsigned)((wm * 64 + mi * 16 + a_r) * BSTRH + kk * 16 + a_c) << 1);
                ldsm4(af[mi][0], af[mi][1], af[mi][2], af[mi][3], addr);
            }
            #pragma unroll
            for (int p = 0; p < 4; p++) {
                unsigned addr = bbase +
                    ((unsigned)((wn * 64 + p * 16 + b_n) * BSTRH + kk * 16 + b_c) << 1);
                ldsm4(bfr[p][0], bfr[p][1], bfr[p][2], bfr[p][3], addr);
            }
            #pragma unroll
            for (int mi = 0; mi < 4; mi++)
                #pragma unroll
                for (int ni = 0; ni < 8; ni++)
                    BMMA(acc[mi][ni], af[mi][0], af[mi][1], af[mi][2], af[mi][3],
                         bfr[ni >> 1][(ni & 1) * 2], bfr[ni >> 1][(ni & 1) * 2 + 1]);
        }
        __syncthreads();
    }

    // ------------- epilogue -------------
    float* C  = (float*)Cv0;
    bf16*  Cb = (bf16*)Cv0;
    if (EPI == 0) {
        int tgt = blockIdx.x;                   // 0/1/2 -> q/k/v (256-col tiles)
        Cb = (bf16*)(tgt == 0 ? Cv0 : tgt == 1 ? Cv1 : Cv2);
    }
    #pragma unroll
    for (int mi = 0; mi < 4; mi++) {
        int row0 = bm + wm * 64 + mi * 16 + g;
        #pragma unroll
        for (int ni = 0; ni < 8; ni++) {
            int col = bn + wn * 64 + ni * 8 + t * 2;
            float2 bb = *(const float2*)(bias + col);
            #pragma unroll
            for (int half = 0; half < 2; half++) {
                int row = row0 + half * 8;
                float v0 = acc[mi][ni][half * 2 + 0] + bb.x;
                float v1 = acc[mi][ni][half * 2 + 1] + bb.y;
                if (EPI == 0) {
                    int ic = col & 255;
                    int bbt = row / SEQ;
                    int s   = row - bbt * SEQ;
                    bf16* cb = Cb + (size_t)bbt * (H * HSTRIDE) + (ic >> 6) * HSTRIDE
                                  + s * DK + (ic & 63);
                    *(bf162*)cb = __floats2bfloat162_rn(v0, v1);
                } else if (EPI == 2) {
                    *(bf162*)(Cb + (size_t)row * N + col) =
                        __floats2bfloat162_rn(fmaxf(v0, 0.f), fmaxf(v1, 0.f));
                } else {
                    size_t ro = (size_t)row * N + col;
                    float2 rv = *(const float2*)(res + ro);
                    *(float2*)(C + ro) = make_float2(rv.x + v0, rv.y + v1);
                }
            }
        }
    }
}

// ---------------- tensor-core attention (block per head, qt loop) ---------
#define QSTR 36     // Q/K smem row stride (uint32)
#define PSTR 188    // P/VT smem row stride (uint32); 376 bf16
#define ATT_SMEM ((64*QSTR + 368*QSTR + 64*PSTR + 64*PSTR) * 4 + 256 * 4)

__global__ __launch_bounds__(256, 1)
void fattn_kernel(const int* __restrict__ src) {
    extern __shared__ unsigned sm32[];
    unsigned* q32  = sm32;                 // 64 x 36
    unsigned* k32  = q32  + 64 * QSTR;     // 368 x 36
    unsigned* vt32 = k32  + 368 * QSTR;    // 64 x 188 (VT: [dk][key])
    unsigned* p32  = vt32 + 64 * PSTR;     // 64 x 188 (P bf16)
    float* redm = (float*)(p32 + 64 * PSTR);
    float* reds = redm + 128;

    const int bh = blockIdx.x;
    const int b  = bh >> 2;
    const size_t hb = (size_t)bh * HSTRIDE;
    const int tid = threadIdx.x;

    // ---- load K + build VT once per head ----
    const uint4* gk = (const uint4*)(g_kb + hb);
    for (int u = tid; u < 2880; u += 256) {
        int row = u >> 3, c8 = u & 7;
        *(uint4*)&k32[row * QSTR + c8 * 4] = gk[u];
    }
    const bf16* gv = g_vb + hb;
    bf16* vt = (bf16*)vt32;
    for (int i = tid; i < SEQ * DK; i += 256) {
        int key = i >> 6, dk = i & 63;
        vt[dk * 376 + key] = gv[i];
    }
    for (int i = tid; i < 64 * 16; i += 256) {
        int dk = i >> 4, key = 360 + (i & 15);
        vt[dk * 376 + key] = __float2bfloat16(0.f);
    }

    const int lane = tid & 31, wid = tid >> 5;
    const int wq = wid >> 1;
    const int wk = wid & 1;
    const int g = lane >> 2, t = lane & 3;
    const int kb = wk * 184;
    const int r_lo = wq * 16 + g, r_hi = r_lo + 8;
    const int head = bh & 3;
    const uint4* gq = (const uint4*)(g_qb + hb);

    for (int qt = 0; qt < 6; qt++) {
        const int qbase = qt * 64;

        // ---- load Q tile (zero OOB rows) ----
        #pragma unroll
        for (int u = tid; u < 512; u += 256) {
            int row = u >> 3, c8 = u & 7;
            uint4 val = make_uint4(0u, 0u, 0u, 0u);
            if (qbase + row < SEQ) val = gq[(qbase + row) * 8 + c8];
            *(uint4*)&q32[row * QSTR + c8 * 4] = val;
        }
        __syncthreads();   // Q visible; also guards P/red reuse across iterations

        // ---- S = Q K^T ----
        float acc[23][4];
        #pragma unroll
        for (int ni = 0; ni < 23; ni++)
            #pragma unroll
            for (int r = 0; r < 4; r++) acc[ni][r] = 0.f;

        #pragma unroll
        for (int kt = 0; kt < 4; kt++) {
            const unsigned* ab = &q32[r_lo * QSTR + kt * 8 + t];
            unsigned a0 = ab[0], a1 = ab[8 * QSTR], a2 = ab[4], a3 = ab[8 * QSTR + 4];
            #pragma unroll
            for (int ni = 0; ni < 23; ni++) {
                const unsigned* bb = &k32[(kb + ni * 8 + g) * QSTR + kt * 8 + t];
                unsigned b0 = bb[0], b1 = bb[4];
                BMMA(acc[ni], a0, a1, a2, a3, b0, b1);
            }
        }

        // ---- softmax ----
        bool v_lo = true, v_hi = true;
        if (qbase + r_lo < SEQ) v_lo = (src[b * SEQ + qbase + r_lo] != PADTOK);
        if (qbase + r_hi < SEQ) v_hi = (src[b * SEQ + qbase + r_hi] != PADTOK);

        float m_lo = -1e30f, m_hi = -1e30f;
        #pragma unroll
        for (int ni = 0; ni < 23; ni++) {
            int col0 = kb + ni * 8 + t * 2;
            bool in0 = col0 < SEQ, in1 = col0 + 1 < SEQ;
            acc[ni][0] = in0 ? (v_lo ? acc[ni][0] : 0.f) : -1e30f;
            acc[ni][1] = in1 ? (v_lo ? acc[ni][1] : 0.f) : -1e30f;
            acc[ni][2] = in0 ? (v_hi ? acc[ni][2] : 0.f) : -1e30f;
            acc[ni][3] = in1 ? (v_hi ? acc[ni][3] : 0.f) : -1e30f;
            m_lo = fmaxf(m_lo, fmaxf(acc[ni][0], acc[ni][1]));
            m_hi = fmaxf(m_hi, fmaxf(acc[ni][2], acc[ni][3]));
        }
        m_lo = fmaxf(m_lo, __shfl_xor_sync(0xffffffffu, m_lo, 1));
        m_lo = fmaxf(m_lo, __shfl_xor_sync(0xffffffffu, m_lo, 2));
        m_hi = fmaxf(m_hi, __shfl_xor_sync(0xffffffffu, m_hi, 1));
        m_hi = fmaxf(m_hi, __shfl_xor_sync(0xffffffffu, m_hi, 2));
        if (t == 0) { redm[wk * 64 + r_lo] = m_lo; redm[wk * 64 + r_hi] = m_hi; }
        __syncthreads();
        m_lo = fmaxf(redm[r_lo], redm[64 + r_lo]);
        m_hi = fmaxf(redm[r_hi], redm[64 + r_hi]);

        float s_lo = 0.f, s_hi = 0.f;
        #pragma unroll
        for (int ni = 0; ni < 23; ni++) {
            acc[ni][0] = __expf(acc[ni][0] - m_lo);
            acc[ni][1] = __expf(acc[ni][1] - m_lo);
            acc[ni][2] = __expf(acc[ni][2] - m_hi);
            acc[ni][3] = __expf(acc[ni][3] - m_hi);
            s_lo += acc[ni][0] + acc[ni][1];
            s_hi += acc[ni][2] + acc[ni][3];
        }
        s_lo += __shfl_xor_sync(0xffffffffu, s_lo, 1);
        s_lo += __shfl_xor_sync(0xffffffffu, s_lo, 2);
        s_hi += __shfl_xor_sync(0xffffffffu, s_hi, 1);
        s_hi += __shfl_xor_sync(0xffffffffu, s_hi, 2);
        if (t == 0) { reds[wk * 64 + r_lo] = s_lo; reds[wk * 64 + r_hi] = s_hi; }
        __syncthreads();
        float inv_lo = 1.f / (reds[r_lo] + reds[64 + r_lo]);
        float inv_hi = 1.f / (reds[r_hi] + reds[64 + r_hi]);

        // ---- write P (bf16) ----
        #pragma unroll
        for (int ni = 0; ni < 23; ni++) {
            int cu = (kb >> 1) + ni * 4 + t;
            bf162 p0 = __floats2bfloat162_rn(acc[ni][0] * inv_lo, acc[ni][1] * inv_lo);
            bf162 p1 = __floats2bfloat162_rn(acc[ni][2] * inv_hi, acc[ni][3] * inv_hi);
            p32[r_lo * PSTR + cu] = *(unsigned*)&p0;
            p32[r_hi * PSTR + cu] = *(unsigned*)&p1;
        }
        __syncthreads();

        // ---- O = P @ V ----
        float o[4][4];
        #pragma unroll
        for (int ni = 0; ni < 4; ni++)
            #pragma unroll
            for (int r = 0; r < 4; r++) o[ni][r] = 0.f;

        #pragma unroll
        for (int kt = 0; kt < 23; kt++) {
            const unsigned* ab = &p32[r_lo * PSTR + kt * 8 + t];
            unsigned a0 = ab[0], a1 = ab[8 * PSTR], a2 = ab[4], a3 = ab[8 * PSTR + 4];
            #pragma unroll
            for (int ni = 0; ni < 4; ni++) {
                const unsigned* bb = &vt32[(wk * 32 + ni * 8 + g) * PSTR + kt * 8 + t];
                unsigned b0 = bb[0], b1 = bb[4];
                BMMA(o[ni], a0, a1, a2, a3, b0, b1);
            }
        }

        #pragma unroll
        for (int ni = 0; ni < 4; ni++) {
            int col = wk * 32 + ni * 8 + t * 2;
            if (qbase + r_lo < SEQ) {
                size_t ob = ((size_t)(b * SEQ + qbase + r_lo)) * D + head * DK + col;
                *(bf162*)(g_ctxb + ob) = __floats2bfloat162_rn(o[ni][0], o[ni][1]);
            }
            if (qbase + r_hi < SEQ) {
                size_t ob = ((size_t)(b * SEQ + qbase + r_hi)) * D + head * DK + col;
                *(bf162*)(g_ctxb + ob) = __floats2bfloat162_rn(o[ni][2], o[ni][3]);
            }
        }
    }
}

// ---------------- classifier (warp per pair, wl in smem) ------------------
__global__ __launch_bounds__(256)
void cls_kernel(const int* __restrict__ src,
                const float* __restrict__ wl,
                const float* __restrict__ bl,
                float* __restrict__ out) {
    __shared__ float swl[6144];                 // 8*256*3
    int tid = threadIdx.x;
    #pragma unroll
    for (int u = 0; u < 24; u++) swl[u * 256 + tid] = wl[u * 256 + tid];
    __syncthreads();

    int w = tid >> 5, lane = tid & 31;
    int bp = blockIdx.x * 8 + w;                // exact: 23296 = 2912*8
    int b = bp / NPAIR, p = bp - b * NPAIR;

    int i = 0, rem = p;
    while (rem >= 13 - i) { rem -= 13 - i; i++; }
    int j = i + 1 + rem;
    int base = i * 12 - (i * (i - 1)) / 2;
    int pe = base + (j - i) - 1;
    int eb = 28 + 2 * pe;
    int gidx[8] = {2*i, 2*i+1, 2*j, 2*j+1, eb, eb+1, eb+2, eb+3};

    const float* xb = g_x + (size_t)(b * SEQ) * D;
    int slots = (j < 13) ? 8 : 4;

    float a0 = 0.f, a1 = 0.f, a2 = 0.f;
    for (int sl = 0; sl < slots; sl++) {
        const float* xr = xb + gidx[sl] * D;
        const float* wr = swl + sl * 768;
        #pragma unroll
        for (int dd = 0; dd < 8; dd++) {
            int dim = lane + dd * 32;
            float xv = xr[dim];
            a0 = fmaf(xv, wr[dim * 3 + 0], a0);
            a1 = fmaf(xv, wr[dim * 3 + 1], a1);
            a2 = fmaf(xv, wr[dim * 3 + 2], a2);
        }
    }
    a0 = warp_sum(a0); a1 = warp_sum(a1); a2 = warp_sum(a2);

    if (lane == 0) {
        const int* sb = src + b * SEQ;
        int ti = sb[2*i], ai = sb[2*i+1], tj = sb[2*j], aj = sb[2*j+1];
        bool c1 = (ai == 2) || (aj == 2);
        bool c2 = (tj == 1) || (ai == 1) || (aj == 1);
        bool c3 = (ti == PADTOK) || (tj == PADTOK) || (ai == 0) || (aj == 0);
        bool c4 = false;
        if (j < 13) {
            int es = 28 + 4 * pe;              // EIDX base: 4*pe (not 2*pe)
            c4 = (sb[es] == 1) || (sb[es+1] == 1) || (sb[es+2] == 1) || (sb[es+3] == 1);
        }
        bool m111 = c3 || c4;
        bool mk1 = m111 || c2;
        bool mk2 = mk1 || c1;
        float* o = out + (size_t)bp * 3;
        o[0] = m111 ? -1e9f : (a0 + bl[0]);
        o[1] = mk1  ? -1e9f : (a1 + bl[1]);
        o[2] = mk2  ? -1e9f : (a2 + bl[2]);
    }
}

// ---------------- launch ----------------
extern "C" void kernel_launch(void* const* d_in, const int* in_sizes, int n_in,
                              void* d_out, int out_size) {
    (void)in_sizes; (void)n_in; (void)out_size;
    const int*   src = (const int*)  d_in[0];
    const float* emb = (const float*)d_in[1];
    const float* wq  = (const float*)d_in[2];
    const float* bq  = (const float*)d_in[3];
    const float* wk  = (const float*)d_in[4];
    const float* bk  = (const float*)d_in[5];
    const float* wv  = (const float*)d_in[6];
    const float* bv  = (const float*)d_in[7];
    const float* wo  = (const float*)d_in[8];
    const float* bo  = (const float*)d_in[9];
    const float* n1a = (const float*)d_in[10];
    const float* n1b = (const float*)d_in[11];
    const float* n2a = (const float*)d_in[12];
    const float* n2b = (const float*)d_in[13];
    const float* w1  = (const float*)d_in[14];
    const float* b1  = (const float*)d_in[15];
    const float* w2  = (const float*)d_in[16];
    const float* b2  = (const float*)d_in[17];
    const float* wl  = (const float*)d_in[18];
    const float* bl  = (const float*)d_in[19];
    float* out = (float*)d_out;

    float *px, *pbqkv;
    bf16 *pxb, *pqb, *pkb, *pvb, *pctxb, *phb, *pwqkvT, *pwoT, *pw1T, *pw2T;
    cudaGetSymbolAddress((void**)&px,     g_x);
    cudaGetSymbolAddress((void**)&pxb,    g_xb);
    cudaGetSymbolAddress((void**)&pqb,    g_qb);
    cudaGetSymbolAddress((void**)&pkb,    g_kb);
    cudaGetSymbolAddress((void**)&pvb,    g_vb);
    cudaGetSymbolAddress((void**)&pctxb,  g_ctxb);
    cudaGetSymbolAddress((void**)&phb,    g_hb);
    cudaGetSymbolAddress((void**)&pwqkvT, g_wqkvT);
    cudaGetSymbolAddress((void**)&pwoT,   g_woT);
    cudaGetSymbolAddress((void**)&pw1T,   g_w1T);
    cudaGetSymbolAddress((void**)&pw2T,   g_w2T);
    cudaGetSymbolAddress((void**)&pbqkv,  g_bqkv);

    cudaFuncSetAttribute(fattn_kernel, cudaFuncAttributeMaxDynamicSharedMemorySize,
                         (int)ATT_SMEM);
    cudaFuncSetAttribute(bgemm_kernel<0>, cudaFuncAttributeMaxDynamicSharedMemorySize, GEMM_SMEM);
    cudaFuncSetAttribute(bgemm_kernel<1>, cudaFuncAttributeMaxDynamicSharedMemorySize, GEMM_SMEM);
    cudaFuncSetAttribute(bgemm_kernel<2>, cudaFuncAttributeMaxDynamicSharedMemorySize, GEMM_SMEM);
    cudaFuncSetAttribute(bgemm_kernel<3>, cudaFuncAttributeMaxDynamicSharedMemorySize, GEMM_SMEM);

    convall_kernel<<<5120, 256>>>(wq, wk, wv, wo, w1, w2);            // 0
    pack_bias_kernel<<<1, 768>>>(bq, bk, bv);                         // 1
    pe_kernel<<<PREFIX, D>>>();                                       // 2
    embed_ln_kernel<<<TOKENS/8, 256>>>(src, emb, n1a, n1b);           // 3

    dim3 gqkv(3, TOKENS / 128);
    bgemm_kernel<0><<<gqkv, 256, GEMM_SMEM>>>(pxb, pwqkvT, pbqkv, nullptr,
                                              pqb, pkb, pvb, TOKENS, 768, D);   // 4

    fattn_kernel<<<HEADS, 256, ATT_SMEM>>>(src);                      // 5

    dim3 g256(1, TOKENS / 128);
    bgemm_kernel<1><<<g256, 256, GEMM_SMEM>>>(pctxb, pwoT, bo, px,
                                              px, nullptr, nullptr, TOKENS, D, D);   // 6

    ln_kernel<<<TOKENS/8, 256>>>(n2a, n2b);                           // 7

    dim3 gff1(8, TOKENS / 128);
    bgemm_kernel<2><<<gff1, 256, GEMM_SMEM>>>(pxb, pw1T, b1, nullptr,
                                              phb, nullptr, nullptr, TOKENS, DFF, D); // 8
    bgemm_kernel<3><<<g256, 256, GEMM_SMEM>>>(phb, pw2T, b2, px,
                                              px, nullptr, nullptr, TOKENS, D, DFF);  // 9

    cls_kernel<<<(BATCH * NPAIR) / 8, 256>>>(src, wl, bl, out);       // 10
}

// round 13
// speedup vs baseline: 8.0967x; 1.5176x over previous
#include <cuda_runtime.h>
#include <cuda_bf16.h>
#include <math.h>

// ---------------- problem constants ----------------
#define BATCH   256
#define SEQ     360
#define PREFIX  340
#define D       256
#define H       4
#define DK      64
#define DFF     2048
#define NPAIR   91
#define PADTOK  799
#define TOKENS  (BATCH*SEQ)          // 92160
#define HEADS   (BATCH*H)            // 1024
#define HSTRIDE (SEQ*DK)             // 23040 (full K/V head stride)
#define S2      192                  // compact tokens per sequence (only 0..185 used)
#define M2      (BATCH*S2)           // 49152
#define HST2    (S2*DK)              // 12288 (compact Q head stride)

typedef __nv_bfloat16 bf16;
typedef __nv_bfloat162 bf162;

// ---------------- scratch (device globals) ----------------
__device__ float g_xc [M2*D];           // residual after embed (compact, fp32)
__device__ bf16  g_xb [TOKENS*D];       // LN1 output (full, bf16) -> QKV input
__device__ bf16  g_qb [M2*D];           // Q (B,H,192,64) bf16
__device__ bf16  g_kb [TOKENS*D];       // K (B,H,360,64) bf16
__device__ bf16  g_vb [TOKENS*D];       // V (B,H,360,64) bf16
__device__ bf16  g_ctxb[M2*D];          // attention output (compact, bf16)
__device__ float g_y  [M2*D];           // residual after WO (compact, fp32)
__device__ bf16  g_x2b[M2*D];           // LN2 output (compact, bf16)
__device__ bf16  g_hb [M2*DFF];         // ffn hidden (compact, bf16)
__device__ float g_xf [M2*D];           // final x (compact, fp32)
__device__ float g_pe [PREFIX*D];       // positional encodings
// transposed bf16 weights [N][K]
__device__ bf16  g_wqkvT[3*D*D];        // q (x0.125) | k | v
__device__ bf16  g_woT[D*D];
__device__ bf16  g_w1T[D*DFF];
__device__ bf16  g_w2T[D*DFF];
__device__ float g_bqkv[3*D];           // bq*0.125 | bk | bv

// ---------------- helpers ----------------
__device__ __forceinline__ float warp_sum(float v) {
    #pragma unroll
    for (int o = 16; o; o >>= 1) v += __shfl_xor_sync(0xffffffffu, v, o);
    return v;
}

#define BMMA(c, a0, a1, a2, a3, b0, b1)                                        \
    asm volatile(                                                              \
        "mma.sync.aligned.m16n8k16.row.col.f32.bf16.bf16.f32 "                 \
        "{%0,%1,%2,%3}, {%4,%5,%6,%7}, {%8,%9}, {%0,%1,%2,%3};"                \
        : "+f"(c[0]), "+f"(c[1]), "+f"(c[2]), "+f"(c[3])                       \
        : "r"(a0), "r"(a1), "r"(a2), "r"(a3), "r"(b0), "r"(b1))

__device__ __forceinline__ void ldsm4(unsigned &r0, unsigned &r1,
                                      unsigned &r2, unsigned &r3, unsigned addr) {
    asm volatile("ldmatrix.sync.aligned.m8n8.x4.shared.b16 {%0,%1,%2,%3}, [%4];"
        : "=r"(r0), "=r"(r1), "=r"(r2), "=r"(r3) : "r"(addr));
}
__device__ __forceinline__ void cpasync16(void* sdst, const void* gsrc) {
    unsigned s = (unsigned)__cvta_generic_to_shared(sdst);
    asm volatile("cp.async.cg.shared.global [%0], [%1], 16;" :: "r"(s), "l"(gsrc));
}

// ---------------- PE table (fp32; abs err ~3e-5, tolerance 1e-3) ----------
__global__ void pe_kernel() {
    int s = blockIdx.x, d = threadIdx.x;
    float ex  = exp2f(-13.287712379549449f * ((float)d) * (1.0f / 128.0f));
    float arg = (float)s * ex;
    g_pe[s * D + d] = (d & 1) ? cosf(arg) : sinf(arg);
}

// ---------------- all weight transposes + bf16 convert (one kernel) -------
__global__ void convall_kernel(const float* __restrict__ wq, const float* __restrict__ wk,
                               const float* __restrict__ wv, const float* __restrict__ wo,
                               const float* __restrict__ w1, const float* __restrict__ w2) {
    int bid = blockIdx.x, tid = threadIdx.x;
    if (bid < 1024) {
        int m = bid >> 8;
        int idx = ((bid & 255) << 8) + tid;
        int k = idx >> 8, n = idx & 255;
        if (m == 0)      g_wqkvT[n * 256 + k]           = __float2bfloat16(wq[idx] * 0.125f);
        else if (m == 1) g_wqkvT[65536 + n * 256 + k]   = __float2bfloat16(wk[idx]);
        else if (m == 2) g_wqkvT[131072 + n * 256 + k]  = __float2bfloat16(wv[idx]);
        else             g_woT[n * 256 + k]             = __float2bfloat16(wo[idx]);
    } else if (bid < 3072) {
        int idx = (bid - 1024) * 256 + tid;
        int k = idx >> 11, n = idx & 2047;
        g_w1T[n * 256 + k] = __float2bfloat16(w1[idx]);
    } else {
        int idx = (bid - 3072) * 256 + tid;
        int k = idx >> 8, n = idx & 255;
        g_w2T[(size_t)n * 2048 + k] = __float2bfloat16(w2[idx]);
    }
}
__global__ void pack_bias_kernel(const float* __restrict__ bq,
                                 const float* __restrict__ bk,
                                 const float* __restrict__ bv) {
    int i = threadIdx.x;
    if (i < 256)      g_bqkv[i] = bq[i] * 0.125f;
    else if (i < 512) g_bqkv[i] = bk[i - 256];
    else              g_bqkv[i] = bv[i - 512];
}

// ---------------- fused embedding + scale + PE + LN1 (warp per token) -----
// writes g_xb (bf16, full) and g_xc (fp32, compact, only s<192)
__global__ void embed_ln_kernel(const int* __restrict__ src,
                                const float* __restrict__ emb,
                                const float* __restrict__ ga,
                                const float* __restrict__ gb) {
    int w = threadIdx.x >> 5, lane = threadIdx.x & 31;
    int t = blockIdx.x * 8 + w;
    int tok = src[t];
    int b = t / SEQ;
    int s = t - b * SEQ;
    const float4* er = (const float4*)(emb + (size_t)tok * D);
    float4 a = er[lane * 2], bb = er[lane * 2 + 1];
    if (s < PREFIX) {
        const float4* pr = (const float4*)(g_pe + s * D);
        float4 p = pr[lane * 2], q = pr[lane * 2 + 1];
        a.x = fmaf(a.x, 16.f, p.x); a.y = fmaf(a.y, 16.f, p.y);
        a.z = fmaf(a.z, 16.f, p.z); a.w = fmaf(a.w, 16.f, p.w);
        bb.x = fmaf(bb.x, 16.f, q.x); bb.y = fmaf(bb.y, 16.f, q.y);
        bb.z = fmaf(bb.z, 16.f, q.z); bb.w = fmaf(bb.w, 16.f, q.w);
    }
    if (s < S2) {
        size_t co = ((size_t)(b * S2 + s)) * D + lane * 8;
        *(float4*)(g_xc + co)     = a;
        *(float4*)(g_xc + co + 4) = bb;
    }

    float sum = a.x + a.y + a.z + a.w + bb.x + bb.y + bb.z + bb.w;
    float mu = warp_sum(sum) * (1.0f / 256.0f);
    float dx[8] = {a.x - mu, a.y - mu, a.z - mu, a.w - mu,
                   bb.x - mu, bb.y - mu, bb.z - mu, bb.w - mu};
    float ss = 0.f;
    #pragma unroll
    for (int i = 0; i < 8; i++) ss = fmaf(dx[i], dx[i], ss);
    float inv = 1.0f / (sqrtf(warp_sum(ss) * (1.0f / 255.0f)) + 1e-6f);

    const float4* gav = (const float4*)(ga + lane * 8);
    const float4* gbv = (const float4*)(gb + lane * 8);
    float4 g0 = gav[0], g1 = gav[1], h0 = gbv[0], h1 = gbv[1];
    bf162 o[4];
    o[0] = __floats2bfloat162_rn(fmaf(g0.x, dx[0]*inv, h0.x), fmaf(g0.y, dx[1]*inv, h0.y));
    o[1] = __floats2bfloat162_rn(fmaf(g0.z, dx[2]*inv, h0.z), fmaf(g0.w, dx[3]*inv, h0.w));
    o[2] = __floats2bfloat162_rn(fmaf(g1.x, dx[4]*inv, h1.x), fmaf(g1.y, dx[5]*inv, h1.y));
    o[3] = __floats2bfloat162_rn(fmaf(g1.z, dx[6]*inv, h1.z), fmaf(g1.w, dx[7]*inv, h1.w));
    *(uint4*)(g_xb + (size_t)t * D + lane * 8) = *(uint4*)o;
}

// ---------------- bf16 tensor-core GEMM (128x256 CTA, warp 64x64) --------
// EPI 0: KV   -> bf16 into Cv0/Cv1 (k/v) at (B,H,360,DK), +bias (N=512)
// EPI 4: Q    -> bf16 into Cv0 at (B,H,192,DK), +bias; A rows remapped compact->full
// EPI 1: WO   -> fp32 Cv0 = res+acc+bias (g_y); fused LN2 -> bf16 Cv1 (g_x2b)
// EPI 2: FFN1 -> bf16 Cv0 = relu(acc+bias)
// EPI 3: FFN2 -> fp32 Cv0 = res+acc+bias
#define KT 64
#define BSTRH 72
#define A_STG (128*BSTRH)
#define B_STG (256*BSTRH)
#define GEMM_SMEM ((2*A_STG + 2*B_STG) * 2)   // 110592 bytes

template<int EPI>
__global__ __launch_bounds__(256)
void bgemm_kernel(const bf16* __restrict__ A, const bf16* __restrict__ Wt,
                  const float* __restrict__ bias, const float* __restrict__ res,
                  void* __restrict__ Cv0, void* __restrict__ Cv1,
                  const float* __restrict__ lnga, const float* __restrict__ lngb,
                  int M, int N, int K) {
    extern __shared__ bf16 smem[];
    const unsigned SMU = (unsigned)__cvta_generic_to_shared(smem);

    const int tid  = threadIdx.x;
    const int lane = tid & 31;
    const int wid  = tid >> 5;
    const int wm = wid >> 2;
    const int wn = wid & 3;
    const int g = lane >> 2;
    const int t = lane & 3;

    const int bm = blockIdx.y * 128;
    const int bn = blockIdx.x * 256;

    const int arow  = tid >> 1;
    const int ahalf = (tid & 1) * 32;
    int garow = bm + arow;
    if (EPI == 4) { int bb = garow / S2; garow = bb * SEQ + (garow - bb * S2); }
    const bf16* Ap = A  + (size_t)garow * K + ahalf;
    const bf16* Bp = Wt + (size_t)(bn + tid) * K;
    bf16* sA = smem;
    bf16* sB = smem + 2 * A_STG;

    const int a_r = lane & 15;
    const int a_c = ((lane >> 4) & 1) * 8;
    const int b_n = (lane & 7) + ((lane >> 4) & 1) * 8;
    const int b_c = ((lane >> 3) & 1) * 8;

    float acc[4][8][4];
    #pragma unroll
    for (int mi = 0; mi < 4; mi++)
        #pragma unroll
        for (int ni = 0; ni < 8; ni++)
            #pragma unroll
            for (int r = 0; r < 4; r++) acc[mi][ni][r] = 0.f;

    const int nt = K >> 6;
    {
        bf16* ad = sA + arow * BSTRH + ahalf;
        #pragma unroll
        for (int c = 0; c < 4; c++) cpasync16(ad + c * 8, Ap + c * 8);
        bf16* bd = sB + tid * BSTRH;
        #pragma unroll
        for (int c = 0; c < 8; c++) cpasync16(bd + c * 8, Bp + c * 8);
    }
    asm volatile("cp.async.commit_group;");

    for (int tl = 0; tl < nt; tl++) {
        const int cur = tl & 1;
        if (tl + 1 < nt) {
            const int nxt = cur ^ 1;
            bf16* ad = sA + nxt * A_STG + arow * BSTRH + ahalf;
            const bf16* ap = Ap + (tl + 1) * KT;
            #pragma unroll
            for (int c = 0; c < 4; c++) cpasync16(ad + c * 8, ap + c * 8);
            bf16* bd = sB + nxt * B_STG + tid * BSTRH;
            const bf16* bp = Bp + (tl + 1) * KT;
            #pragma unroll
            for (int c = 0; c < 8; c++) cpasync16(bd + c * 8, bp + c * 8);
            asm volatile("cp.async.commit_group;");
            asm volatile("cp.async.wait_group 1;" ::: "memory");
        } else {
            asm volatile("cp.async.wait_group 0;" ::: "memory");
        }
        __syncthreads();

        const unsigned abase = SMU + cur * (A_STG * 2);
        const unsigned bbase = SMU + 2 * (A_STG * 2) + cur * (B_STG * 2);
        #pragma unroll
        for (int kk = 0; kk < 4; kk++) {
            unsigned af[4][4], bfr[4][4];
            #pragma unroll
            for (int mi = 0; mi < 4; mi++) {
                unsigned addr = abase +
                    ((unsigned)((wm * 64 + mi * 16 + a_r) * BSTRH + kk * 16 + a_c) << 1);
                ldsm4(af[mi][0], af[mi][1], af[mi][2], af[mi][3], addr);
            }
            #pragma unroll
            for (int p = 0; p < 4; p++) {
                unsigned addr = bbase +
                    ((unsigned)((wn * 64 + p * 16 + b_n) * BSTRH + kk * 16 + b_c) << 1);
                ldsm4(bfr[p][0], bfr[p][1], bfr[p][2], bfr[p][3], addr);
            }
            #pragma unroll
            for (int mi = 0; mi < 4; mi++)
                #pragma unroll
                for (int ni = 0; ni < 8; ni++)
                    BMMA(acc[mi][ni], af[mi][0], af[mi][1], af[mi][2], af[mi][3],
                         bfr[ni >> 1][(ni & 1) * 2], bfr[ni >> 1][(ni & 1) * 2 + 1]);
        }
        __syncthreads();
    }

    // ------------- epilogues -------------
    if (EPI == 0 || EPI == 4) {
        // scatter into (B,H,S,DK)
        bf16* Cb = (bf16*)Cv0;
        if (EPI == 0 && blockIdx.x == 1) Cb = (bf16*)Cv1;
        const int sdim = (EPI == 0) ? SEQ : S2;
        const int hst  = (EPI == 0) ? HSTRIDE : HST2;
        #pragma unroll
        for (int mi = 0; mi < 4; mi++) {
            int row0 = bm + wm * 64 + mi * 16 + g;
            #pragma unroll
            for (int ni = 0; ni < 8; ni++) {
                int col = bn + wn * 64 + ni * 8 + t * 2;
                float2 bb = *(const float2*)(bias + col);
                #pragma unroll
                for (int half = 0; half < 2; half++) {
                    int row = row0 + half * 8;
                    float v0 = acc[mi][ni][half * 2 + 0] + bb.x;
                    float v1 = acc[mi][ni][half * 2 + 1] + bb.y;
                    int ic = col & 255;
                    int bbt = row / sdim;
                    int s   = row - bbt * sdim;
                    bf16* cb = Cb + (size_t)bbt * (H * hst) + (ic >> 6) * hst
                                  + s * DK + (ic & 63);
                    *(bf162*)cb = __floats2bfloat162_rn(v0, v1);
                }
            }
        }
    } else if (EPI == 1) {
        // WO residual + fused LN2. gridDim.x == 1 (CTA owns full rows).
        float* Y  = (float*)Cv0;
        bf16*  X2 = (bf16*)Cv1;
        float* rsum = (float*)smem;          // 128
        float* rss  = rsum + 128;            // 128
        if (tid < 128) { rsum[tid] = 0.f; rss[tid] = 0.f; }
        __syncthreads();

        #pragma unroll
        for (int mi = 0; mi < 4; mi++) {
            #pragma unroll
            for (int half = 0; half < 2; half++) {
                int lrow = wm * 64 + mi * 16 + g + half * 8;
                size_t ro = (size_t)(bm + lrow) * 256;
                float s = 0.f, sq = 0.f;
                #pragma unroll
                for (int ni = 0; ni < 8; ni++) {
                    int col = wn * 64 + ni * 8 + t * 2;
                    float2 bb = *(const float2*)(bias + col);
                    float2 rv = *(const float2*)(res + ro + col);
                    float v0 = acc[mi][ni][half * 2 + 0] + bb.x + rv.x;
                    float v1 = acc[mi][ni][half * 2 + 1] + bb.y + rv.y;
                    acc[mi][ni][half * 2 + 0] = v0;
                    acc[mi][ni][half * 2 + 1] = v1;
                    *(float2*)(Y + ro + col) = make_float2(v0, v1);
                    s += v0 + v1;
                    sq = fmaf(v0, v0, fmaf(v1, v1, sq));
                }
                s  += __shfl_xor_sync(0xffffffffu, s, 1);
                s  += __shfl_xor_sync(0xffffffffu, s, 2);
                sq += __shfl_xor_sync(0xffffffffu, sq, 1);
                sq += __shfl_xor_sync(0xffffffffu, sq, 2);
                if (t == 0) { atomicAdd(&rsum[lrow], s); atomicAdd(&rss[lrow], sq); }
            }
        }
        __syncthreads();

        #pragma unroll
        for (int mi = 0; mi < 4; mi++) {
            #pragma unroll
            for (int half = 0; half < 2; half++) {
                int lrow = wm * 64 + mi * 16 + g + half * 8;
                size_t ro = (size_t)(bm + lrow) * 256;
                float mu  = rsum[lrow] * (1.0f / 256.0f);
                float var = (rss[lrow] - 256.0f * mu * mu) * (1.0f / 255.0f);
                float inv = 1.0f / (sqrtf(var) + 1e-6f);
                #pragma unroll
                for (int ni = 0; ni < 8; ni++) {
                    int col = wn * 64 + ni * 8 + t * 2;
                    float2 ga2 = *(const float2*)(lnga + col);
                    float2 gb2 = *(const float2*)(lngb + col);
                    float v0 = acc[mi][ni][half * 2 + 0];
                    float v1 = acc[mi][ni][half * 2 + 1];
                    bf162 o = __floats2bfloat162_rn(
                        fmaf(ga2.x, (v0 - mu) * inv, gb2.x),
                        fmaf(ga2.y, (v1 - mu) * inv, gb2.y));
                    *(bf162*)(X2 + ro + col) = o;
                }
            }
        }
    } else {
        float* C  = (float*)Cv0;
        bf16*  Cb = (bf16*)Cv0;
        #pragma unroll
        for (int mi = 0; mi < 4; mi++) {
            int row0 = bm + wm * 64 + mi * 16 + g;
            #pragma unroll
            for (int ni = 0; ni < 8; ni++) {
                int col = bn + wn * 64 + ni * 8 + t * 2;
                float2 bb = *(const float2*)(bias + col);
                #pragma unroll
                for (int half = 0; half < 2; half++) {
                    int row = row0 + half * 8;
                    float v0 = acc[mi][ni][half * 2 + 0] + bb.x;
                    float v1 = acc[mi][ni][half * 2 + 1] + bb.y;
                    if (EPI == 2) {
                        *(bf162*)(Cb + (size_t)row * N + col) =
                            __floats2bfloat162_rn(fmaxf(v0, 0.f), fmaxf(v1, 0.f));
                    } else {
                        size_t ro = (size_t)row * N + col;
                        float2 rv = *(const float2*)(res + ro);
                        *(float2*)(C + ro) = make_float2(rv.x + v0, rv.y + v1);
                    }
                }
            }
        }
    }
}

// ---------------- tensor-core attention (block per head, 3 qt tiles) ------
#define QSTR 36
#define PSTR 188
#define ATT_SMEM ((64*QSTR + 368*QSTR + 64*PSTR + 64*PSTR) * 4 + 256 * 4)

__global__ __launch_bounds__(256, 1)
void fattn_kernel(const int* __restrict__ src) {
    extern __shared__ unsigned sm32[];
    unsigned* q32  = sm32;
    unsigned* k32  = q32  + 64 * QSTR;
    unsigned* vt32 = k32  + 368 * QSTR;
    unsigned* p32  = vt32 + 64 * PSTR;
    float* redm = (float*)(p32 + 64 * PSTR);
    float* reds = redm + 128;

    const int bh = blockIdx.x;
    const int b  = bh >> 2;
    const size_t hb = (size_t)bh * HSTRIDE;
    const int tid = threadIdx.x;

    const uint4* gk = (const uint4*)(g_kb + hb);
    for (int u = tid; u < 2880; u += 256) {
        int row = u >> 3, c8 = u & 7;
        *(uint4*)&k32[row * QSTR + c8 * 4] = gk[u];
    }
    const bf16* gv = g_vb + hb;
    bf16* vt = (bf16*)vt32;
    for (int i = tid; i < SEQ * DK; i += 256) {
        int key = i >> 6, dk = i & 63;
        vt[dk * 376 + key] = gv[i];
    }
    for (int i = tid; i < 64 * 16; i += 256) {
        int dk = i >> 4, key = 360 + (i & 15);
        vt[dk * 376 + key] = __float2bfloat16(0.f);
    }

    const int lane = tid & 31, wid = tid >> 5;
    const int wq = wid >> 1;
    const int wk = wid & 1;
    const int g = lane >> 2, t = lane & 3;
    const int kb = wk * 184;
    const int r_lo = wq * 16 + g, r_hi = r_lo + 8;
    const int head = bh & 3;
    const uint4* gq = (const uint4*)(g_qb + (size_t)bh * HST2);

    for (int qt = 0; qt < 3; qt++) {
        const int qbase = qt * 64;

        #pragma unroll
        for (int u = tid; u < 512; u += 256) {
            int row = u >> 3, c8 = u & 7;
            *(uint4*)&q32[row * QSTR + c8 * 4] = gq[(qbase + row) * 8 + c8];
        }
        __syncthreads();

        float acc[23][4];
        #pragma unroll
        for (int ni = 0; ni < 23; ni++)
            #pragma unroll
            for (int r = 0; r < 4; r++) acc[ni][r] = 0.f;

        #pragma unroll
        for (int kt = 0; kt < 4; kt++) {
            const unsigned* ab = &q32[r_lo * QSTR + kt * 8 + t];
            unsigned a0 = ab[0], a1 = ab[8 * QSTR], a2 = ab[4], a3 = ab[8 * QSTR + 4];
            #pragma unroll
            for (int ni = 0; ni < 23; ni++) {
                const unsigned* bb = &k32[(kb + ni * 8 + g) * QSTR + kt * 8 + t];
                unsigned b0 = bb[0], b1 = bb[4];
                BMMA(acc[ni], a0, a1, a2, a3, b0, b1);
            }
        }

        bool v_lo = (src[b * SEQ + qbase + r_lo] != PADTOK);
        bool v_hi = (src[b * SEQ + qbase + r_hi] != PADTOK);

        float m_lo = -1e30f, m_hi = -1e30f;
        #pragma unroll
        for (int ni = 0; ni < 23; ni++) {
            int col0 = kb + ni * 8 + t * 2;
            bool in0 = col0 < SEQ, in1 = col0 + 1 < SEQ;
            acc[ni][0] = in0 ? (v_lo ? acc[ni][0] : 0.f) : -1e30f;
            acc[ni][1] = in1 ? (v_lo ? acc[ni][1] : 0.f) : -1e30f;
            acc[ni][2] = in0 ? (v_hi ? acc[ni][2] : 0.f) : -1e30f;
            acc[ni][3] = in1 ? (v_hi ? acc[ni][3] : 0.f) : -1e30f;
            m_lo = fmaxf(m_lo, fmaxf(acc[ni][0], acc[ni][1]));
            m_hi = fmaxf(m_hi, fmaxf(acc[ni][2], acc[ni][3]));
        }
        m_lo = fmaxf(m_lo, __shfl_xor_sync(0xffffffffu, m_lo, 1));
        m_lo = fmaxf(m_lo, __shfl_xor_sync(0xffffffffu, m_lo, 2));
        m_hi = fmaxf(m_hi, __shfl_xor_sync(0xffffffffu, m_hi, 1));
        m_hi = fmaxf(m_hi, __shfl_xor_sync(0xffffffffu, m_hi, 2));
        if (t == 0) { redm[wk * 64 + r_lo] = m_lo; redm[wk * 64 + r_hi] = m_hi; }
        __syncthreads();
        m_lo = fmaxf(redm[r_lo], redm[64 + r_lo]);
        m_hi = fmaxf(redm[r_hi], redm[64 + r_hi]);

        float s_lo = 0.f, s_hi = 0.f;
        #pragma unroll
        for (int ni = 0; ni < 23; ni++) {
            acc[ni][0] = __expf(acc[ni][0] - m_lo);
            acc[ni][1] = __expf(acc[ni][1] - m_lo);
            acc[ni][2] = __expf(acc[ni][2] - m_hi);
            acc[ni][3] = __expf(acc[ni][3] - m_hi);
            s_lo += acc[ni][0] + acc[ni][1];
            s_hi += acc[ni][2] + acc[ni][3];
        }
        s_lo += __shfl_xor_sync(0xffffffffu, s_lo, 1);
        s_lo += __shfl_xor_sync(0xffffffffu, s_lo, 2);
        s_hi += __shfl_xor_sync(0xffffffffu, s_hi, 1);
        s_hi += __shfl_xor_sync(0xffffffffu, s_hi, 2);
        if (t == 0) { reds[wk * 64 + r_lo] = s_lo; reds[wk * 64 + r_hi] = s_hi; }
        __syncthreads();
        float inv_lo = 1.f / (reds[r_lo] + reds[64 + r_lo]);
        float inv_hi = 1.f / (reds[r_hi] + reds[64 + r_hi]);

        #pragma unroll
        for (int ni = 0; ni < 23; ni++) {
            int cu = (kb >> 1) + ni * 4 + t;
            bf162 p0 = __floats2bfloat162_rn(acc[ni][0] * inv_lo, acc[ni][1] * inv_lo);
            bf162 p1 = __floats2bfloat162_rn(acc[ni][2] * inv_hi, acc[ni][3] * inv_hi);
            p32[r_lo * PSTR + cu] = *(unsigned*)&p0;
            p32[r_hi * PSTR + cu] = *(unsigned*)&p1;
        }
        __syncthreads();

        float o[4][4];
        #pragma unroll
        for (int ni = 0; ni < 4; ni++)
            #pragma unroll
            for (int r = 0; r < 4; r++) o[ni][r] = 0.f;

        #pragma unroll
        for (int kt = 0; kt < 23; kt++) {
            const unsigned* ab = &p32[r_lo * PSTR + kt * 8 + t];
            unsigned a0 = ab[0], a1 = ab[8 * PSTR], a2 = ab[4], a3 = ab[8 * PSTR + 4];
            #pragma unroll
            for (int ni = 0; ni < 4; ni++) {
                const unsigned* bb = &vt32[(wk * 32 + ni * 8 + g) * PSTR + kt * 8 + t];
                unsigned b0 = bb[0], b1 = bb[4];
                BMMA(o[ni], a0, a1, a2, a3, b0, b1);
            }
        }

        #pragma unroll
        for (int ni = 0; ni < 4; ni++) {
            int col = wk * 32 + ni * 8 + t * 2;
            size_t ob0 = ((size_t)(b * S2 + qbase + r_lo)) * D + head * DK + col;
            size_t ob1 = ((size_t)(b * S2 + qbase + r_hi)) * D + head * DK + col;
            *(bf162*)(g_ctxb + ob0) = __floats2bfloat162_rn(o[ni][0], o[ni][1]);
            *(bf162*)(g_ctxb + ob1) = __floats2bfloat162_rn(o[ni][2], o[ni][3]);
        }
    }
}

// ---------------- classifier (warp per pair, wl in smem) ------------------
__global__ __launch_bounds__(256)
void cls_kernel(const int* __restrict__ src,
                const float* __restrict__ wl,
                const float* __restrict__ bl,
                float* __restrict__ out) {
    __shared__ float swl[6144];
    int tid = threadIdx.x;
    #pragma unroll
    for (int u = 0; u < 24; u++) swl[u * 256 + tid] = wl[u * 256 + tid];
    __syncthreads();

    int w = tid >> 5, lane = tid & 31;
    int bp = blockIdx.x * 8 + w;
    int b = bp / NPAIR, p = bp - b * NPAIR;

    int i = 0, rem = p;
    while (rem >= 13 - i) { rem -= 13 - i; i++; }
    int j = i + 1 + rem;
    int base = i * 12 - (i * (i - 1)) / 2;
    int pe = base + (j - i) - 1;
    int eb = 28 + 2 * pe;
    int gidx[8] = {2*i, 2*i+1, 2*j, 2*j+1, eb, eb+1, eb+2, eb+3};

    const float* xb = g_xf + (size_t)(b * S2) * D;
    int slots = (j < 13) ? 8 : 4;

    float a0 = 0.f, a1 = 0.f, a2 = 0.f;
    for (int sl = 0; sl < slots; sl++) {
        const float* xr = xb + gidx[sl] * D;
        const float* wr = swl + sl * 768;
        #pragma unroll
        for (int dd = 0; dd < 8; dd++) {
            int dim = lane + dd * 32;
            float xv = xr[dim];
            a0 = fmaf(xv, wr[dim * 3 + 0], a0);
            a1 = fmaf(xv, wr[dim * 3 + 1], a1);
            a2 = fmaf(xv, wr[dim * 3 + 2], a2);
        }
    }
    a0 = warp_sum(a0); a1 = warp_sum(a1); a2 = warp_sum(a2);

    if (lane == 0) {
        const int* sb = src + b * SEQ;
        int ti = sb[2*i], ai = sb[2*i+1], tj = sb[2*j], aj = sb[2*j+1];
        bool c1 = (ai == 2) || (aj == 2);
        bool c2 = (tj == 1) || (ai == 1) || (aj == 1);
        bool c3 = (ti == PADTOK) || (tj == PADTOK) || (ai == 0) || (aj == 0);
        bool c4 = false;
        if (j < 13) {
            int es = 28 + 4 * pe;
            c4 = (sb[es] == 1) || (sb[es+1] == 1) || (sb[es+2] == 1) || (sb[es+3] == 1);
        }
        bool m111 = c3 || c4;
        bool mk1 = m111 || c2;
        bool mk2 = mk1 || c1;
        float* o = out + (size_t)bp * 3;
        o[0] = m111 ? -1e9f : (a0 + bl[0]);
        o[1] = mk1  ? -1e9f : (a1 + bl[1]);
        o[2] = mk2  ? -1e9f : (a2 + bl[2]);
    }
}

// ---------------- launch ----------------
extern "C" void kernel_launch(void* const* d_in, const int* in_sizes, int n_in,
                              void* d_out, int out_size) {
    (void)in_sizes; (void)n_in; (void)out_size;
    const int*   src = (const int*)  d_in[0];
    const float* emb = (const float*)d_in[1];
    const float* wq  = (const float*)d_in[2];
    const float* bq  = (const float*)d_in[3];
    const float* wk  = (const float*)d_in[4];
    const float* bk  = (const float*)d_in[5];
    const float* wv  = (const float*)d_in[6];
    const float* bv  = (const float*)d_in[7];
    const float* wo  = (const float*)d_in[8];
    const float* bo  = (const float*)d_in[9];
    const float* n1a = (const float*)d_in[10];
    const float* n1b = (const float*)d_in[11];
    const float* n2a = (const float*)d_in[12];
    const float* n2b = (const float*)d_in[13];
    const float* w1  = (const float*)d_in[14];
    const float* b1  = (const float*)d_in[15];
    const float* w2  = (const float*)d_in[16];
    const float* b2  = (const float*)d_in[17];
    const float* wl  = (const float*)d_in[18];
    const float* bl  = (const float*)d_in[19];
    float* out = (float*)d_out;

    float *pxc, *py, *pxf, *pbqkv;
    bf16 *pxb, *pqb, *pkb, *pvb, *pctxb, *px2b, *phb, *pwqkvT, *pwoT, *pw1T, *pw2T;
    cudaGetSymbolAddress((void**)&pxc,    g_xc);
    cudaGetSymbolAddress((void**)&pxb,    g_xb);
    cudaGetSymbolAddress((void**)&pqb,    g_qb);
    cudaGetSymbolAddress((void**)&pkb,    g_kb);
    cudaGetSymbolAddress((void**)&pvb,    g_vb);
    cudaGetSymbolAddress((void**)&pctxb,  g_ctxb);
    cudaGetSymbolAddress((void**)&py,     g_y);
    cudaGetSymbolAddress((void**)&px2b,   g_x2b);
    cudaGetSymbolAddress((void**)&phb,    g_hb);
    cudaGetSymbolAddress((void**)&pxf,    g_xf);
    cudaGetSymbolAddress((void**)&pwqkvT, g_wqkvT);
    cudaGetSymbolAddress((void**)&pwoT,   g_woT);
    cudaGetSymbolAddress((void**)&pw1T,   g_w1T);
    cudaGetSymbolAddress((void**)&pw2T,   g_w2T);
    cudaGetSymbolAddress((void**)&pbqkv,  g_bqkv);

    cudaFuncSetAttribute(fattn_kernel, cudaFuncAttributeMaxDynamicSharedMemorySize,
                         (int)ATT_SMEM);
    cudaFuncSetAttribute(bgemm_kernel<0>, cudaFuncAttributeMaxDynamicSharedMemorySize, GEMM_SMEM);
    cudaFuncSetAttribute(bgemm_kernel<1>, cudaFuncAttributeMaxDynamicSharedMemorySize, GEMM_SMEM);
    cudaFuncSetAttribute(bgemm_kernel<2>, cudaFuncAttributeMaxDynamicSharedMemorySize, GEMM_SMEM);
    cudaFuncSetAttribute(bgemm_kernel<3>, cudaFuncAttributeMaxDynamicSharedMemorySize, GEMM_SMEM);
    cudaFuncSetAttribute(bgemm_kernel<4>, cudaFuncAttributeMaxDynamicSharedMemorySize, GEMM_SMEM);

    convall_kernel<<<5120, 256>>>(wq, wk, wv, wo, w1, w2);
    pack_bias_kernel<<<1, 768>>>(bq, bk, bv);
    pe_kernel<<<PREFIX, D>>>();
    embed_ln_kernel<<<TOKENS/8, 256>>>(src, emb, n1a, n1b);

    // KV projection (full tokens, N=512)
    dim3 gkv(2, TOKENS / 128);
    bgemm_kernel<0><<<gkv, 256, GEMM_SMEM>>>(pxb, pwqkvT + 65536, pbqkv + 256, nullptr,
                                             pkb, pvb, nullptr, nullptr, TOKENS, 512, D);
    // Q projection (compact tokens, row-remapped A)
    dim3 gq(1, M2 / 128);
    bgemm_kernel<4><<<gq, 256, GEMM_SMEM>>>(pxb, pwqkvT, pbqkv, nullptr,
                                            pqb, nullptr, nullptr, nullptr, M2, 256, D);

    fattn_kernel<<<HEADS, 256, ATT_SMEM>>>(src);

    // WO + residual + fused LN2 (compact)
    bgemm_kernel<1><<<gq, 256, GEMM_SMEM>>>(pctxb, pwoT, bo, pxc,
                                            py, px2b, n2a, n2b, M2, 256, D);

    // FFN (compact)
    dim3 gff1(8, M2 / 128);
    bgemm_kernel<2><<<gff1, 256, GEMM_SMEM>>>(px2b, pw1T, b1, nullptr,
                                              phb, nullptr, nullptr, nullptr, M2, DFF, D);
    bgemm_kernel<3><<<gq, 256, GEMM_SMEM>>>(phb, pw2T, b2, py,
                                            pxf, nullptr, nullptr, nullptr, M2, 256, DFF);

    cls_kernel<<<(BATCH * NPAIR) / 8, 256>>>(src, wl, bl, out);
}

// round 14
// speedup vs baseline: 9.0207x; 1.1141x over previous
#include <cuda_runtime.h>
#include <cuda_bf16.h>
#include <math.h>

// ---------------- problem constants ----------------
#define BATCH   256
#define SEQ     360
#define PREFIX  340
#define D       256
#define H       4
#define DK      64
#define DFF     2048
#define NPAIR   91
#define PADTOK  799
#define TOKENS  (BATCH*SEQ)          // 92160
#define HEADS   (BATCH*H)            // 1024
#define HSTRIDE (SEQ*DK)             // 23040 (full K/V head stride)
#define S2      192                  // compact tokens per sequence (only 0..185 used)
#define M2      (BATCH*S2)           // 49152
#define HST2    (S2*DK)              // 12288 (compact Q head stride)

typedef __nv_bfloat16 bf16;
typedef __nv_bfloat162 bf162;

// ---------------- scratch (device globals) ----------------
__device__ float g_xc [M2*D];           // residual after embed (compact, fp32)
__device__ bf16  g_xb [TOKENS*D];       // LN1 output (full, bf16)
__device__ bf16  g_qb [M2*D];           // Q (B,H,192,64) bf16
__device__ bf16  g_kb [TOKENS*D];       // K (B,H,360,64) bf16
__device__ bf16  g_vb [TOKENS*D];       // V (B,H,360,64) bf16
__device__ bf16  g_ctxb[M2*D];          // attention output (compact, bf16)
__device__ float g_y  [M2*D];           // residual after WO (compact, fp32)
__device__ unsigned char g_x2b8[M2*D];  // LN2 output (compact, fp8 e4m3)
__device__ unsigned char g_hb8[M2*DFF]; // ffn hidden (compact, fp8, x8 scale)
__device__ float g_xf [M2*D];           // final x (compact, fp32)
__device__ float g_pe [PREFIX*D];
__device__ bf16  g_wqkvT[3*D*D];        // q (x0.125) | k | v   [n][k] bf16
__device__ bf16  g_woT[D*D];
__device__ unsigned char g_w1T8[DFF*D]; // [n][k] fp8, x64 scale
__device__ unsigned char g_w2T8[D*DFF]; // [n][k] fp8, x64 scale
__device__ float g_bqkv[3*D];

// ---------------- helpers ----------------
__device__ __forceinline__ float warp_sum(float v) {
    #pragma unroll
    for (int o = 16; o; o >>= 1) v += __shfl_xor_sync(0xffffffffu, v, o);
    return v;
}

#define BMMA(c, a0, a1, a2, a3, b0, b1)                                        \
    asm volatile(                                                              \
        "mma.sync.aligned.m16n8k16.row.col.f32.bf16.bf16.f32 "                 \
        "{%0,%1,%2,%3}, {%4,%5,%6,%7}, {%8,%9}, {%0,%1,%2,%3};"                \
        : "+f"(c[0]), "+f"(c[1]), "+f"(c[2]), "+f"(c[3])                       \
        : "r"(a0), "r"(a1), "r"(a2), "r"(a3), "r"(b0), "r"(b1))

#define QMMA(c, a0, a1, a2, a3, b0, b1)                                        \
    asm volatile(                                                              \
        "mma.sync.aligned.m16n8k32.row.col.f32.e4m3.e4m3.f32 "                 \
        "{%0,%1,%2,%3}, {%4,%5,%6,%7}, {%8,%9}, {%0,%1,%2,%3};"                \
        : "+f"(c[0]), "+f"(c[1]), "+f"(c[2]), "+f"(c[3])                       \
        : "r"(a0), "r"(a1), "r"(a2), "r"(a3), "r"(b0), "r"(b1))

__device__ __forceinline__ void ldsm4(unsigned &r0, unsigned &r1,
                                      unsigned &r2, unsigned &r3, unsigned addr) {
    asm volatile("ldmatrix.sync.aligned.m8n8.x4.shared.b16 {%0,%1,%2,%3}, [%4];"
        : "=r"(r0), "=r"(r1), "=r"(r2), "=r"(r3) : "r"(addr));
}
__device__ __forceinline__ void ldsm4t(unsigned &r0, unsigned &r1,
                                       unsigned &r2, unsigned &r3, unsigned addr) {
    asm volatile("ldmatrix.sync.aligned.m8n8.x4.trans.shared.b16 {%0,%1,%2,%3}, [%4];"
        : "=r"(r0), "=r"(r1), "=r"(r2), "=r"(r3) : "r"(addr));
}
__device__ __forceinline__ void cpasync16(void* sdst, const void* gsrc) {
    unsigned s = (unsigned)__cvta_generic_to_shared(sdst);
    asm volatile("cp.async.cg.shared.global [%0], [%1], 16;" :: "r"(s), "l"(gsrc));
}
__device__ __forceinline__ unsigned char f2e4m3(float v) {
    unsigned short t;
    asm("cvt.rn.satfinite.e4m3x2.f32 %0, %1, %2;" : "=h"(t) : "f"(0.f), "f"(v));
    return (unsigned char)t;
}
__device__ __forceinline__ unsigned short f2e4m3x2(float lo, float hi) {
    unsigned short t;
    asm("cvt.rn.satfinite.e4m3x2.f32 %0, %1, %2;" : "=h"(t) : "f"(hi), "f"(lo));
    return t;
}

// ---------------- convall: weights + PE + bias pack (one kernel) ----------
__global__ void convall_kernel(const float* __restrict__ wq, const float* __restrict__ wk,
                               const float* __restrict__ wv, const float* __restrict__ wo,
                               const float* __restrict__ w1, const float* __restrict__ w2,
                               const float* __restrict__ bq, const float* __restrict__ bk,
                               const float* __restrict__ bv) {
    int bid = blockIdx.x, tid = threadIdx.x;
    if (bid < 1024) {
        int m = bid >> 8;
        int idx = ((bid & 255) << 8) + tid;
        int k = idx >> 8, n = idx & 255;
        if (m == 0)      g_wqkvT[n * 256 + k]           = __float2bfloat16(wq[idx] * 0.125f);
        else if (m == 1) g_wqkvT[65536 + n * 256 + k]   = __float2bfloat16(wk[idx]);
        else if (m == 2) g_wqkvT[131072 + n * 256 + k]  = __float2bfloat16(wv[idx]);
        else             g_woT[n * 256 + k]             = __float2bfloat16(wo[idx]);
    } else if (bid < 3072) {                 // w1 [256][2048] -> [2048][256] fp8 x64
        int idx = (bid - 1024) * 256 + tid;
        int k = idx >> 11, n = idx & 2047;
        g_w1T8[n * 256 + k] = f2e4m3(w1[idx] * 64.0f);
    } else if (bid < 5120) {                 // w2 [2048][256] -> [256][2048] fp8 x64
        int idx = (bid - 3072) * 256 + tid;
        int k = idx >> 8, n = idx & 255;
        g_w2T8[(size_t)n * 2048 + k] = f2e4m3(w2[idx] * 64.0f);
    } else if (bid < 5460) {                 // PE table
        int s = bid - 5120, d = tid;
        float ex  = exp2f(-13.287712379549449f * ((float)d) * (1.0f / 128.0f));
        float arg = (float)s * ex;
        g_pe[s * D + d] = (d & 1) ? cosf(arg) : sinf(arg);
    } else {                                 // bias pack
        g_bqkv[tid]       = bq[tid] * 0.125f;
        g_bqkv[tid + 256] = bk[tid];
        g_bqkv[tid + 512] = bv[tid];
    }
}

// ---------------- fused embedding + scale + PE + LN1 (warp per token) -----
__global__ void embed_ln_kernel(const int* __restrict__ src,
                                const float* __restrict__ emb,
                                const float* __restrict__ ga,
                                const float* __restrict__ gb) {
    int w = threadIdx.x >> 5, lane = threadIdx.x & 31;
    int t = blockIdx.x * 8 + w;
    int tok = src[t];
    int b = t / SEQ;
    int s = t - b * SEQ;
    const float4* er = (const float4*)(emb + (size_t)tok * D);
    float4 a = er[lane * 2], bb = er[lane * 2 + 1];
    if (s < PREFIX) {
        const float4* pr = (const float4*)(g_pe + s * D);
        float4 p = pr[lane * 2], q = pr[lane * 2 + 1];
        a.x = fmaf(a.x, 16.f, p.x); a.y = fmaf(a.y, 16.f, p.y);
        a.z = fmaf(a.z, 16.f, p.z); a.w = fmaf(a.w, 16.f, p.w);
        bb.x = fmaf(bb.x, 16.f, q.x); bb.y = fmaf(bb.y, 16.f, q.y);
        bb.z = fmaf(bb.z, 16.f, q.z); bb.w = fmaf(bb.w, 16.f, q.w);
    }
    if (s < S2) {
        size_t co = ((size_t)(b * S2 + s)) * D + lane * 8;
        *(float4*)(g_xc + co)     = a;
        *(float4*)(g_xc + co + 4) = bb;
    }

    float sum = a.x + a.y + a.z + a.w + bb.x + bb.y + bb.z + bb.w;
    float mu = warp_sum(sum) * (1.0f / 256.0f);
    float dx[8] = {a.x - mu, a.y - mu, a.z - mu, a.w - mu,
                   bb.x - mu, bb.y - mu, bb.z - mu, bb.w - mu};
    float ss = 0.f;
    #pragma unroll
    for (int i = 0; i < 8; i++) ss = fmaf(dx[i], dx[i], ss);
    float inv = 1.0f / (sqrtf(warp_sum(ss) * (1.0f / 255.0f)) + 1e-6f);

    const float4* gav = (const float4*)(ga + lane * 8);
    const float4* gbv = (const float4*)(gb + lane * 8);
    float4 g0 = gav[0], g1 = gav[1], h0 = gbv[0], h1 = gbv[1];
    bf162 o[4];
    o[0] = __floats2bfloat162_rn(fmaf(g0.x, dx[0]*inv, h0.x), fmaf(g0.y, dx[1]*inv, h0.y));
    o[1] = __floats2bfloat162_rn(fmaf(g0.z, dx[2]*inv, h0.z), fmaf(g0.w, dx[3]*inv, h0.w));
    o[2] = __floats2bfloat162_rn(fmaf(g1.x, dx[4]*inv, h1.x), fmaf(g1.y, dx[5]*inv, h1.y));
    o[3] = __floats2bfloat162_rn(fmaf(g1.z, dx[6]*inv, h1.z), fmaf(g1.w, dx[7]*inv, h1.w));
    *(uint4*)(g_xb + (size_t)t * D + lane * 8) = *(uint4*)o;
}

// ---------------- bf16 tensor-core GEMM (128x256 CTA, single-sync loop) ---
// EPI 0: KV -> bf16 k/v at (B,H,360,DK); EPI 4: Q compact; EPI 1: WO+res+LN2->fp8
#define KT 64
#define BSTRH 72
#define A_STG (128*BSTRH)
#define B_STG (256*BSTRH)
#define GEMM_SMEM ((2*A_STG + 2*B_STG) * 2)   // 110592 bytes

template<int EPI>
__global__ __launch_bounds__(256)
void bgemm_kernel(const bf16* __restrict__ A, const bf16* __restrict__ Wt,
                  const float* __restrict__ bias, const float* __restrict__ res,
                  void* __restrict__ Cv0, void* __restrict__ Cv1,
                  const float* __restrict__ lnga, const float* __restrict__ lngb,
                  int M, int N, int K) {
    extern __shared__ bf16 smem[];
    const unsigned SMU = (unsigned)__cvta_generic_to_shared(smem);

    const int tid  = threadIdx.x;
    const int lane = tid & 31;
    const int wid  = tid >> 5;
    const int wm = wid >> 2;
    const int wn = wid & 3;
    const int g = lane >> 2;
    const int t = lane & 3;

    const int bm = blockIdx.y * 128;
    const int bn = blockIdx.x * 256;

    const int arow  = tid >> 1;
    const int ahalf = (tid & 1) * 32;
    int garow = bm + arow;
    if (EPI == 4) { int bb = garow / S2; garow = bb * SEQ + (garow - bb * S2); }
    const bf16* Ap = A  + (size_t)garow * K + ahalf;
    const bf16* Bp = Wt + (size_t)(bn + tid) * K;
    bf16* sA = smem;
    bf16* sB = smem + 2 * A_STG;

    const int a_r = lane & 15;
    const int a_c = ((lane >> 4) & 1) * 8;
    const int b_n = (lane & 7) + ((lane >> 4) & 1) * 8;
    const int b_c = ((lane >> 3) & 1) * 8;

    float acc[4][8][4];
    #pragma unroll
    for (int mi = 0; mi < 4; mi++)
        #pragma unroll
        for (int ni = 0; ni < 8; ni++)
            #pragma unroll
            for (int r = 0; r < 4; r++) acc[mi][ni][r] = 0.f;

    const int nt = K >> 6;
    {
        bf16* ad = sA + arow * BSTRH + ahalf;
        #pragma unroll
        for (int c = 0; c < 4; c++) cpasync16(ad + c * 8, Ap + c * 8);
        bf16* bd = sB + tid * BSTRH;
        #pragma unroll
        for (int c = 0; c < 8; c++) cpasync16(bd + c * 8, Bp + c * 8);
    }
    asm volatile("cp.async.commit_group;");

    for (int tl = 0; tl < nt; tl++) {
        const int cur = tl & 1;
        asm volatile("cp.async.wait_group 0;" ::: "memory");
        __syncthreads();                      // tile tl visible + prev compute done
        if (tl + 1 < nt) {
            const int nxt = cur ^ 1;
            bf16* ad = sA + nxt * A_STG + arow * BSTRH + ahalf;
            const bf16* ap = Ap + (tl + 1) * KT;
            #pragma unroll
            for (int c = 0; c < 4; c++) cpasync16(ad + c * 8, ap + c * 8);
            bf16* bd = sB + nxt * B_STG + tid * BSTRH;
            const bf16* bp = Bp + (tl + 1) * KT;
            #pragma unroll
            for (int c = 0; c < 8; c++) cpasync16(bd + c * 8, bp + c * 8);
            asm volatile("cp.async.commit_group;");
        }

        const unsigned abase = SMU + cur * (A_STG * 2);
        const unsigned bbase = SMU + 2 * (A_STG * 2) + cur * (B_STG * 2);
        #pragma unroll
        for (int kk = 0; kk < 4; kk++) {
            unsigned af[4][4], bfr[4][4];
            #pragma unroll
            for (int mi = 0; mi < 4; mi++) {
                unsigned addr = abase +
                    ((unsigned)((wm * 64 + mi * 16 + a_r) * BSTRH + kk * 16 + a_c) << 1);
                ldsm4(af[mi][0], af[mi][1], af[mi][2], af[mi][3], addr);
            }
            #pragma unroll
            for (int p = 0; p < 4; p++) {
                unsigned addr = bbase +
                    ((unsigned)((wn * 64 + p * 16 + b_n) * BSTRH + kk * 16 + b_c) << 1);
                ldsm4(bfr[p][0], bfr[p][1], bfr[p][2], bfr[p][3], addr);
            }
            #pragma unroll
            for (int mi = 0; mi < 4; mi++)
                #pragma unroll
                for (int ni = 0; ni < 8; ni++)
                    BMMA(acc[mi][ni], af[mi][0], af[mi][1], af[mi][2], af[mi][3],
                         bfr[ni >> 1][(ni & 1) * 2], bfr[ni >> 1][(ni & 1) * 2 + 1]);
        }
    }

    // ------------- epilogues -------------
    if (EPI == 0 || EPI == 4) {
        bf16* Cb = (bf16*)Cv0;
        if (EPI == 0 && blockIdx.x == 1) Cb = (bf16*)Cv1;
        const int sdim = (EPI == 0) ? SEQ : S2;
        const int hst  = (EPI == 0) ? HSTRIDE : HST2;
        #pragma unroll
        for (int mi = 0; mi < 4; mi++) {
            int row0 = bm + wm * 64 + mi * 16 + g;
            #pragma unroll
            for (int ni = 0; ni < 8; ni++) {
                int col = bn + wn * 64 + ni * 8 + t * 2;
                float2 bb = *(const float2*)(bias + col);
                #pragma unroll
                for (int half = 0; half < 2; half++) {
                    int row = row0 + half * 8;
                    float v0 = acc[mi][ni][half * 2 + 0] + bb.x;
                    float v1 = acc[mi][ni][half * 2 + 1] + bb.y;
                    int ic = col & 255;
                    int bbt = row / sdim;
                    int s   = row - bbt * sdim;
                    bf16* cb = Cb + (size_t)bbt * (H * hst) + (ic >> 6) * hst
                                  + s * DK + (ic & 63);
                    *(bf162*)cb = __floats2bfloat162_rn(v0, v1);
                }
            }
        }
    } else {
        // EPI 1: WO + residual -> g_y; fused LN2 -> fp8 g_x2b8. gridDim.x == 1.
        float* Y  = (float*)Cv0;
        unsigned char* X2 = (unsigned char*)Cv1;
        float* rsum = (float*)smem;
        float* rss  = rsum + 128;
        if (tid < 128) { rsum[tid] = 0.f; rss[tid] = 0.f; }
        __syncthreads();

        #pragma unroll
        for (int mi = 0; mi < 4; mi++) {
            #pragma unroll
            for (int half = 0; half < 2; half++) {
                int lrow = wm * 64 + mi * 16 + g + half * 8;
                size_t ro = (size_t)(bm + lrow) * 256;
                float s = 0.f, sq = 0.f;
                #pragma unroll
                for (int ni = 0; ni < 8; ni++) {
                    int col = wn * 64 + ni * 8 + t * 2;
                    float2 bb = *(const float2*)(bias + col);
                    float2 rv = *(const float2*)(res + ro + col);
                    float v0 = acc[mi][ni][half * 2 + 0] + bb.x + rv.x;
                    float v1 = acc[mi][ni][half * 2 + 1] + bb.y + rv.y;
                    acc[mi][ni][half * 2 + 0] = v0;
                    acc[mi][ni][half * 2 + 1] = v1;
                    *(float2*)(Y + ro + col) = make_float2(v0, v1);
                    s += v0 + v1;
                    sq = fmaf(v0, v0, fmaf(v1, v1, sq));
                }
                s  += __shfl_xor_sync(0xffffffffu, s, 1);
                s  += __shfl_xor_sync(0xffffffffu, s, 2);
                sq += __shfl_xor_sync(0xffffffffu, sq, 1);
                sq += __shfl_xor_sync(0xffffffffu, sq, 2);
                if (t == 0) { atomicAdd(&rsum[lrow], s); atomicAdd(&rss[lrow], sq); }
            }
        }
        __syncthreads();

        #pragma unroll
        for (int mi = 0; mi < 4; mi++) {
            #pragma unroll
            for (int half = 0; half < 2; half++) {
                int lrow = wm * 64 + mi * 16 + g + half * 8;
                size_t ro = (size_t)(bm + lrow) * 256;
                float mu  = rsum[lrow] * (1.0f / 256.0f);
                float var = (rss[lrow] - 256.0f * mu * mu) * (1.0f / 255.0f);
                float inv = 1.0f / (sqrtf(var) + 1e-6f);
                #pragma unroll
                for (int ni = 0; ni < 8; ni++) {
                    int col = wn * 64 + ni * 8 + t * 2;
                    float2 ga2 = *(const float2*)(lnga + col);
                    float2 gb2 = *(const float2*)(lngb + col);
                    float v0 = acc[mi][ni][half * 2 + 0];
                    float v1 = acc[mi][ni][half * 2 + 1];
                    unsigned short pk = f2e4m3x2(
                        fmaf(ga2.x, (v0 - mu) * inv, gb2.x),
                        fmaf(ga2.y, (v1 - mu) * inv, gb2.y));
                    *(unsigned short*)(X2 + ro + col) = pk;
                }
            }
        }
    }
}

// ---------------- fp8 tensor-core GEMM (FFN; 128x256 CTA, KT=128 fp8) -----
// EPI 0: FFN1 -> fp8 hidden = relu(acc/64 + b1)*8
// EPI 1: FFN2 -> fp32 out = res + acc/512 + b2
#define KT8 128
template<int EPI>
__global__ __launch_bounds__(256)
void qgemm_kernel(const unsigned char* __restrict__ A, const unsigned char* __restrict__ Wt,
                  const float* __restrict__ bias, const float* __restrict__ res,
                  void* __restrict__ Cv0, int M, int N, int K) {
    extern __shared__ unsigned char smem8[];
    const unsigned SMU = (unsigned)__cvta_generic_to_shared(smem8);
    const int AB = 128 * 144;                 // A stage bytes
    const int BB = 256 * 144;                 // B stage bytes

    const int tid  = threadIdx.x;
    const int lane = tid & 31;
    const int wid  = tid >> 5;
    const int wm = wid >> 2;
    const int wn = wid & 3;
    const int g = lane >> 2;
    const int t = lane & 3;

    const int bm = blockIdx.y * 128;
    const int bn = blockIdx.x * 256;

    const int arow  = tid >> 1;
    const int aoff  = (tid & 1) * 64;
    const unsigned char* Ap = A  + (size_t)(bm + arow) * K + aoff;
    const unsigned char* Bp = Wt + (size_t)(bn + tid) * K;
    unsigned char* sA = smem8;
    unsigned char* sB = smem8 + 2 * AB;

    const int a_r = lane & 15;
    const int a_cB = ((lane >> 4) & 1) * 16;
    const int b_n = (lane & 7) + ((lane >> 4) & 1) * 8;
    const int b_cB = ((lane >> 3) & 1) * 16;

    float acc[4][8][4];
    #pragma unroll
    for (int mi = 0; mi < 4; mi++)
        #pragma unroll
        for (int ni = 0; ni < 8; ni++)
            #pragma unroll
            for (int r = 0; r < 4; r++) acc[mi][ni][r] = 0.f;

    const int nt = K >> 7;
    {
        unsigned char* ad = sA + arow * 144 + aoff;
        #pragma unroll
        for (int c = 0; c < 4; c++) cpasync16(ad + c * 16, Ap + c * 16);
        unsigned char* bd = sB + tid * 144;
        #pragma unroll
        for (int c = 0; c < 8; c++) cpasync16(bd + c * 16, Bp + c * 16);
    }
    asm volatile("cp.async.commit_group;");

    for (int tl = 0; tl < nt; tl++) {
        const int cur = tl & 1;
        asm volatile("cp.async.wait_group 0;" ::: "memory");
        __syncthreads();
        if (tl + 1 < nt) {
            const int nxt = cur ^ 1;
            unsigned char* ad = sA + nxt * AB + arow * 144 + aoff;
            const unsigned char* ap = Ap + (tl + 1) * KT8;
            #pragma unroll
            for (int c = 0; c < 4; c++) cpasync16(ad + c * 16, ap + c * 16);
            unsigned char* bd = sB + nxt * BB + tid * 144;
            const unsigned char* bp = Bp + (tl + 1) * KT8;
            #pragma unroll
            for (int c = 0; c < 8; c++) cpasync16(bd + c * 16, bp + c * 16);
            asm volatile("cp.async.commit_group;");
        }

        const unsigned abase = SMU + cur * AB;
        const unsigned bbase = SMU + 2 * AB + cur * BB;
        #pragma unroll
        for (int kk = 0; kk < 4; kk++) {          // 4 x k32
            unsigned af[4][4], bfr[4][4];
            #pragma unroll
            for (int mi = 0; mi < 4; mi++) {
                unsigned addr = abase +
                    (unsigned)((wm * 64 + mi * 16 + a_r) * 144 + kk * 32 + a_cB);
                ldsm4(af[mi][0], af[mi][1], af[mi][2], af[mi][3], addr);
            }
            #pragma unroll
            for (int p = 0; p < 4; p++) {
                unsigned addr = bbase +
                    (unsigned)((wn * 64 + p * 16 + b_n) * 144 + kk * 32 + b_cB);
                ldsm4(bfr[p][0], bfr[p][1], bfr[p][2], bfr[p][3], addr);
            }
            #pragma unroll
            for (int mi = 0; mi < 4; mi++)
                #pragma unroll
                for (int ni = 0; ni < 8; ni++)
                    QMMA(acc[mi][ni], af[mi][0], af[mi][1], af[mi][2], af[mi][3],
                         bfr[ni >> 1][(ni & 1) * 2], bfr[ni >> 1][(ni & 1) * 2 + 1]);
        }
    }

    // ------------- epilogue -------------
    #pragma unroll
    for (int mi = 0; mi < 4; mi++) {
        int row0 = bm + wm * 64 + mi * 16 + g;
        #pragma unroll
        for (int ni = 0; ni < 8; ni++) {
            int col = bn + wn * 64 + ni * 8 + t * 2;
            float2 bb = *(const float2*)(bias + col);
            #pragma unroll
            for (int half = 0; half < 2; half++) {
                int row = row0 + half * 8;
                float a0 = acc[mi][ni][half * 2 + 0];
                float a1 = acc[mi][ni][half * 2 + 1];
                if (EPI == 0) {   // hidden = relu(acc/64 + b1) * 8, fp8
                    float v0 = fmaxf(fmaf(a0, 0.125f, bb.x * 8.0f), 0.f);
                    float v1 = fmaxf(fmaf(a1, 0.125f, bb.y * 8.0f), 0.f);
                    *(unsigned short*)((unsigned char*)Cv0 + (size_t)row * N + col) =
                        f2e4m3x2(v0, v1);
                } else {          // out = res + acc/512 + b2
                    size_t ro = (size_t)row * N + col;
                    float2 rv = *(const float2*)(res + ro);
                    *(float2*)((float*)Cv0 + ro) = make_float2(
                        fmaf(a0, 1.0f / 512.0f, bb.x + rv.x),
                        fmaf(a1, 1.0f / 512.0f, bb.y + rv.y));
                }
            }
        }
    }
}

// ---------------- tensor-core attention (ldmatrix, no V transpose) --------
// smem byte layout: Q 64x144 | K 376x144 | V 376x144 | P 64x752 | red 1KB
#define SMQ_B 0
#define SMK_B (64*144)                // 9216
#define SMV_B (SMK_B + 376*144)       // 63360
#define SMP_B (SMV_B + 376*144)       // 117504
#define SMRED_B (SMP_B + 64*752)      // 165632
#define ATT_SMEM (SMRED_B + 1024)     // 166656

__global__ __launch_bounds__(256, 1)
void fattn_kernel(const int* __restrict__ src) {
    extern __shared__ unsigned sm32[];
    const unsigned SMU = (unsigned)__cvta_generic_to_shared(sm32);
    unsigned* q32 = sm32;                     // stride 36 u32
    unsigned* k32 = sm32 + SMK_B / 4;         // stride 36
    unsigned* v32 = sm32 + SMV_B / 4;         // stride 36
    unsigned* p32 = sm32 + SMP_B / 4;         // stride 188
    float* redm = (float*)(sm32 + SMRED_B / 4);
    float* reds = redm + 128;

    const int bh = blockIdx.x;
    const int b  = bh >> 2;
    const size_t hb = (size_t)bh * HSTRIDE;
    const int tid = threadIdx.x;

    // ---- load K, V (raw [key][dk]); zero pad rows 360..375 ----
    const uint4* gk = (const uint4*)(g_kb + hb);
    const uint4* gv = (const uint4*)(g_vb + hb);
    for (int u = tid; u < 2880; u += 256) {
        int row = u >> 3, c8 = u & 7;
        *(uint4*)&k32[row * 36 + c8 * 4] = gk[u];
        *(uint4*)&v32[row * 36 + c8 * 4] = gv[u];
    }
    for (int u = tid; u < 576; u += 256) {
        int r = 360 + u / 36, c = u - (u / 36) * 36;
        k32[r * 36 + c] = 0u;
        v32[r * 36 + c] = 0u;
    }

    const int lane = tid & 31, wid = tid >> 5;
    const int wq = wid >> 1;
    const int wk = wid & 1;
    const int g = lane >> 2, t = lane & 3;
    const int kb = wk * 184;
    const int r_lo = wq * 16 + g, r_hi = r_lo + 8;
    const int head = bh & 3;
    const uint4* gq = (const uint4*)(g_qb + (size_t)bh * HST2);

    // ldmatrix lane constants
    const int a_r = lane & 15;
    const int a_cB = ((lane >> 4) & 1) * 16;
    const int b_n = (lane & 7) + ((lane >> 4) & 1) * 8;
    const int b_cB = ((lane >> 3) & 1) * 16;
    // V-trans addressing: row = k_base + (lane&15); col bytes = n_base*2 + (lane>>4)*16
    const int vt_r = lane & 15;
    const int vt_cB = ((lane >> 4) & 1) * 16;

    for (int qt = 0; qt < 3; qt++) {
        const int qbase = qt * 64;

        #pragma unroll
        for (int u = tid; u < 512; u += 256) {
            int row = u >> 3, c8 = u & 7;
            *(uint4*)&q32[row * 36 + c8 * 4] = gq[(qbase + row) * 8 + c8];
        }
        __syncthreads();

        // ---- S = Q K^T ----
        float acc[23][4];
        #pragma unroll
        for (int ni = 0; ni < 23; ni++)
            #pragma unroll
            for (int r = 0; r < 4; r++) acc[ni][r] = 0.f;

        #pragma unroll
        for (int kt = 0; kt < 4; kt++) {
            unsigned a0, a1, a2, a3;
            ldsm4(a0, a1, a2, a3,
                  SMU + SMQ_B + (unsigned)((wq * 16 + a_r) * 144 + kt * 32 + a_cB));
            #pragma unroll
            for (int p = 0; p < 12; p++) {
                unsigned b0, b1, b2, b3;
                ldsm4(b0, b1, b2, b3,
                      SMU + SMK_B + (unsigned)((kb + p * 16 + b_n) * 144 + kt * 32 + b_cB));
                BMMA(acc[2 * p], a0, a1, a2, a3, b0, b1);
                if (2 * p + 1 < 23) BMMA(acc[2 * p + 1], a0, a1, a2, a3, b2, b3);
            }
        }

        // ---- softmax ----
        bool v_lo = (src[b * SEQ + qbase + r_lo] != PADTOK);
        bool v_hi = (src[b * SEQ + qbase + r_hi] != PADTOK);

        float m_lo = -1e30f, m_hi = -1e30f;
        #pragma unroll
        for (int ni = 0; ni < 23; ni++) {
            int col0 = kb + ni * 8 + t * 2;
            bool in0 = col0 < SEQ, in1 = col0 + 1 < SEQ;
            acc[ni][0] = in0 ? (v_lo ? acc[ni][0] : 0.f) : -1e30f;
            acc[ni][1] = in1 ? (v_lo ? acc[ni][1] : 0.f) : -1e30f;
            acc[ni][2] = in0 ? (v_hi ? acc[ni][2] : 0.f) : -1e30f;
            acc[ni][3] = in1 ? (v_hi ? acc[ni][3] : 0.f) : -1e30f;
            m_lo = fmaxf(m_lo, fmaxf(acc[ni][0], acc[ni][1]));
            m_hi = fmaxf(m_hi, fmaxf(acc[ni][2], acc[ni][3]));
        }
        m_lo = fmaxf(m_lo, __shfl_xor_sync(0xffffffffu, m_lo, 1));
        m_lo = fmaxf(m_lo, __shfl_xor_sync(0xffffffffu, m_lo, 2));
        m_hi = fmaxf(m_hi, __shfl_xor_sync(0xffffffffu, m_hi, 1));
        m_hi = fmaxf(m_hi, __shfl_xor_sync(0xffffffffu, m_hi, 2));
        if (t == 0) { redm[wk * 64 + r_lo] = m_lo; redm[wk * 64 + r_hi] = m_hi; }
        __syncthreads();
        m_lo = fmaxf(redm[r_lo], redm[64 + r_lo]);
        m_hi = fmaxf(redm[r_hi], redm[64 + r_hi]);

        float s_lo = 0.f, s_hi = 0.f;
        #pragma unroll
        for (int ni = 0; ni < 23; ni++) {
            acc[ni][0] = __expf(acc[ni][0] - m_lo);
            acc[ni][1] = __expf(acc[ni][1] - m_lo);
            acc[ni][2] = __expf(acc[ni][2] - m_hi);
            acc[ni][3] = __expf(acc[ni][3] - m_hi);
            s_lo += acc[ni][0] + acc[ni][1];
            s_hi += acc[ni][2] + acc[ni][3];
        }
        s_lo += __shfl_xor_sync(0xffffffffu, s_lo, 1);
        s_lo += __shfl_xor_sync(0xffffffffu, s_lo, 2);
        s_hi += __shfl_xor_sync(0xffffffffu, s_hi, 1);
        s_hi += __shfl_xor_sync(0xffffffffu, s_hi, 2);
        if (t == 0) { reds[wk * 64 + r_lo] = s_lo; reds[wk * 64 + r_hi] = s_hi; }
        __syncthreads();
        float inv_lo = 1.f / (reds[r_lo] + reds[64 + r_lo]);
        float inv_hi = 1.f / (reds[r_hi] + reds[64 + r_hi]);

        // ---- write P (bf16, row stride 188 u32) ----
        #pragma unroll
        for (int ni = 0; ni < 23; ni++) {
            int cu = (kb >> 1) + ni * 4 + t;
            bf162 p0 = __floats2bfloat162_rn(acc[ni][0] * inv_lo, acc[ni][1] * inv_lo);
            bf162 p1 = __floats2bfloat162_rn(acc[ni][2] * inv_hi, acc[ni][3] * inv_hi);
            p32[r_lo * 188 + cu] = *(unsigned*)&p0;
            p32[r_hi * 188 + cu] = *(unsigned*)&p1;
        }
        __syncthreads();

        // ---- O = P @ V (B-frags via ldmatrix.trans on raw V) ----
        float o[4][4];
        #pragma unroll
        for (int ni = 0; ni < 4; ni++)
            #pragma unroll
            for (int r = 0; r < 4; r++) o[ni][r] = 0.f;

        #pragma unroll
        for (int kt = 0; kt < 23; kt++) {
            unsigned a0, a1, a2, a3;
            ldsm4(a0, a1, a2, a3,
                  SMU + SMP_B + (unsigned)((wq * 16 + a_r) * 752 + kt * 32 + a_cB));
            #pragma unroll
            for (int nb = 0; nb < 2; nb++) {
                unsigned b0, b1, b2, b3;
                ldsm4t(b0, b1, b2, b3,
                       SMU + SMV_B + (unsigned)((kt * 16 + vt_r) * 144
                                                + wk * 64 + nb * 32 + vt_cB));
                BMMA(o[2 * nb],     a0, a1, a2, a3, b0, b1);
                BMMA(o[2 * nb + 1], a0, a1, a2, a3, b2, b3);
            }
        }

        #pragma unroll
        for (int ni = 0; ni < 4; ni++) {
            int col = wk * 32 + ni * 8 + t * 2;
            size_t ob0 = ((size_t)(b * S2 + qbase + r_lo)) * D + head * DK + col;
            size_t ob1 = ((size_t)(b * S2 + qbase + r_hi)) * D + head * DK + col;
            *(bf162*)(g_ctxb + ob0) = __floats2bfloat162_rn(o[ni][0], o[ni][1]);
            *(bf162*)(g_ctxb + ob1) = __floats2bfloat162_rn(o[ni][2], o[ni][3]);
        }
    }
}

// ---------------- classifier (warp per pair, wl in smem) ------------------
__global__ __launch_bounds__(256)
void cls_kernel(const int* __restrict__ src,
                const float* __restrict__ wl,
                const float* __restrict__ bl,
                float* __restrict__ out) {
    __shared__ float swl[6144];
    int tid = threadIdx.x;
    #pragma unroll
    for (int u = 0; u < 24; u++) swl[u * 256 + tid] = wl[u * 256 + tid];
    __syncthreads();

    int w = tid >> 5, lane = tid & 31;
    int bp = blockIdx.x * 8 + w;
    int b = bp / NPAIR, p = bp - b * NPAIR;

    int i = 0, rem = p;
    while (rem >= 13 - i) { rem -= 13 - i; i++; }
    int j = i + 1 + rem;
    int base = i * 12 - (i * (i - 1)) / 2;
    int pe = base + (j - i) - 1;
    int eb = 28 + 2 * pe;
    int gidx[8] = {2*i, 2*i+1, 2*j, 2*j+1, eb, eb+1, eb+2, eb+3};

    const float* xb = g_xf + (size_t)(b * S2) * D;
    int slots = (j < 13) ? 8 : 4;

    float a0 = 0.f, a1 = 0.f, a2 = 0.f;
    for (int sl = 0; sl < slots; sl++) {
        const float* xr = xb + gidx[sl] * D;
        const float* wr = swl + sl * 768;
        #pragma unroll
        for (int dd = 0; dd < 8; dd++) {
            int dim = lane + dd * 32;
            float xv = xr[dim];
            a0 = fmaf(xv, wr[dim * 3 + 0], a0);
            a1 = fmaf(xv, wr[dim * 3 + 1], a1);
            a2 = fmaf(xv, wr[dim * 3 + 2], a2);
        }
    }
    a0 = warp_sum(a0); a1 = warp_sum(a1); a2 = warp_sum(a2);

    if (lane == 0) {
        const int* sb = src + b * SEQ;
        int ti = sb[2*i], ai = sb[2*i+1], tj = sb[2*j], aj = sb[2*j+1];
        bool c1 = (ai == 2) || (aj == 2);
        bool c2 = (tj == 1) || (ai == 1) || (aj == 1);
        bool c3 = (ti == PADTOK) || (tj == PADTOK) || (ai == 0) || (aj == 0);
        bool c4 = false;
        if (j < 13) {
            int es = 28 + 4 * pe;
            c4 = (sb[es] == 1) || (sb[es+1] == 1) || (sb[es+2] == 1) || (sb[es+3] == 1);
        }
        bool m111 = c3 || c4;
        bool mk1 = m111 || c2;
        bool mk2 = mk1 || c1;
        float* o = out + (size_t)bp * 3;
        o[0] = m111 ? -1e9f : (a0 + bl[0]);
        o[1] = mk1  ? -1e9f : (a1 + bl[1]);
        o[2] = mk2  ? -1e9f : (a2 + bl[2]);
    }
}

// ---------------- launch ----------------
extern "C" void kernel_launch(void* const* d_in, const int* in_sizes, int n_in,
                              void* d_out, int out_size) {
    (void)in_sizes; (void)n_in; (void)out_size;
    const int*   src = (const int*)  d_in[0];
    const float* emb = (const float*)d_in[1];
    const float* wq  = (const float*)d_in[2];
    const float* bq  = (const float*)d_in[3];
    const float* wk  = (const float*)d_in[4];
    const float* bk  = (const float*)d_in[5];
    const float* wv  = (const float*)d_in[6];
    const float* bv  = (const float*)d_in[7];
    const float* wo  = (const float*)d_in[8];
    const float* bo  = (const float*)d_in[9];
    const float* n1a = (const float*)d_in[10];
    const float* n1b = (const float*)d_in[11];
    const float* n2a = (const float*)d_in[12];
    const float* n2b = (const float*)d_in[13];
    const float* w1  = (const float*)d_in[14];
    const float* b1  = (const float*)d_in[15];
    const float* w2  = (const float*)d_in[16];
    const float* b2  = (const float*)d_in[17];
    const float* wl  = (const float*)d_in[18];
    const float* bl  = (const float*)d_in[19];
    float* out = (float*)d_out;

    float *pxc, *py, *pxf, *pbqkv;
    bf16 *pxb, *pqb, *pkb, *pvb, *pctxb, *pwqkvT, *pwoT;
    unsigned char *px2b8, *phb8, *pw1T8, *pw2T8;
    cudaGetSymbolAddress((void**)&pxc,    g_xc);
    cudaGetSymbolAddress((void**)&pxb,    g_xb);
    cudaGetSymbolAddress((void**)&pqb,    g_qb);
    cudaGetSymbolAddress((void**)&pkb,    g_kb);
    cudaGetSymbolAddress((void**)&pvb,    g_vb);
    cudaGetSymbolAddress((void**)&pctxb,  g_ctxb);
    cudaGetSymbolAddress((void**)&py,     g_y);
    cudaGetSymbolAddress((void**)&px2b8,  g_x2b8);
    cudaGetSymbolAddress((void**)&phb8,   g_hb8);
    cudaGetSymbolAddress((void**)&pxf,    g_xf);
    cudaGetSymbolAddress((void**)&pwqkvT, g_wqkvT);
    cudaGetSymbolAddress((void**)&pwoT,   g_woT);
    cudaGetSymbolAddress((void**)&pw1T8,  g_w1T8);
    cudaGetSymbolAddress((void**)&pw2T8,  g_w2T8);
    cudaGetSymbolAddress((void**)&pbqkv,  g_bqkv);

    cudaFuncSetAttribute(fattn_kernel, cudaFuncAttributeMaxDynamicSharedMemorySize,
                         (int)ATT_SMEM);
    cudaFuncSetAttribute(bgemm_kernel<0>, cudaFuncAttributeMaxDynamicSharedMemorySize, GEMM_SMEM);
    cudaFuncSetAttribute(bgemm_kernel<1>, cudaFuncAttributeMaxDynamicSharedMemorySize, GEMM_SMEM);
    cudaFuncSetAttribute(bgemm_kernel<4>, cudaFuncAttributeMaxDynamicSharedMemorySize, GEMM_SMEM);
    cudaFuncSetAttribute(qgemm_kernel<0>, cudaFuncAttributeMaxDynamicSharedMemorySize, GEMM_SMEM);
    cudaFuncSetAttribute(qgemm_kernel<1>, cudaFuncAttributeMaxDynamicSharedMemorySize, GEMM_SMEM);

    convall_kernel<<<5461, 256>>>(wq, wk, wv, wo, w1, w2, bq, bk, bv);
    embed_ln_kernel<<<TOKENS/8, 256>>>(src, emb, n1a, n1b);

    // KV projection (full tokens, N=512)
    dim3 gkv(2, TOKENS / 128);
    bgemm_kernel<0><<<gkv, 256, GEMM_SMEM>>>(pxb, pwqkvT + 65536, pbqkv + 256, nullptr,
                                             pkb, pvb, nullptr, nullptr, TOKENS, 512, D);
    // Q projection (compact tokens, row-remapped A)
    dim3 gq(1, M2 / 128);
    bgemm_kernel<4><<<gq, 256, GEMM_SMEM>>>(pxb, pwqkvT, pbqkv, nullptr,
                                            pqb, nullptr, nullptr, nullptr, M2, 256, D);

    fattn_kernel<<<HEADS, 256, ATT_SMEM>>>(src);

    // WO + residual + fused LN2 (fp8 out)
    bgemm_kernel<1><<<gq, 256, GEMM_SMEM>>>(pctxb, pwoT, bo, pxc,
                                            py, px2b8, n2a, n2b, M2, 256, D);

    // FFN in fp8
    dim3 gff1(8, M2 / 128);
    qgemm_kernel<0><<<gff1, 256, GEMM_SMEM>>>(px2b8, pw1T8, b1, nullptr,
                                              phb8, M2, DFF, D);
    qgemm_kernel<1><<<gq, 256, GEMM_SMEM>>>(phb8, pw2T8, b2, py,
                                            pxf, M2, 256, DFF);

    cls_kernel<<<(BATCH * NPAIR) / 8, 256>>>(src, wl, bl, out);
}

// round 15
// speedup vs baseline: 10.9192x; 1.2105x over previous
#include <cuda_runtime.h>
#include <cuda_bf16.h>
#include <math.h>

// ---------------- problem constants ----------------
#define BATCH   256
#define SEQ     360
#define PREFIX  340
#define D       256
#define H       4
#define DK      64
#define DFF     2048
#define NPAIR   91
#define PADTOK  799
#define TOKENS  (BATCH*SEQ)          // 92160
#define HEADS   (BATCH*H)            // 1024
#define HSTRIDE (SEQ*DK)             // 23040
#define S2      192                  // compact tokens per sequence
#define M2      (BATCH*S2)           // 49152
#define HST2    (S2*DK)              // 12288

typedef __nv_bfloat16 bf16;
typedef __nv_bfloat162 bf162;
typedef unsigned char u8;

// ---------------- scratch (device globals) ----------------
__device__ float g_xc [M2*D];           // residual after embed (compact, fp32)
__device__ u8    g_x18[TOKENS*D];       // LN1 output (full, fp8)
__device__ bf16  g_qb [M2*D];           // Q (B,H,192,64) bf16
__device__ bf16  g_kb [TOKENS*D];       // K (B,H,360,64) bf16
__device__ bf16  g_vb [TOKENS*D];       // V (B,H,360,64) bf16
__device__ u8    g_ctx8[M2*D];          // attention output (compact, fp8)
__device__ float g_y  [M2*D];           // residual after WO (compact, fp32)
__device__ u8    g_x2b8[M2*D];          // LN2 output (compact, fp8)
__device__ u8    g_hb8[M2*DFF];         // ffn hidden (compact, fp8, x8)
__device__ float g_xf [M2*D];           // final x (compact, fp32)
__device__ float g_pe [PREFIX*D];
__device__ u8    g_wqkv8[3*D*D];        // [768][256]: q(x8=0.125*64) | k(x64) | v(x64)
__device__ u8    g_wo8[D*D];            // x64
__device__ u8    g_w18[DFF*D];          // x64
__device__ u8    g_w28[D*DFF];          // x64
__device__ float g_bqkv[3*D];           // bq*0.125 | bk | bv

// ---------------- helpers ----------------
__device__ __forceinline__ float warp_sum(float v) {
    #pragma unroll
    for (int o = 16; o; o >>= 1) v += __shfl_xor_sync(0xffffffffu, v, o);
    return v;
}

#define BMMA(c, a0, a1, a2, a3, b0, b1)                                        \
    asm volatile(                                                              \
        "mma.sync.aligned.m16n8k16.row.col.f32.bf16.bf16.f32 "                 \
        "{%0,%1,%2,%3}, {%4,%5,%6,%7}, {%8,%9}, {%0,%1,%2,%3};"                \
        : "+f"(c[0]), "+f"(c[1]), "+f"(c[2]), "+f"(c[3])                       \
        : "r"(a0), "r"(a1), "r"(a2), "r"(a3), "r"(b0), "r"(b1))

#define QMMA(c, a0, a1, a2, a3, b0, b1)                                        \
    asm volatile(                                                              \
        "mma.sync.aligned.m16n8k32.row.col.f32.e4m3.e4m3.f32 "                 \
        "{%0,%1,%2,%3}, {%4,%5,%6,%7}, {%8,%9}, {%0,%1,%2,%3};"                \
        : "+f"(c[0]), "+f"(c[1]), "+f"(c[2]), "+f"(c[3])                       \
        : "r"(a0), "r"(a1), "r"(a2), "r"(a3), "r"(b0), "r"(b1))

__device__ __forceinline__ void ldsm4(unsigned &r0, unsigned &r1,
                                      unsigned &r2, unsigned &r3, unsigned addr) {
    asm volatile("ldmatrix.sync.aligned.m8n8.x4.shared.b16 {%0,%1,%2,%3}, [%4];"
        : "=r"(r0), "=r"(r1), "=r"(r2), "=r"(r3) : "r"(addr));
}
__device__ __forceinline__ void ldsm4t(unsigned &r0, unsigned &r1,
                                       unsigned &r2, unsigned &r3, unsigned addr) {
    asm volatile("ldmatrix.sync.aligned.m8n8.x4.trans.shared.b16 {%0,%1,%2,%3}, [%4];"
        : "=r"(r0), "=r"(r1), "=r"(r2), "=r"(r3) : "r"(addr));
}
__device__ __forceinline__ void cpasync16(void* sdst, const void* gsrc) {
    unsigned s = (unsigned)__cvta_generic_to_shared(sdst);
    asm volatile("cp.async.cg.shared.global [%0], [%1], 16;" :: "r"(s), "l"(gsrc));
}
__device__ __forceinline__ u8 f2e4m3(float v) {
    unsigned short t;
    asm("cvt.rn.satfinite.e4m3x2.f32 %0, %1, %2;" : "=h"(t) : "f"(0.f), "f"(v));
    return (u8)t;
}
__device__ __forceinline__ unsigned short f2e4m3x2(float lo, float hi) {
    unsigned short t;
    asm("cvt.rn.satfinite.e4m3x2.f32 %0, %1, %2;" : "=h"(t) : "f"(hi), "f"(lo));
    return t;
}

// ---------------- convall: weights (fp8) + PE + bias pack -----------------
__global__ void convall_kernel(const float* __restrict__ wq, const float* __restrict__ wk,
                               const float* __restrict__ wv, const float* __restrict__ wo,
                               const float* __restrict__ w1, const float* __restrict__ w2,
                               const float* __restrict__ bq, const float* __restrict__ bk,
                               const float* __restrict__ bv) {
    int bid = blockIdx.x, tid = threadIdx.x;
    if (bid < 768) {                         // wq/wk/wv -> g_wqkv8
        int m = bid >> 8;                    // 0,1,2
        int idx = ((bid & 255) << 8) + tid;
        int k = idx >> 8, n = idx & 255;
        if (m == 0)      g_wqkv8[n * 256 + k]             = f2e4m3(wq[idx] * 8.0f);
        else if (m == 1) g_wqkv8[(256 + n) * 256 + k]     = f2e4m3(wk[idx] * 64.0f);
        else             g_wqkv8[(512 + n) * 256 + k]     = f2e4m3(wv[idx] * 64.0f);
    } else if (bid < 1024) {                 // wo
        int idx = ((bid - 768) << 8) + tid;
        int k = idx >> 8, n = idx & 255;
        g_wo8[n * 256 + k] = f2e4m3(wo[idx] * 64.0f);
    } else if (bid < 3072) {                 // w1 [256][2048] -> [2048][256]
        int idx = (bid - 1024) * 256 + tid;
        int k = idx >> 11, n = idx & 2047;
        g_w18[n * 256 + k] = f2e4m3(w1[idx] * 64.0f);
    } else if (bid < 5120) {                 // w2 [2048][256] -> [256][2048]
        int idx = (bid - 3072) * 256 + tid;
        int k = idx >> 8, n = idx & 255;
        g_w28[(size_t)n * 2048 + k] = f2e4m3(w2[idx] * 64.0f);
    } else if (bid < 5460) {                 // PE table
        int s = bid - 5120, d = tid;
        float ex  = exp2f(-13.287712379549449f * ((float)d) * (1.0f / 128.0f));
        float arg = (float)s * ex;
        g_pe[s * D + d] = (d & 1) ? cosf(arg) : sinf(arg);
    } else {                                 // bias pack
        g_bqkv[tid]       = bq[tid] * 0.125f;
        g_bqkv[tid + 256] = bk[tid];
        g_bqkv[tid + 512] = bv[tid];
    }
}

// ---------------- fused embedding + scale + PE + LN1 (warp per token) -----
__global__ void embed_ln_kernel(const int* __restrict__ src,
                                const float* __restrict__ emb,
                                const float* __restrict__ ga,
                                const float* __restrict__ gb) {
    int w = threadIdx.x >> 5, lane = threadIdx.x & 31;
    int t = blockIdx.x * 8 + w;
    int tok = src[t];
    int b = t / SEQ;
    int s = t - b * SEQ;
    const float4* er = (const float4*)(emb + (size_t)tok * D);
    float4 a = er[lane * 2], bb = er[lane * 2 + 1];
    if (s < PREFIX) {
        const float4* pr = (const float4*)(g_pe + s * D);
        float4 p = pr[lane * 2], q = pr[lane * 2 + 1];
        a.x = fmaf(a.x, 16.f, p.x); a.y = fmaf(a.y, 16.f, p.y);
        a.z = fmaf(a.z, 16.f, p.z); a.w = fmaf(a.w, 16.f, p.w);
        bb.x = fmaf(bb.x, 16.f, q.x); bb.y = fmaf(bb.y, 16.f, q.y);
        bb.z = fmaf(bb.z, 16.f, q.z); bb.w = fmaf(bb.w, 16.f, q.w);
    }
    if (s < S2) {
        size_t co = ((size_t)(b * S2 + s)) * D + lane * 8;
        *(float4*)(g_xc + co)     = a;
        *(float4*)(g_xc + co + 4) = bb;
    }

    float sum = a.x + a.y + a.z + a.w + bb.x + bb.y + bb.z + bb.w;
    float mu = warp_sum(sum) * (1.0f / 256.0f);
    float dx[8] = {a.x - mu, a.y - mu, a.z - mu, a.w - mu,
                   bb.x - mu, bb.y - mu, bb.z - mu, bb.w - mu};
    float ss = 0.f;
    #pragma unroll
    for (int i = 0; i < 8; i++) ss = fmaf(dx[i], dx[i], ss);
    float inv = 1.0f / (sqrtf(warp_sum(ss) * (1.0f / 255.0f)) + 1e-6f);

    const float4* gav = (const float4*)(ga + lane * 8);
    const float4* gbv = (const float4*)(gb + lane * 8);
    float4 g0 = gav[0], g1 = gav[1], h0 = gbv[0], h1 = gbv[1];
    float y0 = fmaf(g0.x, dx[0]*inv, h0.x), y1 = fmaf(g0.y, dx[1]*inv, h0.y);
    float y2 = fmaf(g0.z, dx[2]*inv, h0.z), y3 = fmaf(g0.w, dx[3]*inv, h0.w);
    float y4 = fmaf(g1.x, dx[4]*inv, h1.x), y5 = fmaf(g1.y, dx[5]*inv, h1.y);
    float y6 = fmaf(g1.z, dx[6]*inv, h1.z), y7 = fmaf(g1.w, dx[7]*inv, h1.w);
    unsigned s0 = f2e4m3x2(y0, y1), s1 = f2e4m3x2(y2, y3);
    unsigned s2 = f2e4m3x2(y4, y5), s3 = f2e4m3x2(y6, y7);
    uint2 pk;
    pk.x = s0 | (s1 << 16);
    pk.y = s2 | (s3 << 16);
    *(uint2*)(g_x18 + (size_t)t * D + lane * 8) = pk;
}

// ---------------- layernorm 2 (warp per token, fp32 -> fp8) ---------------
__global__ void ln2_kernel(const float* __restrict__ ga, const float* __restrict__ gb) {
    int w = threadIdx.x >> 5, lane = threadIdx.x & 31;
    int t = blockIdx.x * 8 + w;
    size_t off = (size_t)t * D + lane * 8;
    float4 a = *(const float4*)(g_y + off);
    float4 b = *(const float4*)(g_y + off + 4);

    float sum = a.x + a.y + a.z + a.w + b.x + b.y + b.z + b.w;
    float mu = warp_sum(sum) * (1.0f / 256.0f);
    float dx[8] = {a.x - mu, a.y - mu, a.z - mu, a.w - mu,
                   b.x - mu, b.y - mu, b.z - mu, b.w - mu};
    float ss = 0.f;
    #pragma unroll
    for (int i = 0; i < 8; i++) ss = fmaf(dx[i], dx[i], ss);
    float inv = 1.0f / (sqrtf(warp_sum(ss) * (1.0f / 255.0f)) + 1e-6f);

    const float4* gav = (const float4*)(ga + lane * 8);
    const float4* gbv = (const float4*)(gb + lane * 8);
    float4 g0 = gav[0], g1 = gav[1], h0 = gbv[0], h1 = gbv[1];
    float y0 = fmaf(g0.x, dx[0]*inv, h0.x), y1 = fmaf(g0.y, dx[1]*inv, h0.y);
    float y2 = fmaf(g0.z, dx[2]*inv, h0.z), y3 = fmaf(g0.w, dx[3]*inv, h0.w);
    float y4 = fmaf(g1.x, dx[4]*inv, h1.x), y5 = fmaf(g1.y, dx[5]*inv, h1.y);
    float y6 = fmaf(g1.z, dx[6]*inv, h1.z), y7 = fmaf(g1.w, dx[7]*inv, h1.w);
    unsigned s0 = f2e4m3x2(y0, y1), s1 = f2e4m3x2(y2, y3);
    unsigned s2 = f2e4m3x2(y4, y5), s3 = f2e4m3x2(y6, y7);
    uint2 pk;
    pk.x = s0 | (s1 << 16);
    pk.y = s2 | (s3 << 16);
    *(uint2*)(g_x2b8 + off) = pk;
}

// ---------------- universal fp8 GEMM: CTA 128x128, warp 64x32, KT=64 ------
// EPI 0: merged KVQ -> bf16 scatter. blockIdx.x: 0-3 K/V (full M), 4-5 Q (compact).
// EPI 1: WO   -> fp32 g_y = res + acc/64 + bias
// EPI 2: FFN1 -> fp8 hidden = relu(acc/64 + b1) * 8
// EPI 3: FFN2 -> fp32 out = res + acc/512 + b2
#define RSTR 80                               // fp8 row stride bytes (64 + 16 pad)
#define ASTG (128*RSTR)                       // 10240 bytes per stage per matrix
#define QG_SMEM (4*ASTG)                      // 40960 bytes

template<int EPI>
__global__ __launch_bounds__(256, 2)
void q128_kernel(const u8* __restrict__ A, const u8* __restrict__ Wt,
                 const float* __restrict__ bias, const float* __restrict__ res,
                 void* __restrict__ Cv0, int M, int N, int K) {
    const int bx = blockIdx.x;
    if (EPI == 0 && bx >= 4 && blockIdx.y >= 384) return;

    extern __shared__ u8 sm8[];
    const unsigned SMU = (unsigned)__cvta_generic_to_shared(sm8);

    const int tid  = threadIdx.x;
    const int lane = tid & 31;
    const int wid  = tid >> 5;
    const int wm = wid >> 2;                  // 0..1 (64 rows)
    const int wn = wid & 3;                   // 0..3 (32 cols)
    const int g = lane >> 2;
    const int t = lane & 3;

    const int bm = blockIdx.y * 128;
    const int wrow0 = (EPI == 0) ? ((bx < 4) ? 256 + bx * 128 : (bx - 4) * 128)
                                 : bx * 128;

    // cp.async mapping: row = tid/2, 32-byte half = (tid&1)
    const int arow = tid >> 1;
    const int acb  = (tid & 1) * 32;
    int garow = bm + arow;
    if (EPI == 0 && bx >= 4) { int bb = garow / S2; garow = bb * SEQ + (garow - bb * S2); }
    const u8* Ap = A  + (size_t)garow * K + acb;
    const u8* Bp = Wt + (size_t)(wrow0 + arow) * K + acb;

    const int a_r  = lane & 15;
    const int a_cB = ((lane >> 4) & 1) * 16;
    const int b_n  = (lane & 7) + ((lane >> 4) & 1) * 8;
    const int b_cB = ((lane >> 3) & 1) * 16;

    float acc[4][4][4];
    #pragma unroll
    for (int mi = 0; mi < 4; mi++)
        #pragma unroll
        for (int ni = 0; ni < 4; ni++)
            #pragma unroll
            for (int r = 0; r < 4; r++) acc[mi][ni][r] = 0.f;

    const int nt = K >> 6;
    {
        u8* ad = sm8 + arow * RSTR + acb;
        cpasync16(ad, Ap); cpasync16(ad + 16, Ap + 16);
        u8* bd = sm8 + 2 * ASTG + arow * RSTR + acb;
        cpasync16(bd, Bp); cpasync16(bd + 16, Bp + 16);
    }
    asm volatile("cp.async.commit_group;");

    for (int tl = 0; tl < nt; tl++) {
        const int cur = tl & 1;
        asm volatile("cp.async.wait_group 0;" ::: "memory");
        __syncthreads();
        if (tl + 1 < nt) {
            const int nxt = cur ^ 1;
            const u8* ap = Ap + (tl + 1) * 64;
            u8* ad = sm8 + nxt * ASTG + arow * RSTR + acb;
            cpasync16(ad, ap); cpasync16(ad + 16, ap + 16);
            const u8* bp = Bp + (tl + 1) * 64;
            u8* bd = sm8 + 2 * ASTG + nxt * ASTG + arow * RSTR + acb;
            cpasync16(bd, bp); cpasync16(bd + 16, bp + 16);
            asm volatile("cp.async.commit_group;");
        }

        const unsigned abase = SMU + cur * ASTG;
        const unsigned bbase = SMU + 2 * ASTG + cur * ASTG;
        #pragma unroll
        for (int kk = 0; kk < 2; kk++) {      // two k32 groups
            unsigned af[4][4], bfr[2][4];
            #pragma unroll
            for (int mi = 0; mi < 4; mi++) {
                unsigned addr = abase +
                    (unsigned)((wm * 64 + mi * 16 + a_r) * RSTR + kk * 32 + a_cB);
                ldsm4(af[mi][0], af[mi][1], af[mi][2], af[mi][3], addr);
            }
            #pragma unroll
            for (int p = 0; p < 2; p++) {
                unsigned addr = bbase +
                    (unsigned)((wn * 32 + p * 16 + b_n) * RSTR + kk * 32 + b_cB);
                ldsm4(bfr[p][0], bfr[p][1], bfr[p][2], bfr[p][3], addr);
            }
            #pragma unroll
            for (int mi = 0; mi < 4; mi++)
                #pragma unroll
                for (int ni = 0; ni < 4; ni++)
                    QMMA(acc[mi][ni], af[mi][0], af[mi][1], af[mi][2], af[mi][3],
                         bfr[ni >> 1][(ni & 1) * 2], bfr[ni >> 1][(ni & 1) * 2 + 1]);
        }
    }

    // ------------- epilogues -------------
    #pragma unroll
    for (int mi = 0; mi < 4; mi++) {
        int row0 = bm + wm * 64 + mi * 16 + g;
        #pragma unroll
        for (int ni = 0; ni < 4; ni++) {
            int nlocal = wn * 32 + ni * 8 + t * 2;
            #pragma unroll
            for (int half = 0; half < 2; half++) {
                int row = row0 + half * 8;
                float a0 = acc[mi][ni][half * 2 + 0];
                float a1 = acc[mi][ni][half * 2 + 1];
                if (EPI == 0) {
                    float b0 = bias[wrow0 + nlocal];
                    float b1 = bias[wrow0 + nlocal + 1];
                    float v0 = fmaf(a0, 1.0f / 64.0f, b0);
                    float v1 = fmaf(a1, 1.0f / 64.0f, b1);
                    if (bx < 4) {
                        int kvcol = bx * 128 + nlocal;           // 0..511
                        bf16* dst = (kvcol >> 8) ? g_vb : g_kb;
                        int ic = kvcol & 255;
                        int bbt = row / SEQ;
                        int s   = row - bbt * SEQ;
                        *(bf162*)(dst + (size_t)bbt * (H * HSTRIDE) + (ic >> 6) * HSTRIDE
                                      + s * DK + (ic & 63)) = __floats2bfloat162_rn(v0, v1);
                    } else {
                        int qcol = (bx - 4) * 128 + nlocal;      // 0..255
                        int bbt = row / S2;
                        int s   = row - bbt * S2;
                        *(bf162*)(g_qb + (size_t)bbt * (H * HST2) + (qcol >> 6) * HST2
                                      + s * DK + (qcol & 63)) = __floats2bfloat162_rn(v0, v1);
                    }
                } else if (EPI == 1) {
                    int col = bx * 128 + nlocal;
                    size_t ro = (size_t)row * 256 + col;
                    float2 bb = *(const float2*)(bias + col);
                    float2 rv = *(const float2*)(res + ro);
                    *(float2*)((float*)Cv0 + ro) = make_float2(
                        fmaf(a0, 1.0f / 64.0f, bb.x + rv.x),
                        fmaf(a1, 1.0f / 64.0f, bb.y + rv.y));
                } else if (EPI == 2) {
                    int col = bx * 128 + nlocal;
                    float2 bb = *(const float2*)(bias + col);
                    float v0 = fmaxf(fmaf(a0, 0.125f, bb.x * 8.0f), 0.f);
                    float v1 = fmaxf(fmaf(a1, 0.125f, bb.y * 8.0f), 0.f);
                    *(unsigned short*)((u8*)Cv0 + (size_t)row * N + col) = f2e4m3x2(v0, v1);
                } else {
                    int col = bx * 128 + nlocal;
                    size_t ro = (size_t)row * 256 + col;
                    float2 bb = *(const float2*)(bias + col);
                    float2 rv = *(const float2*)(res + ro);
                    *(float2*)((float*)Cv0 + ro) = make_float2(
                        fmaf(a0, 1.0f / 512.0f, bb.x + rv.x),
                        fmaf(a1, 1.0f / 512.0f, bb.y + rv.y));
                }
            }
        }
    }
}

// ---------------- tensor-core attention (bf16; fp8 ctx out) ---------------
#define SMQ_B 0
#define SMK_B (64*144)
#define SMV_B (SMK_B + 376*144)
#define SMP_B (SMV_B + 376*144)
#define SMRED_B (SMP_B + 64*752)
#define ATT_SMEM (SMRED_B + 1024)

__global__ __launch_bounds__(256, 1)
void fattn_kernel(const int* __restrict__ src) {
    extern __shared__ unsigned sm32[];
    const unsigned SMU = (unsigned)__cvta_generic_to_shared(sm32);
    unsigned* q32 = sm32;
    unsigned* k32 = sm32 + SMK_B / 4;
    unsigned* v32 = sm32 + SMV_B / 4;
    unsigned* p32 = sm32 + SMP_B / 4;
    float* redm = (float*)(sm32 + SMRED_B / 4);
    float* reds = redm + 128;

    const int bh = blockIdx.x;
    const int b  = bh >> 2;
    const size_t hb = (size_t)bh * HSTRIDE;
    const int tid = threadIdx.x;

    const uint4* gk = (const uint4*)(g_kb + hb);
    const uint4* gv = (const uint4*)(g_vb + hb);
    for (int u = tid; u < 2880; u += 256) {
        int row = u >> 3, c8 = u & 7;
        *(uint4*)&k32[row * 36 + c8 * 4] = gk[u];
        *(uint4*)&v32[row * 36 + c8 * 4] = gv[u];
    }
    for (int u = tid; u < 576; u += 256) {
        int r = 360 + u / 36, c = u - (u / 36) * 36;
        k32[r * 36 + c] = 0u;
        v32[r * 36 + c] = 0u;
    }

    const int lane = tid & 31, wid = tid >> 5;
    const int wq = wid >> 1;
    const int wk = wid & 1;
    const int g = lane >> 2, t = lane & 3;
    const int kb = wk * 184;
    const int r_lo = wq * 16 + g, r_hi = r_lo + 8;
    const int head = bh & 3;
    const uint4* gq = (const uint4*)(g_qb + (size_t)bh * HST2);

    const int a_r = lane & 15;
    const int a_cB = ((lane >> 4) & 1) * 16;
    const int b_n = (lane & 7) + ((lane >> 4) & 1) * 8;
    const int b_cB = ((lane >> 3) & 1) * 16;
    const int vt_r = lane & 15;
    const int vt_cB = ((lane >> 4) & 1) * 16;

    for (int qt = 0; qt < 3; qt++) {
        const int qbase = qt * 64;

        #pragma unroll
        for (int u = tid; u < 512; u += 256) {
            int row = u >> 3, c8 = u & 7;
            *(uint4*)&q32[row * 36 + c8 * 4] = gq[(qbase + row) * 8 + c8];
        }
        __syncthreads();

        float acc[23][4];
        #pragma unroll
        for (int ni = 0; ni < 23; ni++)
            #pragma unroll
            for (int r = 0; r < 4; r++) acc[ni][r] = 0.f;

        #pragma unroll
        for (int kt = 0; kt < 4; kt++) {
            unsigned a0, a1, a2, a3;
            ldsm4(a0, a1, a2, a3,
                  SMU + SMQ_B + (unsigned)((wq * 16 + a_r) * 144 + kt * 32 + a_cB));
            #pragma unroll
            for (int p = 0; p < 12; p++) {
                unsigned b0, b1, b2, b3;
                ldsm4(b0, b1, b2, b3,
                      SMU + SMK_B + (unsigned)((kb + p * 16 + b_n) * 144 + kt * 32 + b_cB));
                BMMA(acc[2 * p], a0, a1, a2, a3, b0, b1);
                if (2 * p + 1 < 23) BMMA(acc[2 * p + 1], a0, a1, a2, a3, b2, b3);
            }
        }

        bool v_lo = (src[b * SEQ + qbase + r_lo] != PADTOK);
        bool v_hi = (src[b * SEQ + qbase + r_hi] != PADTOK);

        float m_lo = -1e30f, m_hi = -1e30f;
        #pragma unroll
        for (int ni = 0; ni < 23; ni++) {
            int col0 = kb + ni * 8 + t * 2;
            bool in0 = col0 < SEQ, in1 = col0 + 1 < SEQ;
            acc[ni][0] = in0 ? (v_lo ? acc[ni][0] : 0.f) : -1e30f;
            acc[ni][1] = in1 ? (v_lo ? acc[ni][1] : 0.f) : -1e30f;
            acc[ni][2] = in0 ? (v_hi ? acc[ni][2] : 0.f) : -1e30f;
            acc[ni][3] = in1 ? (v_hi ? acc[ni][3] : 0.f) : -1e30f;
            m_lo = fmaxf(m_lo, fmaxf(acc[ni][0], acc[ni][1]));
            m_hi = fmaxf(m_hi, fmaxf(acc[ni][2], acc[ni][3]));
        }
        m_lo = fmaxf(m_lo, __shfl_xor_sync(0xffffffffu, m_lo, 1));
        m_lo = fmaxf(m_lo, __shfl_xor_sync(0xffffffffu, m_lo, 2));
        m_hi = fmaxf(m_hi, __shfl_xor_sync(0xffffffffu, m_hi, 1));
        m_hi = fmaxf(m_hi, __shfl_xor_sync(0xffffffffu, m_hi, 2));
        if (t == 0) { redm[wk * 64 + r_lo] = m_lo; redm[wk * 64 + r_hi] = m_hi; }
        __syncthreads();
        m_lo = fmaxf(redm[r_lo], redm[64 + r_lo]);
        m_hi = fmaxf(redm[r_hi], redm[64 + r_hi]);

        float s_lo = 0.f, s_hi = 0.f;
        #pragma unroll
        for (int ni = 0; ni < 23; ni++) {
            acc[ni][0] = __expf(acc[ni][0] - m_lo);
            acc[ni][1] = __expf(acc[ni][1] - m_lo);
            acc[ni][2] = __expf(acc[ni][2] - m_hi);
            acc[ni][3] = __expf(acc[ni][3] - m_hi);
            s_lo += acc[ni][0] + acc[ni][1];
            s_hi += acc[ni][2] + acc[ni][3];
        }
        s_lo += __shfl_xor_sync(0xffffffffu, s_lo, 1);
        s_lo += __shfl_xor_sync(0xffffffffu, s_lo, 2);
        s_hi += __shfl_xor_sync(0xffffffffu, s_hi, 1);
        s_hi += __shfl_xor_sync(0xffffffffu, s_hi, 2);
        if (t == 0) { reds[wk * 64 + r_lo] = s_lo; reds[wk * 64 + r_hi] = s_hi; }
        __syncthreads();
        float inv_lo = 1.f / (reds[r_lo] + reds[64 + r_lo]);
        float inv_hi = 1.f / (reds[r_hi] + reds[64 + r_hi]);

        #pragma unroll
        for (int ni = 0; ni < 23; ni++) {
            int cu = (kb >> 1) + ni * 4 + t;
            bf162 p0 = __floats2bfloat162_rn(acc[ni][0] * inv_lo, acc[ni][1] * inv_lo);
            bf162 p1 = __floats2bfloat162_rn(acc[ni][2] * inv_hi, acc[ni][3] * inv_hi);
            p32[r_lo * 188 + cu] = *(unsigned*)&p0;
            p32[r_hi * 188 + cu] = *(unsigned*)&p1;
        }
        __syncthreads();

        float o[4][4];
        #pragma unroll
        for (int ni = 0; ni < 4; ni++)
            #pragma unroll
            for (int r = 0; r < 4; r++) o[ni][r] = 0.f;

        #pragma unroll
        for (int kt = 0; kt < 23; kt++) {
            unsigned a0, a1, a2, a3;
            ldsm4(a0, a1, a2, a3,
                  SMU + SMP_B + (unsigned)((wq * 16 + a_r) * 752 + kt * 32 + a_cB));
            #pragma unroll
            for (int nb = 0; nb < 2; nb++) {
                unsigned b0, b1, b2, b3;
                ldsm4t(b0, b1, b2, b3,
                       SMU + SMV_B + (unsigned)((kt * 16 + vt_r) * 144
                                                + wk * 64 + nb * 32 + vt_cB));
                BMMA(o[2 * nb],     a0, a1, a2, a3, b0, b1);
                BMMA(o[2 * nb + 1], a0, a1, a2, a3, b2, b3);
            }
        }

        #pragma unroll
        for (int ni = 0; ni < 4; ni++) {
            int col = wk * 32 + ni * 8 + t * 2;
            size_t ob0 = ((size_t)(b * S2 + qbase + r_lo)) * D + head * DK + col;
            size_t ob1 = ((size_t)(b * S2 + qbase + r_hi)) * D + head * DK + col;
            *(unsigned short*)(g_ctx8 + ob0) = f2e4m3x2(o[ni][0], o[ni][1]);
            *(unsigned short*)(g_ctx8 + ob1) = f2e4m3x2(o[ni][2], o[ni][3]);
        }
    }
}

// ---------------- classifier (warp per pair, wl in smem) ------------------
__global__ __launch_bounds__(256)
void cls_kernel(const int* __restrict__ src,
                const float* __restrict__ wl,
                const float* __restrict__ bl,
                float* __restrict__ out) {
    __shared__ float swl[6144];
    int tid = threadIdx.x;
    #pragma unroll
    for (int u = 0; u < 24; u++) swl[u * 256 + tid] = wl[u * 256 + tid];
    __syncthreads();

    int w = tid >> 5, lane = tid & 31;
    int bp = blockIdx.x * 8 + w;
    int b = bp / NPAIR, p = bp - b * NPAIR;

    int i = 0, rem = p;
    while (rem >= 13 - i) { rem -= 13 - i; i++; }
    int j = i + 1 + rem;
    int base = i * 12 - (i * (i - 1)) / 2;
    int pe = base + (j - i) - 1;
    int eb = 28 + 2 * pe;
    int gidx[8] = {2*i, 2*i+1, 2*j, 2*j+1, eb, eb+1, eb+2, eb+3};

    const float* xb = g_xf + (size_t)(b * S2) * D;
    int slots = (j < 13) ? 8 : 4;

    float a0 = 0.f, a1 = 0.f, a2 = 0.f;
    for (int sl = 0; sl < slots; sl++) {
        const float* xr = xb + gidx[sl] * D;
        const float* wr = swl + sl * 768;
        #pragma unroll
        for (int dd = 0; dd < 8; dd++) {
            int dim = lane + dd * 32;
            float xv = xr[dim];
            a0 = fmaf(xv, wr[dim * 3 + 0], a0);
            a1 = fmaf(xv, wr[dim * 3 + 1], a1);
            a2 = fmaf(xv, wr[dim * 3 + 2], a2);
        }
    }
    a0 = warp_sum(a0); a1 = warp_sum(a1); a2 = warp_sum(a2);

    if (lane == 0) {
        const int* sb = src + b * SEQ;
        int ti = sb[2*i], ai = sb[2*i+1], tj = sb[2*j], aj = sb[2*j+1];
        bool c1 = (ai == 2) || (aj == 2);
        bool c2 = (tj == 1) || (ai == 1) || (aj == 1);
        bool c3 = (ti == PADTOK) || (tj == PADTOK) || (ai == 0) || (aj == 0);
        bool c4 = false;
        if (j < 13) {
            int es = 28 + 4 * pe;
            c4 = (sb[es] == 1) || (sb[es+1] == 1) || (sb[es+2] == 1) || (sb[es+3] == 1);
        }
        bool m111 = c3 || c4;
        bool mk1 = m111 || c2;
        bool mk2 = mk1 || c1;
        float* o = out + (size_t)bp * 3;
        o[0] = m111 ? -1e9f : (a0 + bl[0]);
        o[1] = mk1  ? -1e9f : (a1 + bl[1]);
        o[2] = mk2  ? -1e9f : (a2 + bl[2]);
    }
}

// ---------------- launch ----------------
extern "C" void kernel_launch(void* const* d_in, const int* in_sizes, int n_in,
                              void* d_out, int out_size) {
    (void)in_sizes; (void)n_in; (void)out_size;
    const int*   src = (const int*)  d_in[0];
    const float* emb = (const float*)d_in[1];
    const float* wq  = (const float*)d_in[2];
    const float* bq  = (const float*)d_in[3];
    const float* wk  = (const float*)d_in[4];
    const float* bk  = (const float*)d_in[5];
    const float* wv  = (const float*)d_in[6];
    const float* bv  = (const float*)d_in[7];
    const float* wo  = (const float*)d_in[8];
    const float* bo  = (const float*)d_in[9];
    const float* n1a = (const float*)d_in[10];
    const float* n1b = (const float*)d_in[11];
    const float* n2a = (const float*)d_in[12];
    const float* n2b = (const float*)d_in[13];
    const float* w1  = (const float*)d_in[14];
    const float* b1  = (const float*)d_in[15];
    const float* w2  = (const float*)d_in[16];
    const float* b2  = (const float*)d_in[17];
    const float* wl  = (const float*)d_in[18];
    const float* bl  = (const float*)d_in[19];
    float* out = (float*)d_out;

    float *pxc, *py, *pxf, *pbqkv;
    u8 *px18, *pctx8, *px2b8, *phb8, *pwqkv8, *pwo8, *pw18, *pw28;
    cudaGetSymbolAddress((void**)&pxc,    g_xc);
    cudaGetSymbolAddress((void**)&px18,   g_x18);
    cudaGetSymbolAddress((void**)&pctx8,  g_ctx8);
    cudaGetSymbolAddress((void**)&py,     g_y);
    cudaGetSymbolAddress((void**)&px2b8,  g_x2b8);
    cudaGetSymbolAddress((void**)&phb8,   g_hb8);
    cudaGetSymbolAddress((void**)&pxf,    g_xf);
    cudaGetSymbolAddress((void**)&pwqkv8, g_wqkv8);
    cudaGetSymbolAddress((void**)&pwo8,   g_wo8);
    cudaGetSymbolAddress((void**)&pw18,   g_w18);
    cudaGetSymbolAddress((void**)&pw28,   g_w28);
    cudaGetSymbolAddress((void**)&pbqkv,  g_bqkv);

    cudaFuncSetAttribute(fattn_kernel, cudaFuncAttributeMaxDynamicSharedMemorySize,
                         (int)ATT_SMEM);

    convall_kernel<<<5461, 256>>>(wq, wk, wv, wo, w1, w2, bq, bk, bv);
    embed_ln_kernel<<<TOKENS/8, 256>>>(src, emb, n1a, n1b);

    // merged KV (full) + Q (compact) projections
    dim3 gkvq(6, TOKENS / 128);
    q128_kernel<0><<<gkvq, 256, QG_SMEM>>>(px18, pwqkv8, pbqkv, nullptr,
                                           nullptr, TOKENS, 256, D);

    fattn_kernel<<<HEADS, 256, ATT_SMEM>>>(src);

    // WO + residual -> g_y (fp32)
    dim3 gwo(2, M2 / 128);
    q128_kernel<1><<<gwo, 256, QG_SMEM>>>(pctx8, pwo8, bo, pxc, py, M2, 256, D);

    // LN2 -> fp8
    ln2_kernel<<<M2/8, 256>>>(n2a, n2b);

    // FFN
    dim3 gff1(16, M2 / 128);
    q128_kernel<2><<<gff1, 256, QG_SMEM>>>(px2b8, pw18, b1, nullptr, phb8, M2, DFF, D);
    q128_kernel<3><<<gwo, 256, QG_SMEM>>>(phb8, pw28, b2, py, pxf, M2, 256, DFF);

    cls_kernel<<<(BATCH * NPAIR) / 8, 256>>>(src, wl, bl, out);
}

// round 16
// speedup vs baseline: 11.3925x; 1.0433x over previous
#include <cuda_runtime.h>
#include <cuda_bf16.h>
#include <math.h>

// ---------------- problem constants ----------------
#define BATCH   256
#define SEQ     360
#define PREFIX  340
#define D       256
#define H       4
#define DK      64
#define DFF     2048
#define NPAIR   91
#define PADTOK  799
#define TOKENS  (BATCH*SEQ)          // 92160
#define HEADS   (BATCH*H)            // 1024
#define HSTRIDE (SEQ*DK)             // 23040
#define S2      192                  // compact tokens per sequence
#define M2      (BATCH*S2)           // 49152
#define HST2    (S2*DK)              // 12288

typedef __nv_bfloat16 bf16;
typedef __nv_bfloat162 bf162;
typedef unsigned char u8;

// ---------------- scratch (device globals) ----------------
__device__ float g_xc [M2*D];           // residual after embed (compact, fp32)
__device__ u8    g_x18[TOKENS*D];       // LN1 output (full, fp8)
__device__ bf16  g_qb [M2*D];           // Q (B,H,192,64) bf16
__device__ bf16  g_kb [TOKENS*D];       // K (B,H,360,64) bf16
__device__ bf16  g_vb [TOKENS*D];       // V (B,H,360,64) bf16
__device__ u8    g_ctx8[M2*D];          // attention output (compact, fp8)
__device__ float g_y  [M2*D];           // residual after WO (compact, fp32)
__device__ u8    g_x2b8[M2*D];          // LN2 output (compact, fp8)
__device__ u8    g_hb8[M2*DFF];         // ffn hidden (compact, fp8, x8)
__device__ bf16  g_xfb[M2*D];           // final x (compact, bf16)
__device__ float g_pe [PREFIX*D];
__device__ u8    g_wqkv8[3*D*D];        // [768][256]: q(x8) | k(x64) | v(x64)
__device__ u8    g_wo8[D*D];            // x64
__device__ u8    g_w18[DFF*D];          // x64
__device__ u8    g_w28[D*DFF];          // x64
__device__ float g_bqkv[3*D];           // bq*0.125 | bk | bv

// ---------------- helpers ----------------
__device__ __forceinline__ float warp_sum(float v) {
    #pragma unroll
    for (int o = 16; o; o >>= 1) v += __shfl_xor_sync(0xffffffffu, v, o);
    return v;
}

#define BMMA(c, a0, a1, a2, a3, b0, b1)                                        \
    asm volatile(                                                              \
        "mma.sync.aligned.m16n8k16.row.col.f32.bf16.bf16.f32 "                 \
        "{%0,%1,%2,%3}, {%4,%5,%6,%7}, {%8,%9}, {%0,%1,%2,%3};"                \
        : "+f"(c[0]), "+f"(c[1]), "+f"(c[2]), "+f"(c[3])                       \
        : "r"(a0), "r"(a1), "r"(a2), "r"(a3), "r"(b0), "r"(b1))

#define QMMA(c, a0, a1, a2, a3, b0, b1)                                        \
    asm volatile(                                                              \
        "mma.sync.aligned.m16n8k32.row.col.f32.e4m3.e4m3.f32 "                 \
        "{%0,%1,%2,%3}, {%4,%5,%6,%7}, {%8,%9}, {%0,%1,%2,%3};"                \
        : "+f"(c[0]), "+f"(c[1]), "+f"(c[2]), "+f"(c[3])                       \
        : "r"(a0), "r"(a1), "r"(a2), "r"(a3), "r"(b0), "r"(b1))

__device__ __forceinline__ void ldsm4(unsigned &r0, unsigned &r1,
                                      unsigned &r2, unsigned &r3, unsigned addr) {
    asm volatile("ldmatrix.sync.aligned.m8n8.x4.shared.b16 {%0,%1,%2,%3}, [%4];"
        : "=r"(r0), "=r"(r1), "=r"(r2), "=r"(r3) : "r"(addr));
}
__device__ __forceinline__ void ldsm4t(unsigned &r0, unsigned &r1,
                                       unsigned &r2, unsigned &r3, unsigned addr) {
    asm volatile("ldmatrix.sync.aligned.m8n8.x4.trans.shared.b16 {%0,%1,%2,%3}, [%4];"
        : "=r"(r0), "=r"(r1), "=r"(r2), "=r"(r3) : "r"(addr));
}
__device__ __forceinline__ void cpasync16(void* sdst, const void* gsrc) {
    unsigned s = (unsigned)__cvta_generic_to_shared(sdst);
    asm volatile("cp.async.cg.shared.global [%0], [%1], 16;" :: "r"(s), "l"(gsrc));
}
__device__ __forceinline__ u8 f2e4m3(float v) {
    unsigned short t;
    asm("cvt.rn.satfinite.e4m3x2.f32 %0, %1, %2;" : "=h"(t) : "f"(0.f), "f"(v));
    return (u8)t;
}
__device__ __forceinline__ unsigned short f2e4m3x2(float lo, float hi) {
    unsigned short t;
    asm("cvt.rn.satfinite.e4m3x2.f32 %0, %1, %2;" : "=h"(t) : "f"(hi), "f"(lo));
    return t;
}

// ---------------- convall: weights (fp8) + PE + bias pack -----------------
__global__ void convall_kernel(const float* __restrict__ wq, const float* __restrict__ wk,
                               const float* __restrict__ wv, const float* __restrict__ wo,
                               const float* __restrict__ w1, const float* __restrict__ w2,
                               const float* __restrict__ bq, const float* __restrict__ bk,
                               const float* __restrict__ bv) {
    int bid = blockIdx.x, tid = threadIdx.x;
    if (bid < 768) {
        int m = bid >> 8;
        int idx = ((bid & 255) << 8) + tid;
        int k = idx >> 8, n = idx & 255;
        if (m == 0)      g_wqkv8[n * 256 + k]             = f2e4m3(wq[idx] * 8.0f);
        else if (m == 1) g_wqkv8[(256 + n) * 256 + k]     = f2e4m3(wk[idx] * 64.0f);
        else             g_wqkv8[(512 + n) * 256 + k]     = f2e4m3(wv[idx] * 64.0f);
    } else if (bid < 1024) {
        int idx = ((bid - 768) << 8) + tid;
        int k = idx >> 8, n = idx & 255;
        g_wo8[n * 256 + k] = f2e4m3(wo[idx] * 64.0f);
    } else if (bid < 3072) {
        int idx = (bid - 1024) * 256 + tid;
        int k = idx >> 11, n = idx & 2047;
        g_w18[n * 256 + k] = f2e4m3(w1[idx] * 64.0f);
    } else if (bid < 5120) {
        int idx = (bid - 3072) * 256 + tid;
        int k = idx >> 8, n = idx & 255;
        g_w28[(size_t)n * 2048 + k] = f2e4m3(w2[idx] * 64.0f);
    } else if (bid < 5460) {
        int s = bid - 5120, d = tid;
        float ex  = exp2f(-13.287712379549449f * ((float)d) * (1.0f / 128.0f));
        float arg = (float)s * ex;
        g_pe[s * D + d] = (d & 1) ? cosf(arg) : sinf(arg);
    } else {
        g_bqkv[tid]       = bq[tid] * 0.125f;
        g_bqkv[tid + 256] = bk[tid];
        g_bqkv[tid + 512] = bv[tid];
    }
}

// ---------------- fused embedding + scale + PE + LN1 (warp per token) -----
__global__ void embed_ln_kernel(const int* __restrict__ src,
                                const float* __restrict__ emb,
                                const float* __restrict__ ga,
                                const float* __restrict__ gb) {
    int w = threadIdx.x >> 5, lane = threadIdx.x & 31;
    int t = blockIdx.x * 8 + w;
    int tok = src[t];
    int b = t / SEQ;
    int s = t - b * SEQ;
    const float4* er = (const float4*)(emb + (size_t)tok * D);
    float4 a = er[lane * 2], bb = er[lane * 2 + 1];
    if (s < PREFIX) {
        const float4* pr = (const float4*)(g_pe + s * D);
        float4 p = pr[lane * 2], q = pr[lane * 2 + 1];
        a.x = fmaf(a.x, 16.f, p.x); a.y = fmaf(a.y, 16.f, p.y);
        a.z = fmaf(a.z, 16.f, p.z); a.w = fmaf(a.w, 16.f, p.w);
        bb.x = fmaf(bb.x, 16.f, q.x); bb.y = fmaf(bb.y, 16.f, q.y);
        bb.z = fmaf(bb.z, 16.f, q.z); bb.w = fmaf(bb.w, 16.f, q.w);
    }
    if (s < S2) {
        size_t co = ((size_t)(b * S2 + s)) * D + lane * 8;
        *(float4*)(g_xc + co)     = a;
        *(float4*)(g_xc + co + 4) = bb;
    }

    float sum = a.x + a.y + a.z + a.w + bb.x + bb.y + bb.z + bb.w;
    float mu = warp_sum(sum) * (1.0f / 256.0f);
    float dx[8] = {a.x - mu, a.y - mu, a.z - mu, a.w - mu,
                   bb.x - mu, bb.y - mu, bb.z - mu, bb.w - mu};
    float ss = 0.f;
    #pragma unroll
    for (int i = 0; i < 8; i++) ss = fmaf(dx[i], dx[i], ss);
    float inv = 1.0f / (sqrtf(warp_sum(ss) * (1.0f / 255.0f)) + 1e-6f);

    const float4* gav = (const float4*)(ga + lane * 8);
    const float4* gbv = (const float4*)(gb + lane * 8);
    float4 g0 = gav[0], g1 = gav[1], h0 = gbv[0], h1 = gbv[1];
    float y0 = fmaf(g0.x, dx[0]*inv, h0.x), y1 = fmaf(g0.y, dx[1]*inv, h0.y);
    float y2 = fmaf(g0.z, dx[2]*inv, h0.z), y3 = fmaf(g0.w, dx[3]*inv, h0.w);
    float y4 = fmaf(g1.x, dx[4]*inv, h1.x), y5 = fmaf(g1.y, dx[5]*inv, h1.y);
    float y6 = fmaf(g1.z, dx[6]*inv, h1.z), y7 = fmaf(g1.w, dx[7]*inv, h1.w);
    unsigned s0 = f2e4m3x2(y0, y1), s1 = f2e4m3x2(y2, y3);
    unsigned s2 = f2e4m3x2(y4, y5), s3 = f2e4m3x2(y6, y7);
    uint2 pk;
    pk.x = s0 | (s1 << 16);
    pk.y = s2 | (s3 << 16);
    *(uint2*)(g_x18 + (size_t)t * D + lane * 8) = pk;
}

// ---------------- layernorm 2 (warp per token, fp32 -> fp8) ---------------
__global__ void ln2_kernel(const float* __restrict__ ga, const float* __restrict__ gb) {
    int w = threadIdx.x >> 5, lane = threadIdx.x & 31;
    int t = blockIdx.x * 8 + w;
    size_t off = (size_t)t * D + lane * 8;
    float4 a = *(const float4*)(g_y + off);
    float4 b = *(const float4*)(g_y + off + 4);

    float sum = a.x + a.y + a.z + a.w + b.x + b.y + b.z + b.w;
    float mu = warp_sum(sum) * (1.0f / 256.0f);
    float dx[8] = {a.x - mu, a.y - mu, a.z - mu, a.w - mu,
                   b.x - mu, b.y - mu, b.z - mu, b.w - mu};
    float ss = 0.f;
    #pragma unroll
    for (int i = 0; i < 8; i++) ss = fmaf(dx[i], dx[i], ss);
    float inv = 1.0f / (sqrtf(warp_sum(ss) * (1.0f / 255.0f)) + 1e-6f);

    const float4* gav = (const float4*)(ga + lane * 8);
    const float4* gbv = (const float4*)(gb + lane * 8);
    float4 g0 = gav[0], g1 = gav[1], h0 = gbv[0], h1 = gbv[1];
    float y0 = fmaf(g0.x, dx[0]*inv, h0.x), y1 = fmaf(g0.y, dx[1]*inv, h0.y);
    float y2 = fmaf(g0.z, dx[2]*inv, h0.z), y3 = fmaf(g0.w, dx[3]*inv, h0.w);
    float y4 = fmaf(g1.x, dx[4]*inv, h1.x), y5 = fmaf(g1.y, dx[5]*inv, h1.y);
    float y6 = fmaf(g1.z, dx[6]*inv, h1.z), y7 = fmaf(g1.w, dx[7]*inv, h1.w);
    unsigned s0 = f2e4m3x2(y0, y1), s1 = f2e4m3x2(y2, y3);
    unsigned s2 = f2e4m3x2(y4, y5), s3 = f2e4m3x2(y6, y7);
    uint2 pk;
    pk.x = s0 | (s1 << 16);
    pk.y = s2 | (s3 << 16);
    *(uint2*)(g_x2b8 + off) = pk;
}

// ---------------- universal fp8 GEMM: CTA 128x128, warp 64x32, KT=64 ------
// EPI 0: merged KVQ -> bf16 scatter. blockIdx.x: 0-3 K/V (full M), 4-5 Q (compact).
// EPI 1: WO   -> fp32 g_y = res + acc/64 + bias
// EPI 2: FFN1 -> fp8 hidden = relu(acc/64 + b1) * 8
// EPI 3: FFN2 -> bf16 out = res + acc/512 + b2
#define RSTR 80
#define ASTG (128*RSTR)
#define QG_SMEM (4*ASTG)

template<int EPI>
__global__ __launch_bounds__(256, 2)
void q128_kernel(const u8* __restrict__ A, const u8* __restrict__ Wt,
                 const float* __restrict__ bias, const float* __restrict__ res,
                 void* __restrict__ Cv0, int M, int N, int K) {
    const int bx = blockIdx.x;
    if (EPI == 0 && bx >= 4 && blockIdx.y >= 384) return;

    extern __shared__ u8 sm8[];
    const unsigned SMU = (unsigned)__cvta_generic_to_shared(sm8);

    const int tid  = threadIdx.x;
    const int lane = tid & 31;
    const int wid  = tid >> 5;
    const int wm = wid >> 2;
    const int wn = wid & 3;
    const int g = lane >> 2;
    const int t = lane & 3;

    const int bm = blockIdx.y * 128;
    const int wrow0 = (EPI == 0) ? ((bx < 4) ? 256 + bx * 128 : (bx - 4) * 128)
                                 : bx * 128;

    const int arow = tid >> 1;
    const int acb  = (tid & 1) * 32;
    int garow = bm + arow;
    if (EPI == 0 && bx >= 4) { int bb = garow / S2; garow = bb * SEQ + (garow - bb * S2); }
    const u8* Ap = A  + (size_t)garow * K + acb;
    const u8* Bp = Wt + (size_t)(wrow0 + arow) * K + acb;

    const int a_r  = lane & 15;
    const int a_cB = ((lane >> 4) & 1) * 16;
    const int b_n  = (lane & 7) + ((lane >> 4) & 1) * 8;
    const int b_cB = ((lane >> 3) & 1) * 16;

    float acc[4][4][4];
    #pragma unroll
    for (int mi = 0; mi < 4; mi++)
        #pragma unroll
        for (int ni = 0; ni < 4; ni++)
            #pragma unroll
            for (int r = 0; r < 4; r++) acc[mi][ni][r] = 0.f;

    const int nt = K >> 6;
    {
        u8* ad = sm8 + arow * RSTR + acb;
        cpasync16(ad, Ap); cpasync16(ad + 16, Ap + 16);
        u8* bd = sm8 + 2 * ASTG + arow * RSTR + acb;
        cpasync16(bd, Bp); cpasync16(bd + 16, Bp + 16);
    }
    asm volatile("cp.async.commit_group;");

    for (int tl = 0; tl < nt; tl++) {
        const int cur = tl & 1;
        asm volatile("cp.async.wait_group 0;" ::: "memory");
        __syncthreads();
        if (tl + 1 < nt) {
            const int nxt = cur ^ 1;
            const u8* ap = Ap + (tl + 1) * 64;
            u8* ad = sm8 + nxt * ASTG + arow * RSTR + acb;
            cpasync16(ad, ap); cpasync16(ad + 16, ap + 16);
            const u8* bp = Bp + (tl + 1) * 64;
            u8* bd = sm8 + 2 * ASTG + nxt * ASTG + arow * RSTR + acb;
            cpasync16(bd, bp); cpasync16(bd + 16, bp + 16);
            asm volatile("cp.async.commit_group;");
        }

        const unsigned abase = SMU + cur * ASTG;
        const unsigned bbase = SMU + 2 * ASTG + cur * ASTG;
        #pragma unroll
        for (int kk = 0; kk < 2; kk++) {
            unsigned af[4][4], bfr[2][4];
            #pragma unroll
            for (int mi = 0; mi < 4; mi++) {
                unsigned addr = abase +
                    (unsigned)((wm * 64 + mi * 16 + a_r) * RSTR + kk * 32 + a_cB);
                ldsm4(af[mi][0], af[mi][1], af[mi][2], af[mi][3], addr);
            }
            #pragma unroll
            for (int p = 0; p < 2; p++) {
                unsigned addr = bbase +
                    (unsigned)((wn * 32 + p * 16 + b_n) * RSTR + kk * 32 + b_cB);
                ldsm4(bfr[p][0], bfr[p][1], bfr[p][2], bfr[p][3], addr);
            }
            #pragma unroll
            for (int mi = 0; mi < 4; mi++)
                #pragma unroll
                for (int ni = 0; ni < 4; ni++)
                    QMMA(acc[mi][ni], af[mi][0], af[mi][1], af[mi][2], af[mi][3],
                         bfr[ni >> 1][(ni & 1) * 2], bfr[ni >> 1][(ni & 1) * 2 + 1]);
        }
    }

    #pragma unroll
    for (int mi = 0; mi < 4; mi++) {
        int row0 = bm + wm * 64 + mi * 16 + g;
        #pragma unroll
        for (int ni = 0; ni < 4; ni++) {
            int nlocal = wn * 32 + ni * 8 + t * 2;
            #pragma unroll
            for (int half = 0; half < 2; half++) {
                int row = row0 + half * 8;
                float a0 = acc[mi][ni][half * 2 + 0];
                float a1 = acc[mi][ni][half * 2 + 1];
                if (EPI == 0) {
                    float b0 = bias[wrow0 + nlocal];
                    float b1 = bias[wrow0 + nlocal + 1];
                    float v0 = fmaf(a0, 1.0f / 64.0f, b0);
                    float v1 = fmaf(a1, 1.0f / 64.0f, b1);
                    if (bx < 4) {
                        int kvcol = bx * 128 + nlocal;
                        bf16* dst = (kvcol >> 8) ? g_vb : g_kb;
                        int ic = kvcol & 255;
                        int bbt = row / SEQ;
                        int s   = row - bbt * SEQ;
                        *(bf162*)(dst + (size_t)bbt * (H * HSTRIDE) + (ic >> 6) * HSTRIDE
                                      + s * DK + (ic & 63)) = __floats2bfloat162_rn(v0, v1);
                    } else {
                        int qcol = (bx - 4) * 128 + nlocal;
                        int bbt = row / S2;
                        int s   = row - bbt * S2;
                        *(bf162*)(g_qb + (size_t)bbt * (H * HST2) + (qcol >> 6) * HST2
                                      + s * DK + (qcol & 63)) = __floats2bfloat162_rn(v0, v1);
                    }
                } else if (EPI == 1) {
                    int col = bx * 128 + nlocal;
                    size_t ro = (size_t)row * 256 + col;
                    float2 bb = *(const float2*)(bias + col);
                    float2 rv = *(const float2*)(res + ro);
                    *(float2*)((float*)Cv0 + ro) = make_float2(
                        fmaf(a0, 1.0f / 64.0f, bb.x + rv.x),
                        fmaf(a1, 1.0f / 64.0f, bb.y + rv.y));
                } else if (EPI == 2) {
                    int col = bx * 128 + nlocal;
                    float2 bb = *(const float2*)(bias + col);
                    float v0 = fmaxf(fmaf(a0, 0.125f, bb.x * 8.0f), 0.f);
                    float v1 = fmaxf(fmaf(a1, 0.125f, bb.y * 8.0f), 0.f);
                    *(unsigned short*)((u8*)Cv0 + (size_t)row * N + col) = f2e4m3x2(v0, v1);
                } else {
                    int col = bx * 128 + nlocal;
                    size_t ro = (size_t)row * 256 + col;
                    float2 bb = *(const float2*)(bias + col);
                    float2 rv = *(const float2*)(res + ro);
                    *(bf162*)((bf16*)Cv0 + ro) = __floats2bfloat162_rn(
                        fmaf(a0, 1.0f / 512.0f, bb.x + rv.x),
                        fmaf(a1, 1.0f / 512.0f, bb.y + rv.y));
                }
            }
        }
    }
}

// ---------------- attention v2: 512 threads, 4 q-subtiles x 4 key-quarters
// smem (bytes): Q 64x128 swz | K 384x128 swz | V 384x128 swz | P 64x784 | red 2KB
#define SQ_B 0
#define SK_B 8192
#define SV_B (SK_B + 384*128)     // 57344
#define SP_B (SV_B + 384*128)     // 106496
#define RED_B (SP_B + 64*784)     // 156672
#define ATT2_SMEM (RED_B + 2048)  // 158720

__global__ __launch_bounds__(512, 1)
void fattn2_kernel(const int* __restrict__ src) {
    extern __shared__ u8 sm8[];
    const unsigned SMU = (unsigned)__cvta_generic_to_shared(sm8);
    unsigned* sP = (unsigned*)(sm8 + SP_B);
    float* redm = (float*)(sm8 + RED_B);       // [4][64]
    float* reds = redm + 256;                  // [4][64]

    const int bh = blockIdx.x;
    const int b  = bh >> 2;
    const int head = bh & 3;
    const size_t hb = (size_t)bh * HSTRIDE;
    const int tid = threadIdx.x;

    // ---- K/V loads (cp.async, swizzled) ----
    const u8* kp = (const u8*)(g_kb + hb);
    const u8* vp = (const u8*)(g_vb + hb);
    for (int u = tid; u < 2880; u += 512) {
        int row = u >> 3, c16 = u & 7;
        int sw = (c16 ^ (row & 7)) << 4;
        cpasync16(sm8 + SK_B + row * 128 + sw, kp + u * 16);
        cpasync16(sm8 + SV_B + row * 128 + sw, vp + u * 16);
    }
    asm volatile("cp.async.commit_group;");
    // zero V pad rows 360..383 (K pads masked by index, stay garbage)
    for (int u = tid; u < 192; u += 512) {
        int row = 360 + (u >> 3), c16 = u & 7;
        *(uint4*)(sm8 + SV_B + row * 128 + ((c16 ^ (row & 7)) << 4)) =
            make_uint4(0u, 0u, 0u, 0u);
    }

    const int lane = tid & 31, wid = tid >> 5;
    const int wq = wid >> 2;                  // 0..3 q-subtile
    const int wk = wid & 3;                   // 0..3 key-quarter
    const int g = lane >> 2, t = lane & 3;
    const int kq = wk * 96;
    const int r_lo = wq * 16 + g, r_hi = r_lo + 8;

    const int a_r  = lane & 15;
    const int a_cB = ((lane >> 4) & 1) * 16;
    const int b_n  = (lane & 7) + ((lane >> 4) & 1) * 8;
    const int b_cB = ((lane >> 3) & 1) * 16;
    const int vt_r = lane & 15;
    const int vt_cB = ((lane >> 4) & 1) * 16;

    const u8* qp = (const u8*)(g_qb + (size_t)bh * HST2);

    for (int qt = 0; qt < 3; qt++) {
        const int qbase = qt * 64;

        // ---- Q tile load (512 16B units = 1/thread) ----
        {
            int row = tid >> 3, c16 = tid & 7;
            cpasync16(sm8 + SQ_B + row * 128 + ((c16 ^ (row & 7)) << 4),
                      qp + (size_t)(qbase + row) * 128 + c16 * 16);
        }
        asm volatile("cp.async.commit_group;");
        asm volatile("cp.async.wait_group 0;" ::: "memory");
        __syncthreads();

        // ---- S = Q K^T (warp: 16 q x 96 keys) ----
        float acc[12][4];
        #pragma unroll
        for (int ni = 0; ni < 12; ni++)
            #pragma unroll
            for (int r = 0; r < 4; r++) acc[ni][r] = 0.f;

        #pragma unroll
        for (int kt = 0; kt < 4; kt++) {
            int arow = wq * 16 + a_r;
            int acol = kt * 32 + a_cB;
            unsigned a0, a1, a2, a3;
            ldsm4(a0, a1, a2, a3, SMU + SQ_B + arow * 128 +
                  ((((acol >> 4) ^ (arow & 7))) << 4));
            #pragma unroll
            for (int p = 0; p < 6; p++) {
                int brow = kq + p * 16 + b_n;
                int bcol = kt * 32 + b_cB;
                unsigned b0, b1, b2, b3;
                ldsm4(b0, b1, b2, b3, SMU + SK_B + brow * 128 +
                      ((((bcol >> 4) ^ (brow & 7))) << 4));
                BMMA(acc[2 * p],     a0, a1, a2, a3, b0, b1);
                BMMA(acc[2 * p + 1], a0, a1, a2, a3, b2, b3);
            }
        }

        // ---- mask + softmax (cross 4 quarters via smem) ----
        bool v_lo = (src[b * SEQ + qbase + r_lo] != PADTOK);
        bool v_hi = (src[b * SEQ + qbase + r_hi] != PADTOK);

        float m_lo = -1e30f, m_hi = -1e30f;
        #pragma unroll
        for (int ni = 0; ni < 12; ni++) {
            int col0 = kq + ni * 8 + t * 2;
            bool in0 = col0 < SEQ, in1 = col0 + 1 < SEQ;
            acc[ni][0] = in0 ? (v_lo ? acc[ni][0] : 0.f) : -1e30f;
            acc[ni][1] = in1 ? (v_lo ? acc[ni][1] : 0.f) : -1e30f;
            acc[ni][2] = in0 ? (v_hi ? acc[ni][2] : 0.f) : -1e30f;
            acc[ni][3] = in1 ? (v_hi ? acc[ni][3] : 0.f) : -1e30f;
            m_lo = fmaxf(m_lo, fmaxf(acc[ni][0], acc[ni][1]));
            m_hi = fmaxf(m_hi, fmaxf(acc[ni][2], acc[ni][3]));
        }
        m_lo = fmaxf(m_lo, __shfl_xor_sync(0xffffffffu, m_lo, 1));
        m_lo = fmaxf(m_lo, __shfl_xor_sync(0xffffffffu, m_lo, 2));
        m_hi = fmaxf(m_hi, __shfl_xor_sync(0xffffffffu, m_hi, 1));
        m_hi = fmaxf(m_hi, __shfl_xor_sync(0xffffffffu, m_hi, 2));
        if (t == 0) { redm[wk * 64 + r_lo] = m_lo; redm[wk * 64 + r_hi] = m_hi; }
        __syncthreads();
        m_lo = fmaxf(fmaxf(redm[r_lo], redm[64 + r_lo]),
                     fmaxf(redm[128 + r_lo], redm[192 + r_lo]));
        m_hi = fmaxf(fmaxf(redm[r_hi], redm[64 + r_hi]),
                     fmaxf(redm[128 + r_hi], redm[192 + r_hi]));

        float s_lo = 0.f, s_hi = 0.f;
        #pragma unroll
        for (int ni = 0; ni < 12; ni++) {
            acc[ni][0] = __expf(acc[ni][0] - m_lo);
            acc[ni][1] = __expf(acc[ni][1] - m_lo);
            acc[ni][2] = __expf(acc[ni][2] - m_hi);
            acc[ni][3] = __expf(acc[ni][3] - m_hi);
            s_lo += acc[ni][0] + acc[ni][1];
            s_hi += acc[ni][2] + acc[ni][3];
        }
        s_lo += __shfl_xor_sync(0xffffffffu, s_lo, 1);
        s_lo += __shfl_xor_sync(0xffffffffu, s_lo, 2);
        s_hi += __shfl_xor_sync(0xffffffffu, s_hi, 1);
        s_hi += __shfl_xor_sync(0xffffffffu, s_hi, 2);
        if (t == 0) { reds[wk * 64 + r_lo] = s_lo; reds[wk * 64 + r_hi] = s_hi; }
        __syncthreads();
        float inv_lo = 1.f / (reds[r_lo] + reds[64 + r_lo] +
                              reds[128 + r_lo] + reds[192 + r_lo]);
        float inv_hi = 1.f / (reds[r_hi] + reds[64 + r_hi] +
                              reds[128 + r_hi] + reds[192 + r_hi]);

        // ---- write P (bf16, row stride 784B = 196 u32) ----
        #pragma unroll
        for (int ni = 0; ni < 12; ni++) {
            int cu = wk * 48 + ni * 4 + t;
            bf162 p0 = __floats2bfloat162_rn(acc[ni][0] * inv_lo, acc[ni][1] * inv_lo);
            bf162 p1 = __floats2bfloat162_rn(acc[ni][2] * inv_hi, acc[ni][3] * inv_hi);
            sP[r_lo * 196 + cu] = *(unsigned*)&p0;
            sP[r_hi * 196 + cu] = *(unsigned*)&p1;
        }
        __syncthreads();

        // ---- O = P @ V (warp: 16 q x 16 dk, k = 384 keys) ----
        float o[2][4];
        #pragma unroll
        for (int ni = 0; ni < 2; ni++)
            #pragma unroll
            for (int r = 0; r < 4; r++) o[ni][r] = 0.f;

        #pragma unroll
        for (int kt = 0; kt < 24; kt++) {
            unsigned a0, a1, a2, a3;
            ldsm4(a0, a1, a2, a3,
                  SMU + SP_B + (unsigned)((wq * 16 + a_r) * 784 + kt * 32 + a_cB));
            int vrow = kt * 16 + vt_r;
            int vcol = wk * 32 + vt_cB;
            unsigned b0, b1, b2, b3;
            ldsm4t(b0, b1, b2, b3, SMU + SV_B + vrow * 128 +
                   ((((vcol >> 4) ^ (vrow & 7))) << 4));
            BMMA(o[0], a0, a1, a2, a3, b0, b1);
            BMMA(o[1], a0, a1, a2, a3, b2, b3);
        }

        #pragma unroll
        for (int ni = 0; ni < 2; ni++) {
            int col = wk * 16 + ni * 8 + t * 2;
            size_t ob0 = ((size_t)(b * S2 + qbase + r_lo)) * D + head * DK + col;
            size_t ob1 = ((size_t)(b * S2 + qbase + r_hi)) * D + head * DK + col;
            *(unsigned short*)(g_ctx8 + ob0) = f2e4m3x2(o[ni][0], o[ni][1]);
            *(unsigned short*)(g_ctx8 + ob1) = f2e4m3x2(o[ni][2], o[ni][3]);
        }
    }
}

// ---------------- classifier (warp per pair, wl in smem, bf16 x) ----------
__global__ __launch_bounds__(256)
void cls_kernel(const int* __restrict__ src,
                const float* __restrict__ wl,
                const float* __restrict__ bl,
                float* __restrict__ out) {
    __shared__ float swl[6144];
    int tid = threadIdx.x;
    #pragma unroll
    for (int u = 0; u < 24; u++) swl[u * 256 + tid] = wl[u * 256 + tid];
    __syncthreads();

    int w = tid >> 5, lane = tid & 31;
    int bp = blockIdx.x * 8 + w;
    int b = bp / NPAIR, p = bp - b * NPAIR;

    int i = 0, rem = p;
    while (rem >= 13 - i) { rem -= 13 - i; i++; }
    int j = i + 1 + rem;
    int base = i * 12 - (i * (i - 1)) / 2;
    int pe = base + (j - i) - 1;
    int eb = 28 + 2 * pe;
    int gidx[8] = {2*i, 2*i+1, 2*j, 2*j+1, eb, eb+1, eb+2, eb+3};

    const bf16* xb = g_xfb + (size_t)(b * S2) * D;
    int slots = (j < 13) ? 8 : 4;

    float a0 = 0.f, a1 = 0.f, a2 = 0.f;
    for (int sl = 0; sl < slots; sl++) {
        const bf16* xr = xb + gidx[sl] * D;
        const float* wr = swl + sl * 768;
        #pragma unroll
        for (int dd = 0; dd < 4; dd++) {
            int dim = lane * 2 + dd * 64;
            bf162 xv2 = *(const bf162*)(xr + dim);
            float x0 = __bfloat162float(xv2.x);
            float x1 = __bfloat162float(xv2.y);
            a0 = fmaf(x0, wr[dim * 3 + 0], fmaf(x1, wr[dim * 3 + 3], a0));
            a1 = fmaf(x0, wr[dim * 3 + 1], fmaf(x1, wr[dim * 3 + 4], a1));
            a2 = fmaf(x0, wr[dim * 3 + 2], fmaf(x1, wr[dim * 3 + 5], a2));
        }
    }
    a0 = warp_sum(a0); a1 = warp_sum(a1); a2 = warp_sum(a2);

    if (lane == 0) {
        const int* sb = src + b * SEQ;
        int ti = sb[2*i], ai = sb[2*i+1], tj = sb[2*j], aj = sb[2*j+1];
        bool c1 = (ai == 2) || (aj == 2);
        bool c2 = (tj == 1) || (ai == 1) || (aj == 1);
        bool c3 = (ti == PADTOK) || (tj == PADTOK) || (ai == 0) || (aj == 0);
        bool c4 = false;
        if (j < 13) {
            int es = 28 + 4 * pe;
            c4 = (sb[es] == 1) || (sb[es+1] == 1) || (sb[es+2] == 1) || (sb[es+3] == 1);
        }
        bool m111 = c3 || c4;
        bool mk1 = m111 || c2;
        bool mk2 = mk1 || c1;
        float* o = out + (size_t)bp * 3;
        o[0] = m111 ? -1e9f : (a0 + bl[0]);
        o[1] = mk1  ? -1e9f : (a1 + bl[1]);
        o[2] = mk2  ? -1e9f : (a2 + bl[2]);
    }
}

// ---------------- launch ----------------
extern "C" void kernel_launch(void* const* d_in, const int* in_sizes, int n_in,
                              void* d_out, int out_size) {
    (void)in_sizes; (void)n_in; (void)out_size;
    const int*   src = (const int*)  d_in[0];
    const float* emb = (const float*)d_in[1];
    const float* wq  = (const float*)d_in[2];
    const float* bq  = (const float*)d_in[3];
    const float* wk  = (const float*)d_in[4];
    const float* bk  = (const float*)d_in[5];
    const float* wv  = (const float*)d_in[6];
    const float* bv  = (const float*)d_in[7];
    const float* wo  = (const float*)d_in[8];
    const float* bo  = (const float*)d_in[9];
    const float* n1a = (const float*)d_in[10];
    const float* n1b = (const float*)d_in[11];
    const float* n2a = (const float*)d_in[12];
    const float* n2b = (const float*)d_in[13];
    const float* w1  = (const float*)d_in[14];
    const float* b1  = (const float*)d_in[15];
    const float* w2  = (const float*)d_in[16];
    const float* b2  = (const float*)d_in[17];
    const float* wl  = (const float*)d_in[18];
    const float* bl  = (const float*)d_in[19];
    float* out = (float*)d_out;

    float *pxc, *py, *pbqkv;
    bf16 *pxfb;
    u8 *px18, *pctx8, *px2b8, *phb8, *pwqkv8, *pwo8, *pw18, *pw28;
    cudaGetSymbolAddress((void**)&pxc,    g_xc);
    cudaGetSymbolAddress((void**)&px18,   g_x18);
    cudaGetSymbolAddress((void**)&pctx8,  g_ctx8);
    cudaGetSymbolAddress((void**)&py,     g_y);
    cudaGetSymbolAddress((void**)&px2b8,  g_x2b8);
    cudaGetSymbolAddress((void**)&phb8,   g_hb8);
    cudaGetSymbolAddress((void**)&pxfb,   g_xfb);
    cudaGetSymbolAddress((void**)&pwqkv8, g_wqkv8);
    cudaGetSymbolAddress((void**)&pwo8,   g_wo8);
    cudaGetSymbolAddress((void**)&pw18,   g_w18);
    cudaGetSymbolAddress((void**)&pw28,   g_w28);
    cudaGetSymbolAddress((void**)&pbqkv,  g_bqkv);

    cudaFuncSetAttribute(fattn2_kernel, cudaFuncAttributeMaxDynamicSharedMemorySize,
                         (int)ATT2_SMEM);

    convall_kernel<<<5461, 256>>>(wq, wk, wv, wo, w1, w2, bq, bk, bv);
    embed_ln_kernel<<<TOKENS/8, 256>>>(src, emb, n1a, n1b);

    // merged KV (full) + Q (compact) projections
    dim3 gkvq(6, TOKENS / 128);
    q128_kernel<0><<<gkvq, 256, QG_SMEM>>>(px18, pwqkv8, pbqkv, nullptr,
                                           nullptr, TOKENS, 256, D);

    fattn2_kernel<<<HEADS, 512, ATT2_SMEM>>>(src);

    // WO + residual -> g_y (fp32)
    dim3 gwo(2, M2 / 128);
    q128_kernel<1><<<gwo, 256, QG_SMEM>>>(pctx8, pwo8, bo, pxc, py, M2, 256, D);

    // LN2 -> fp8
    ln2_kernel<<<M2/8, 256>>>(n2a, n2b);

    // FFN
    dim3 gff1(16, M2 / 128);
    q128_kernel<2><<<gff1, 256, QG_SMEM>>>(px2b8, pw18, b1, nullptr, phb8, M2, DFF, D);
    q128_kernel<3><<<gwo, 256, QG_SMEM>>>(phb8, pw28, b2, py, pxfb, M2, 256, DFF);

    cls_kernel<<<(BATCH * NPAIR) / 8, 256>>>(src, wl, bl, out);
}

// round 17
// speedup vs baseline: 11.4828x; 1.0079x over previous
#include <cuda_runtime.h>
#include <cuda_bf16.h>
#include <math.h>

// ---------------- problem constants ----------------
#define BATCH   256
#define SEQ     360
#define PREFIX  340
#define D       256
#define H       4
#define DK      64
#define DFF     2048
#define NPAIR   91
#define PADTOK  799
#define TOKENS  (BATCH*SEQ)          // 92160
#define HEADS   (BATCH*H)            // 1024
#define HSTRIDE (SEQ*DK)             // 23040
#define S2      192                  // compact tokens per sequence
#define M2      (BATCH*S2)           // 49152
#define HST2    (S2*DK)              // 12288
#define VTST    (DK*384)             // 24576 per head (VT)

typedef __nv_bfloat16 bf16;
typedef __nv_bfloat162 bf162;
typedef unsigned char u8;

// ---------------- scratch (device globals) ----------------
__device__ float g_xc [M2*D];           // residual after embed (compact, fp32)
__device__ u8    g_x18[TOKENS*D];       // LN1 output (full, fp8)
__device__ u8    g_q8 [M2*D];           // Q (B,H,192,64) fp8 x2
__device__ u8    g_k8 [TOKENS*D];       // K (B,H,360,64) fp8 x16
__device__ u8    g_vt8[HEADS*VTST];     // V^T (B,H,64,384) fp8 x16 (keys 360..383 zero)
__device__ u8    g_ctx8[M2*D];          // attention output (compact, fp8 x16)
__device__ float g_y  [M2*D];           // residual after WO (compact, fp32)
__device__ u8    g_x2b8[M2*D];          // LN2 output (compact, fp8)
__device__ u8    g_hb8[M2*DFF];         // ffn hidden (compact, fp8, x8)
__device__ bf16  g_xfb[M2*D];           // final x (compact, bf16)
__device__ float g_pe [PREFIX*D];
__device__ u8    g_wqkv8[3*D*D];        // [768][256]: q(x8) | k(x64) | v(x64)
__device__ u8    g_wo8[D*D];            // x64
__device__ u8    g_w18[DFF*D];          // x64
__device__ u8    g_w28[D*DFF];          // x64
__device__ float g_bqkv[3*D];           // bq*2 | bk*16 | bv*16

// ---------------- helpers ----------------
__device__ __forceinline__ float warp_sum(float v) {
    #pragma unroll
    for (int o = 16; o; o >>= 1) v += __shfl_xor_sync(0xffffffffu, v, o);
    return v;
}

#define QMMA(c, a0, a1, a2, a3, b0, b1)                                        \
    asm volatile(                                                              \
        "mma.sync.aligned.m16n8k32.row.col.f32.e4m3.e4m3.f32 "                 \
        "{%0,%1,%2,%3}, {%4,%5,%6,%7}, {%8,%9}, {%0,%1,%2,%3};"                \
        : "+f"(c[0]), "+f"(c[1]), "+f"(c[2]), "+f"(c[3])                       \
        : "r"(a0), "r"(a1), "r"(a2), "r"(a3), "r"(b0), "r"(b1))

__device__ __forceinline__ void ldsm4(unsigned &r0, unsigned &r1,
                                      unsigned &r2, unsigned &r3, unsigned addr) {
    asm volatile("ldmatrix.sync.aligned.m8n8.x4.shared.b16 {%0,%1,%2,%3}, [%4];"
        : "=r"(r0), "=r"(r1), "=r"(r2), "=r"(r3) : "r"(addr));
}
__device__ __forceinline__ void cpasync16(void* sdst, const void* gsrc) {
    unsigned s = (unsigned)__cvta_generic_to_shared(sdst);
    asm volatile("cp.async.cg.shared.global [%0], [%1], 16;" :: "r"(s), "l"(gsrc));
}
__device__ __forceinline__ u8 f2e4m3(float v) {
    unsigned short t;
    asm("cvt.rn.satfinite.e4m3x2.f32 %0, %1, %2;" : "=h"(t) : "f"(0.f), "f"(v));
    return (u8)t;
}
__device__ __forceinline__ unsigned short f2e4m3x2(float lo, float hi) {
    unsigned short t;
    asm("cvt.rn.satfinite.e4m3x2.f32 %0, %1, %2;" : "=h"(t) : "f"(hi), "f"(lo));
    return t;
}

// ---------------- convall: weights (fp8) + PE + bias pack + VT pad zero ---
__global__ void convall_kernel(const float* __restrict__ wq, const float* __restrict__ wk,
                               const float* __restrict__ wv, const float* __restrict__ wo,
                               const float* __restrict__ w1, const float* __restrict__ w2,
                               const float* __restrict__ bq, const float* __restrict__ bk,
                               const float* __restrict__ bv) {
    int bid = blockIdx.x, tid = threadIdx.x;
    if (bid < 768) {
        int m = bid >> 8;
        int idx = ((bid & 255) << 8) + tid;
        int k = idx >> 8, n = idx & 255;
        if (m == 0)      g_wqkv8[n * 256 + k]             = f2e4m3(wq[idx] * 8.0f);
        else if (m == 1) g_wqkv8[(256 + n) * 256 + k]     = f2e4m3(wk[idx] * 64.0f);
        else             g_wqkv8[(512 + n) * 256 + k]     = f2e4m3(wv[idx] * 64.0f);
    } else if (bid < 1024) {
        int idx = ((bid - 768) << 8) + tid;
        int k = idx >> 8, n = idx & 255;
        g_wo8[n * 256 + k] = f2e4m3(wo[idx] * 64.0f);
    } else if (bid < 3072) {
        int idx = (bid - 1024) * 256 + tid;
        int k = idx >> 11, n = idx & 2047;
        g_w18[n * 256 + k] = f2e4m3(w1[idx] * 64.0f);
    } else if (bid < 5120) {
        int idx = (bid - 3072) * 256 + tid;
        int k = idx >> 8, n = idx & 255;
        g_w28[(size_t)n * 2048 + k] = f2e4m3(w2[idx] * 64.0f);
    } else if (bid < 5460) {
        int s = bid - 5120, d = tid;
        float ex  = exp2f(-13.287712379549449f * ((float)d) * (1.0f / 128.0f));
        float arg = (float)s * ex;
        g_pe[s * D + d] = (d & 1) ? cosf(arg) : sinf(arg);
    } else if (bid == 5460) {
        g_bqkv[tid]       = bq[tid] * 2.0f;
        g_bqkv[tid + 256] = bk[tid] * 16.0f;
        g_bqkv[tid + 512] = bv[tid] * 16.0f;
    } else {
        // zero VT pad keys 360..383: 65536 rows x 24 bytes = 393216 u32
        int gid = (bid - 5461) * 256 + tid;
        int row = gid / 6, c = gid - row * 6;
        ((unsigned*)g_vt8)[row * 96 + 90 + c] = 0u;
    }
}

// ---------------- fused embedding + scale + PE + LN1 (warp per token) -----
__global__ void embed_ln_kernel(const int* __restrict__ src,
                                const float* __restrict__ emb,
                                const float* __restrict__ ga,
                                const float* __restrict__ gb) {
    int w = threadIdx.x >> 5, lane = threadIdx.x & 31;
    int t = blockIdx.x * 8 + w;
    int tok = src[t];
    int b = t / SEQ;
    int s = t - b * SEQ;
    const float4* er = (const float4*)(emb + (size_t)tok * D);
    float4 a = er[lane * 2], bb = er[lane * 2 + 1];
    if (s < PREFIX) {
        const float4* pr = (const float4*)(g_pe + s * D);
        float4 p = pr[lane * 2], q = pr[lane * 2 + 1];
        a.x = fmaf(a.x, 16.f, p.x); a.y = fmaf(a.y, 16.f, p.y);
        a.z = fmaf(a.z, 16.f, p.z); a.w = fmaf(a.w, 16.f, p.w);
        bb.x = fmaf(bb.x, 16.f, q.x); bb.y = fmaf(bb.y, 16.f, q.y);
        bb.z = fmaf(bb.z, 16.f, q.z); bb.w = fmaf(bb.w, 16.f, q.w);
    }
    if (s < S2) {
        size_t co = ((size_t)(b * S2 + s)) * D + lane * 8;
        *(float4*)(g_xc + co)     = a;
        *(float4*)(g_xc + co + 4) = bb;
    }

    float sum = a.x + a.y + a.z + a.w + bb.x + bb.y + bb.z + bb.w;
    float mu = warp_sum(sum) * (1.0f / 256.0f);
    float dx[8] = {a.x - mu, a.y - mu, a.z - mu, a.w - mu,
                   bb.x - mu, bb.y - mu, bb.z - mu, bb.w - mu};
    float ss = 0.f;
    #pragma unroll
    for (int i = 0; i < 8; i++) ss = fmaf(dx[i], dx[i], ss);
    float inv = 1.0f / (sqrtf(warp_sum(ss) * (1.0f / 255.0f)) + 1e-6f);

    const float4* gav = (const float4*)(ga + lane * 8);
    const float4* gbv = (const float4*)(gb + lane * 8);
    float4 g0 = gav[0], g1 = gav[1], h0 = gbv[0], h1 = gbv[1];
    float y0 = fmaf(g0.x, dx[0]*inv, h0.x), y1 = fmaf(g0.y, dx[1]*inv, h0.y);
    float y2 = fmaf(g0.z, dx[2]*inv, h0.z), y3 = fmaf(g0.w, dx[3]*inv, h0.w);
    float y4 = fmaf(g1.x, dx[4]*inv, h1.x), y5 = fmaf(g1.y, dx[5]*inv, h1.y);
    float y6 = fmaf(g1.z, dx[6]*inv, h1.z), y7 = fmaf(g1.w, dx[7]*inv, h1.w);
    unsigned s0 = f2e4m3x2(y0, y1), s1 = f2e4m3x2(y2, y3);
    unsigned s2 = f2e4m3x2(y4, y5), s3 = f2e4m3x2(y6, y7);
    uint2 pk;
    pk.x = s0 | (s1 << 16);
    pk.y = s2 | (s3 << 16);
    *(uint2*)(g_x18 + (size_t)t * D + lane * 8) = pk;
}

// ---------------- layernorm 2 (warp per token, fp32 -> fp8) ---------------
__global__ void ln2_kernel(const float* __restrict__ ga, const float* __restrict__ gb) {
    int w = threadIdx.x >> 5, lane = threadIdx.x & 31;
    int t = blockIdx.x * 8 + w;
    size_t off = (size_t)t * D + lane * 8;
    float4 a = *(const float4*)(g_y + off);
    float4 b = *(const float4*)(g_y + off + 4);

    float sum = a.x + a.y + a.z + a.w + b.x + b.y + b.z + b.w;
    float mu = warp_sum(sum) * (1.0f / 256.0f);
    float dx[8] = {a.x - mu, a.y - mu, a.z - mu, a.w - mu,
                   b.x - mu, b.y - mu, b.z - mu, b.w - mu};
    float ss = 0.f;
    #pragma unroll
    for (int i = 0; i < 8; i++) ss = fmaf(dx[i], dx[i], ss);
    float inv = 1.0f / (sqrtf(warp_sum(ss) * (1.0f / 255.0f)) + 1e-6f);

    const float4* gav = (const float4*)(ga + lane * 8);
    const float4* gbv = (const float4*)(gb + lane * 8);
    float4 g0 = gav[0], g1 = gav[1], h0 = gbv[0], h1 = gbv[1];
    float y0 = fmaf(g0.x, dx[0]*inv, h0.x), y1 = fmaf(g0.y, dx[1]*inv, h0.y);
    float y2 = fmaf(g0.z, dx[2]*inv, h0.z), y3 = fmaf(g0.w, dx[3]*inv, h0.w);
    float y4 = fmaf(g1.x, dx[4]*inv, h1.x), y5 = fmaf(g1.y, dx[5]*inv, h1.y);
    float y6 = fmaf(g1.z, dx[6]*inv, h1.z), y7 = fmaf(g1.w, dx[7]*inv, h1.w);
    unsigned s0 = f2e4m3x2(y0, y1), s1 = f2e4m3x2(y2, y3);
    unsigned s2 = f2e4m3x2(y4, y5), s3 = f2e4m3x2(y6, y7);
    uint2 pk;
    pk.x = s0 | (s1 << 16);
    pk.y = s2 | (s3 << 16);
    *(uint2*)(g_x2b8 + off) = pk;
}

// ---------------- universal fp8 GEMM: CTA 128x128, warp 64x32, KT=64 ------
// EPI 0: KVQ. blockIdx.x: 0-1 K (full M), 2-3 V->VT (full M), 4-5 Q (compact).
// EPI 1: WO   -> fp32 g_y = res + acc/1024 + bias
// EPI 2: FFN1 -> fp8 hidden = relu(acc/64 + b1) * 8
// EPI 3: FFN2 -> bf16 out = res + acc/512 + b2
#define RSTR 80
#define ASTG (128*RSTR)
#define QG_SMEM (4*ASTG)

template<int EPI>
__global__ __launch_bounds__(256, 2)
void q128_kernel(const u8* __restrict__ A, const u8* __restrict__ Wt,
                 const float* __restrict__ bias, const float* __restrict__ res,
                 void* __restrict__ Cv0, int M, int N, int K) {
    const int bx = blockIdx.x;
    if (EPI == 0 && bx >= 4 && blockIdx.y >= 384) return;

    extern __shared__ u8 sm8[];
    const unsigned SMU = (unsigned)__cvta_generic_to_shared(sm8);

    const int tid  = threadIdx.x;
    const int lane = tid & 31;
    const int wid  = tid >> 5;
    const int wm = wid >> 2;
    const int wn = wid & 3;
    const int g = lane >> 2;
    const int t = lane & 3;

    const int bm = blockIdx.y * 128;
    int wrow0;
    if (EPI == 0) {
        if (bx < 2)      wrow0 = 256 + bx * 128;          // K weights
        else if (bx < 4) wrow0 = 512 + (bx - 2) * 128;    // V weights
        else             wrow0 = (bx - 4) * 128;          // Q weights
    } else wrow0 = bx * 128;

    const int arow = tid >> 1;
    const int acb  = (tid & 1) * 32;
    int garow = bm + arow;
    if (EPI == 0 && bx >= 4) { int bb = garow / S2; garow = bb * SEQ + (garow - bb * S2); }
    const u8* Ap = A  + (size_t)garow * K + acb;
    const u8* Bp = Wt + (size_t)(wrow0 + arow) * K + acb;

    const int a_r  = lane & 15;
    const int a_cB = ((lane >> 4) & 1) * 16;
    const int b_n  = (lane & 7) + ((lane >> 4) & 1) * 8;
    const int b_cB = ((lane >> 3) & 1) * 16;

    float acc[4][4][4];
    #pragma unroll
    for (int mi = 0; mi < 4; mi++)
        #pragma unroll
        for (int ni = 0; ni < 4; ni++)
            #pragma unroll
            for (int r = 0; r < 4; r++) acc[mi][ni][r] = 0.f;

    const int nt = K >> 6;
    {
        u8* ad = sm8 + arow * RSTR + acb;
        cpasync16(ad, Ap); cpasync16(ad + 16, Ap + 16);
        u8* bd = sm8 + 2 * ASTG + arow * RSTR + acb;
        cpasync16(bd, Bp); cpasync16(bd + 16, Bp + 16);
    }
    asm volatile("cp.async.commit_group;");

    for (int tl = 0; tl < nt; tl++) {
        const int cur = tl & 1;
        asm volatile("cp.async.wait_group 0;" ::: "memory");
        __syncthreads();
        if (tl + 1 < nt) {
            const int nxt = cur ^ 1;
            const u8* ap = Ap + (tl + 1) * 64;
            u8* ad = sm8 + nxt * ASTG + arow * RSTR + acb;
            cpasync16(ad, ap); cpasync16(ad + 16, ap + 16);
            const u8* bp = Bp + (tl + 1) * 64;
            u8* bd = sm8 + 2 * ASTG + nxt * ASTG + arow * RSTR + acb;
            cpasync16(bd, bp); cpasync16(bd + 16, bp + 16);
            asm volatile("cp.async.commit_group;");
        }

        const unsigned abase = SMU + cur * ASTG;
        const unsigned bbase = SMU + 2 * ASTG + cur * ASTG;
        #pragma unroll
        for (int kk = 0; kk < 2; kk++) {
            unsigned af[4][4], bfr[2][4];
            #pragma unroll
            for (int mi = 0; mi < 4; mi++) {
                unsigned addr = abase +
                    (unsigned)((wm * 64 + mi * 16 + a_r) * RSTR + kk * 32 + a_cB);
                ldsm4(af[mi][0], af[mi][1], af[mi][2], af[mi][3], addr);
            }
            #pragma unroll
            for (int p = 0; p < 2; p++) {
                unsigned addr = bbase +
                    (unsigned)((wn * 32 + p * 16 + b_n) * RSTR + kk * 32 + b_cB);
                ldsm4(bfr[p][0], bfr[p][1], bfr[p][2], bfr[p][3], addr);
            }
            #pragma unroll
            for (int mi = 0; mi < 4; mi++)
                #pragma unroll
                for (int ni = 0; ni < 4; ni++)
                    QMMA(acc[mi][ni], af[mi][0], af[mi][1], af[mi][2], af[mi][3],
                         bfr[ni >> 1][(ni & 1) * 2], bfr[ni >> 1][(ni & 1) * 2 + 1]);
        }
    }

    #pragma unroll
    for (int mi = 0; mi < 4; mi++) {
        int row0 = bm + wm * 64 + mi * 16 + g;
        #pragma unroll
        for (int ni = 0; ni < 4; ni++) {
            int nlocal = wn * 32 + ni * 8 + t * 2;
            #pragma unroll
            for (int half = 0; half < 2; half++) {
                int row = row0 + half * 8;
                float a0 = acc[mi][ni][half * 2 + 0];
                float a1 = acc[mi][ni][half * 2 + 1];
                if (EPI == 0) {
                    float v0 = fmaf(a0, 0.25f, bias[wrow0 + nlocal]);
                    float v1 = fmaf(a1, 0.25f, bias[wrow0 + nlocal + 1]);
                    if (bx < 2) {                       // K fp8 row-major
                        int ic = bx * 128 + nlocal;
                        int bbt = row / SEQ;
                        int s   = row - bbt * SEQ;
                        *(unsigned short*)(g_k8 + (size_t)bbt * (H * HSTRIDE)
                            + (ic >> 6) * HSTRIDE + s * DK + (ic & 63)) = f2e4m3x2(v0, v1);
                    } else if (bx < 4) {                // V -> VT fp8
                        int ic = (bx - 2) * 128 + nlocal;
                        int bbt = row / SEQ;
                        int s   = row - bbt * SEQ;
                        size_t base = ((size_t)(bbt * H + (ic >> 6)) * DK + (ic & 63)) * 384 + s;
                        g_vt8[base]       = f2e4m3(v0);
                        g_vt8[base + 384] = f2e4m3(v1);
                    } else {                            // Q fp8 compact
                        int ic = (bx - 4) * 128 + nlocal;
                        int bbt = row / S2;
                        int s   = row - bbt * S2;
                        *(unsigned short*)(g_q8 + (size_t)bbt * (H * HST2)
                            + (ic >> 6) * HST2 + s * DK + (ic & 63)) = f2e4m3x2(v0, v1);
                    }
                } else if (EPI == 1) {
                    int col = bx * 128 + nlocal;
                    size_t ro = (size_t)row * 256 + col;
                    float2 bb = *(const float2*)(bias + col);
                    float2 rv = *(const float2*)(res + ro);
                    *(float2*)((float*)Cv0 + ro) = make_float2(
                        fmaf(a0, 1.0f / 1024.0f, bb.x + rv.x),
                        fmaf(a1, 1.0f / 1024.0f, bb.y + rv.y));
                } else if (EPI == 2) {
                    int col = bx * 128 + nlocal;
                    float2 bb = *(const float2*)(bias + col);
                    float v0 = fmaxf(fmaf(a0, 0.125f, bb.x * 8.0f), 0.f);
                    float v1 = fmaxf(fmaf(a1, 0.125f, bb.y * 8.0f), 0.f);
                    *(unsigned short*)((u8*)Cv0 + (size_t)row * N + col) = f2e4m3x2(v0, v1);
                } else {
                    int col = bx * 128 + nlocal;
                    size_t ro = (size_t)row * 256 + col;
                    float2 bb = *(const float2*)(bias + col);
                    float2 rv = *(const float2*)(res + ro);
                    *(bf162*)((bf16*)Cv0 + ro) = __floats2bfloat162_rn(
                        fmaf(a0, 1.0f / 512.0f, bb.x + rv.x),
                        fmaf(a1, 1.0f / 512.0f, bb.y + rv.y));
                }
            }
        }
    }
}

// ---------------- fp8 attention: 512 threads, 4 q-subtiles x 4 key-quarters
// smem bytes: Q 64x80 | K 384x80 (360 loaded) | VT 64x400 | P 64x400 | red 2KB
#define SQ3  0
#define SK3  5120
#define SVT3 35840
#define SP3  61440
#define RED3 87040
#define ATT3_SMEM 89088

__global__ __launch_bounds__(512, 1)
void fattn3_kernel(const int* __restrict__ src) {
    extern __shared__ u8 sm8[];
    const unsigned SMU = (unsigned)__cvta_generic_to_shared(sm8);
    unsigned short* sP16 = (unsigned short*)(sm8 + SP3);
    float* redm = (float*)(sm8 + RED3);        // [4][64]
    float* reds = redm + 256;                  // [4][64]

    const int bh = blockIdx.x;
    const int b  = bh >> 2;
    const int head = bh & 3;
    const int tid = threadIdx.x;

    // ---- K (360x64 fp8) and VT (64x384 fp8) loads ----
    const u8* k8p  = g_k8  + (size_t)bh * HSTRIDE;
    const u8* vt8p = g_vt8 + (size_t)bh * VTST;
    for (int u = tid; u < 1440; u += 512) {
        int row = u >> 2, c = u & 3;
        cpasync16(sm8 + SK3 + row * 80 + c * 16, k8p + u * 16);
    }
    for (int u = tid; u < 1536; u += 512) {
        int row = u / 24, c = u - row * 24;
        cpasync16(sm8 + SVT3 + row * 400 + c * 16, vt8p + u * 16);
    }
    asm volatile("cp.async.commit_group;");

    const int lane = tid & 31, wid = tid >> 5;
    const int wq = wid >> 2;                  // 0..3 q-subtile
    const int wk = wid & 3;                   // 0..3 key-quarter / dk-quarter
    const int g = lane >> 2, t = lane & 3;
    const int kq = wk * 96;
    const int r_lo = wq * 16 + g, r_hi = r_lo + 8;

    const int a_r  = lane & 15;
    const int a_cB = ((lane >> 4) & 1) * 16;
    const int b_n  = (lane & 7) + ((lane >> 4) & 1) * 8;
    const int b_cB = ((lane >> 3) & 1) * 16;

    const u8* q8p = g_q8 + (size_t)bh * HST2;

    for (int qt = 0; qt < 3; qt++) {
        const int qbase = qt * 64;

        // ---- Q tile load (256 units) ----
        if (tid < 256) {
            int row = tid >> 2, c = tid & 3;
            cpasync16(sm8 + SQ3 + row * 80 + c * 16,
                      q8p + (size_t)(qbase + row) * 64 + c * 16);
        }
        asm volatile("cp.async.commit_group;");
        asm volatile("cp.async.wait_group 0;" ::: "memory");
        __syncthreads();

        // ---- S = Q K^T (warp: 16 q x 96 keys, k=64 in 2 k32 steps) ----
        float acc[12][4];
        #pragma unroll
        for (int ni = 0; ni < 12; ni++)
            #pragma unroll
            for (int r = 0; r < 4; r++) acc[ni][r] = 0.f;

        #pragma unroll
        for (int kt = 0; kt < 2; kt++) {
            unsigned a0, a1, a2, a3;
            ldsm4(a0, a1, a2, a3,
                  SMU + SQ3 + (unsigned)((wq * 16 + a_r) * 80 + kt * 32 + a_cB));
            #pragma unroll
            for (int p = 0; p < 6; p++) {
                unsigned b0, b1, b2, b3;
                ldsm4(b0, b1, b2, b3,
                      SMU + SK3 + (unsigned)((kq + p * 16 + b_n) * 80 + kt * 32 + b_cB));
                QMMA(acc[2 * p],     a0, a1, a2, a3, b0, b1);
                QMMA(acc[2 * p + 1], a0, a1, a2, a3, b2, b3);
            }
        }

        // ---- mask + unscale (1/256) + softmax across 4 quarters ----
        bool v_lo = (src[b * SEQ + qbase + r_lo] != PADTOK);
        bool v_hi = (src[b * SEQ + qbase + r_hi] != PADTOK);

        float m_lo = -1e30f, m_hi = -1e30f;
        #pragma unroll
        for (int ni = 0; ni < 12; ni++) {
            int col0 = kq + ni * 8 + t * 2;
            bool in0 = col0 < SEQ, in1 = col0 + 1 < SEQ;
            acc[ni][0] = in0 ? (v_lo ? acc[ni][0] * (1.f/256.f) : 0.f) : -1e30f;
            acc[ni][1] = in1 ? (v_lo ? acc[ni][1] * (1.f/256.f) : 0.f) : -1e30f;
            acc[ni][2] = in0 ? (v_hi ? acc[ni][2] * (1.f/256.f) : 0.f) : -1e30f;
            acc[ni][3] = in1 ? (v_hi ? acc[ni][3] * (1.f/256.f) : 0.f) : -1e30f;
            m_lo = fmaxf(m_lo, fmaxf(acc[ni][0], acc[ni][1]));
            m_hi = fmaxf(m_hi, fmaxf(acc[ni][2], acc[ni][3]));
        }
        m_lo = fmaxf(m_lo, __shfl_xor_sync(0xffffffffu, m_lo, 1));
        m_lo = fmaxf(m_lo, __shfl_xor_sync(0xffffffffu, m_lo, 2));
        m_hi = fmaxf(m_hi, __shfl_xor_sync(0xffffffffu, m_hi, 1));
        m_hi = fmaxf(m_hi, __shfl_xor_sync(0xffffffffu, m_hi, 2));
        if (t == 0) { redm[wk * 64 + r_lo] = m_lo; redm[wk * 64 + r_hi] = m_hi; }
        __syncthreads();
        m_lo = fmaxf(fmaxf(redm[r_lo], redm[64 + r_lo]),
                     fmaxf(redm[128 + r_lo], redm[192 + r_lo]));
        m_hi = fmaxf(fmaxf(redm[r_hi], redm[64 + r_hi]),
                     fmaxf(redm[128 + r_hi], redm[192 + r_hi]));

        float s_lo = 0.f, s_hi = 0.f;
        #pragma unroll
        for (int ni = 0; ni < 12; ni++) {
            acc[ni][0] = __expf(acc[ni][0] - m_lo);
            acc[ni][1] = __expf(acc[ni][1] - m_lo);
            acc[ni][2] = __expf(acc[ni][2] - m_hi);
            acc[ni][3] = __expf(acc[ni][3] - m_hi);
            s_lo += acc[ni][0] + acc[ni][1];
            s_hi += acc[ni][2] + acc[ni][3];
        }
        s_lo += __shfl_xor_sync(0xffffffffu, s_lo, 1);
        s_lo += __shfl_xor_sync(0xffffffffu, s_lo, 2);
        s_hi += __shfl_xor_sync(0xffffffffu, s_hi, 1);
        s_hi += __shfl_xor_sync(0xffffffffu, s_hi, 2);
        if (t == 0) { reds[wk * 64 + r_lo] = s_lo; reds[wk * 64 + r_hi] = s_hi; }
        __syncthreads();
        float inv_lo = 64.f / (reds[r_lo] + reds[64 + r_lo] +
                               reds[128 + r_lo] + reds[192 + r_lo]);   // x64 for fp8 P
        float inv_hi = 64.f / (reds[r_hi] + reds[64 + r_hi] +
                               reds[128 + r_hi] + reds[192 + r_hi]);

        // ---- write P (fp8 x64, row stride 400 B) ----
        #pragma unroll
        for (int ni = 0; ni < 12; ni++) {
            int cu = wk * 48 + ni * 4 + t;                // u16 column index
            sP16[r_lo * 200 + cu] = f2e4m3x2(acc[ni][0] * inv_lo, acc[ni][1] * inv_lo);
            sP16[r_hi * 200 + cu] = f2e4m3x2(acc[ni][2] * inv_hi, acc[ni][3] * inv_hi);
        }
        __syncthreads();

        // ---- O = P @ VT (warp: 16 q x 16 dk, k = 384 in 12 k32 steps) ----
        float o[2][4];
        #pragma unroll
        for (int ni = 0; ni < 2; ni++)
            #pragma unroll
            for (int r = 0; r < 4; r++) o[ni][r] = 0.f;

        #pragma unroll
        for (int kt = 0; kt < 12; kt++) {
            unsigned a0, a1, a2, a3;
            ldsm4(a0, a1, a2, a3,
                  SMU + SP3 + (unsigned)((wq * 16 + a_r) * 400 + kt * 32 + a_cB));
            unsigned b0, b1, b2, b3;
            ldsm4(b0, b1, b2, b3,
                  SMU + SVT3 + (unsigned)((wk * 16 + b_n) * 400 + kt * 32 + b_cB));
            QMMA(o[0], a0, a1, a2, a3, b0, b1);
            QMMA(o[1], a0, a1, a2, a3, b2, b3);
        }

        // ---- ctx fp8 x16: val = (accO/1024) * 16 = accO/64 ----
        #pragma unroll
        for (int ni = 0; ni < 2; ni++) {
            int col = wk * 16 + ni * 8 + t * 2;
            size_t ob0 = ((size_t)(b * S2 + qbase + r_lo)) * D + head * DK + col;
            size_t ob1 = ((size_t)(b * S2 + qbase + r_hi)) * D + head * DK + col;
            *(unsigned short*)(g_ctx8 + ob0) =
                f2e4m3x2(o[ni][0] * (1.f/64.f), o[ni][1] * (1.f/64.f));
            *(unsigned short*)(g_ctx8 + ob1) =
                f2e4m3x2(o[ni][2] * (1.f/64.f), o[ni][3] * (1.f/64.f));
        }
    }
}

// ---------------- classifier (warp per pair, wl in smem, bf16 x) ----------
__global__ __launch_bounds__(256)
void cls_kernel(const int* __restrict__ src,
                const float* __restrict__ wl,
                const float* __restrict__ bl,
                float* __restrict__ out) {
    __shared__ float swl[6144];
    int tid = threadIdx.x;
    #pragma unroll
    for (int u = 0; u < 24; u++) swl[u * 256 + tid] = wl[u * 256 + tid];
    __syncthreads();

    int w = tid >> 5, lane = tid & 31;
    int bp = blockIdx.x * 8 + w;
    int b = bp / NPAIR, p = bp - b * NPAIR;

    int i = 0, rem = p;
    while (rem >= 13 - i) { rem -= 13 - i; i++; }
    int j = i + 1 + rem;
    int base = i * 12 - (i * (i - 1)) / 2;
    int pe = base + (j - i) - 1;
    int eb = 28 + 2 * pe;
    int gidx[8] = {2*i, 2*i+1, 2*j, 2*j+1, eb, eb+1, eb+2, eb+3};

    const bf16* xb = g_xfb + (size_t)(b * S2) * D;
    int slots = (j < 13) ? 8 : 4;

    float a0 = 0.f, a1 = 0.f, a2 = 0.f;
    for (int sl = 0; sl < slots; sl++) {
        const bf16* xr = xb + gidx[sl] * D;
        const float* wr = swl + sl * 768;
        #pragma unroll
        for (int dd = 0; dd < 4; dd++) {
            int dim = lane * 2 + dd * 64;
            bf162 xv2 = *(const bf162*)(xr + dim);
            float x0 = __bfloat162float(xv2.x);
            float x1 = __bfloat162float(xv2.y);
            a0 = fmaf(x0, wr[dim * 3 + 0], fmaf(x1, wr[dim * 3 + 3], a0));
            a1 = fmaf(x0, wr[dim * 3 + 1], fmaf(x1, wr[dim * 3 + 4], a1));
            a2 = fmaf(x0, wr[dim * 3 + 2], fmaf(x1, wr[dim * 3 + 5], a2));
        }
    }
    a0 = warp_sum(a0); a1 = warp_sum(a1); a2 = warp_sum(a2);

    if (lane == 0) {
        const int* sb = src + b * SEQ;
        int ti = sb[2*i], ai = sb[2*i+1], tj = sb[2*j], aj = sb[2*j+1];
        bool c1 = (ai == 2) || (aj == 2);
        bool c2 = (tj == 1) || (ai == 1) || (aj == 1);
        bool c3 = (ti == PADTOK) || (tj == PADTOK) || (ai == 0) || (aj == 0);
        bool c4 = false;
        if (j < 13) {
            int es = 28 + 4 * pe;
            c4 = (sb[es] == 1) || (sb[es+1] == 1) || (sb[es+2] == 1) || (sb[es+3] == 1);
        }
        bool m111 = c3 || c4;
        bool mk1 = m111 || c2;
        bool mk2 = mk1 || c1;
        float* o = out + (size_t)bp * 3;
        o[0] = m111 ? -1e9f : (a0 + bl[0]);
        o[1] = mk1  ? -1e9f : (a1 + bl[1]);
        o[2] = mk2  ? -1e9f : (a2 + bl[2]);
    }
}

// ---------------- launch ----------------
extern "C" void kernel_launch(void* const* d_in, const int* in_sizes, int n_in,
                              void* d_out, int out_size) {
    (void)in_sizes; (void)n_in; (void)out_size;
    const int*   src = (const int*)  d_in[0];
    const float* emb = (const float*)d_in[1];
    const float* wq  = (const float*)d_in[2];
    const float* bq  = (const float*)d_in[3];
    const float* wk  = (const float*)d_in[4];
    const float* bk  = (const float*)d_in[5];
    const float* wv  = (const float*)d_in[6];
    const float* bv  = (const float*)d_in[7];
    const float* wo  = (const float*)d_in[8];
    const float* bo  = (const float*)d_in[9];
    const float* n1a = (const float*)d_in[10];
    const float* n1b = (const float*)d_in[11];
    const float* n2a = (const float*)d_in[12];
    const float* n2b = (const float*)d_in[13];
    const float* w1  = (const float*)d_in[14];
    const float* b1  = (const float*)d_in[15];
    const float* w2  = (const float*)d_in[16];
    const float* b2  = (const float*)d_in[17];
    const float* wl  = (const float*)d_in[18];
    const float* bl  = (const float*)d_in[19];
    float* out = (float*)d_out;

    float *pxc, *py, *pbqkv;
    bf16 *pxfb;
    u8 *px18, *pctx8, *px2b8, *phb8, *pwqkv8, *pwo8, *pw18, *pw28;
    cudaGetSymbolAddress((void**)&pxc,    g_xc);
    cudaGetSymbolAddress((void**)&px18,   g_x18);
    cudaGetSymbolAddress((void**)&pctx8,  g_ctx8);
    cudaGetSymbolAddress((void**)&py,     g_y);
    cudaGetSymbolAddress((void**)&px2b8,  g_x2b8);
    cudaGetSymbolAddress((void**)&phb8,   g_hb8);
    cudaGetSymbolAddress((void**)&pxfb,   g_xfb);
    cudaGetSymbolAddress((void**)&pwqkv8, g_wqkv8);
    cudaGetSymbolAddress((void**)&pwo8,   g_wo8);
    cudaGetSymbolAddress((void**)&pw18,   g_w18);
    cudaGetSymbolAddress((void**)&pw28,   g_w28);
    cudaGetSymbolAddress((void**)&pbqkv,  g_bqkv);

    cudaFuncSetAttribute(fattn3_kernel, cudaFuncAttributeMaxDynamicSharedMemorySize,
                         (int)ATT3_SMEM);

    // 5461 base blocks + 1536 VT-pad-zero blocks
    convall_kernel<<<6997, 256>>>(wq, wk, wv, wo, w1, w2, bq, bk, bv);
    embed_ln_kernel<<<TOKENS/8, 256>>>(src, emb, n1a, n1b);

    // merged K (full) + V->VT (full) + Q (compact) projections
    dim3 gkvq(6, TOKENS / 128);
    q128_kernel<0><<<gkvq, 256, QG_SMEM>>>(px18, pwqkv8, pbqkv, nullptr,
                                           nullptr, TOKENS, 256, D);

    fattn3_kernel<<<HEADS, 512, ATT3_SMEM>>>(src);

    // WO + residual -> g_y (fp32); ctx is x16 -> acc/1024
    dim3 gwo(2, M2 / 128);
    q128_kernel<1><<<gwo, 256, QG_SMEM>>>(pctx8, pwo8, bo, pxc, py, M2, 256, D);

    // LN2 -> fp8
    ln2_kernel<<<M2/8, 256>>>(n2a, n2b);

    // FFN
    dim3 gff1(16, M2 / 128);
    q128_kernel<2><<<gff1, 256, QG_SMEM>>>(px2b8, pw18, b1, nullptr, phb8, M2, DFF, D);
    q128_kernel<3><<<gwo, 256, QG_SMEM>>>(phb8, pw28, b2, py, pxfb, M2, 256, DFF);

    cls_kernel<<<(BATCH * NPAIR) / 8, 256>>>(src, wl, bl, out);
}